// round 12
// baseline (speedup 1.0000x reference)
#include <cuda_runtime.h>
#include <cuda_bf16.h>
#include <math.h>
#include <stdint.h>

#define NB 8
#define NA 512
#define NN 64
#define ND 128
#define NF 128
#define NG 25
#define NL 3
#define NGA 512
#define BA (NB*NA)          // 4096
#define CUTOFF 5.0f
#define RSTART 1.2f
#define LN2F 0.6931471805599453f

// -------- device scratch --------
__device__ float d_x[BA*ND];
__device__ float d_y[BA*NF];
__device__ float d_agg[BA*NF];
__device__ float d_vang[NL*BA*ND];
__device__ float d_cm[BA*NN];
__device__ __nv_bfloat16 d_fhi[BA*NN*32];       // f_ij split, k padded to 32
__device__ __nv_bfloat16 d_flo[BA*NN*32];
__device__ __nv_bfloat16 d_w1hi[NL*NF*32];      // w1^T split [l][f][k32]
__device__ __nv_bfloat16 d_w1lo[NL*NF*32];
__device__ __nv_bfloat16 d_w2hi[NL*NF*NF];      // w2^T split [l][f][k]
__device__ __nv_bfloat16 d_w2lo[NL*NF*NF];
__device__ __nv_bfloat16 d_i2fhi[NL*NF*ND];     // in2f^T split
__device__ __nv_bfloat16 d_i2flo[NL*NF*ND];
__device__ __nv_bfloat16 d_anghi[NL*ND*NGA];    // angw^T split
__device__ __nv_bfloat16 d_anglo[NL*ND*NGA];
__device__ float d_wc[NL*ND*ND];                // f2w @ dense composite
__device__ __nv_bfloat16 d_wchi[NL*ND*ND];      // Wc^T split
__device__ __nv_bfloat16 d_wclo[NL*ND*ND];
__device__ float d_bc[NL*ND];                   // f2b @ dense + db

__device__ __forceinline__ float ssp(float v) {
    return fmaxf(v, 0.f) + __logf(1.f + __expf(-fabsf(v))) - LN2F;
}

__device__ __forceinline__ uint32_t smem_u32(const void* p) {
    uint32_t a;
    asm("{ .reg .u64 t; cvta.to.shared.u64 t, %1; cvt.u32.u64 %0, t; }" : "=r"(a) : "l"(p));
    return a;
}

__device__ __forceinline__ void split2(float a, float b, uint32_t& hi, uint32_t& lo) {
    __nv_bfloat16 ah = __float2bfloat16(a), bh = __float2bfloat16(b);
    float ar = a - __bfloat162float(ah);
    float br = b - __bfloat162float(bh);
    __nv_bfloat162 hp; hp.x = ah; hp.y = bh;
    __nv_bfloat162 lp = __floats2bfloat162_rn(ar, br);
    hi = *(uint32_t*)&hp;
    lo = *(uint32_t*)&lp;
}

// -------- embedding gather --------
__global__ void embed_kernel(const int* __restrict__ z, const float* __restrict__ emb) {
    int i = blockIdx.x, t = threadIdx.x;
    d_x[i*ND + t] = emb[z[i]*ND + t];
}

// -------- distances + gaussian smearing (bf16-split) + cutoff*mask --------
__global__ void dist_kernel(const float* __restrict__ pos,
                            const int* __restrict__ nb,
                            const int* __restrict__ nmask) {
    int i = blockIdx.x;
    int n = threadIdx.x;
    int bofs = (i >> 9) << 9;
    float px = pos[i*3+0], py = pos[i*3+1], pz = pos[i*3+2];
    int j = nb[i*NN + n];
    int gj = bofs + j;
    float dx = pos[gj*3+0] - px;
    float dy = pos[gj*3+1] - py;
    float dz = pos[gj*3+2] - pz;
    float r = sqrtf(dx*dx + dy*dy + dz*dz + 1e-12f);
    float m = (float)nmask[i*NN + n];
    d_cm[i*NN + n] = (r <= CUTOFF) ? m : 0.f;
    const float width = (CUTOFF - RSTART) / (float)(NG - 1);
    const float coeff = -0.5f / (width * width);
    __nv_bfloat16* oh = d_fhi + (size_t)(i*NN + n) * 32;
    __nv_bfloat16* ol = d_flo + (size_t)(i*NN + n) * 32;
    #pragma unroll
    for (int g = 0; g < 32; g++) {
        float v = 0.f;
        if (g < NG) {
            float d = r - (RSTART + width * (float)g);
            v = __expf(coeff * d * d);
        }
        __nv_bfloat16 hi = __float2bfloat16(v);
        oh[g] = hi;
        ol[g] = __float2bfloat16(v - __bfloat162float(hi));
    }
}

// -------- prestage: transpose + split w1 [L][25][128] -> [l][f][k32] --------
__global__ void w1split_kernel(const float* __restrict__ w1) {
    int idx = blockIdx.x * 256 + threadIdx.x;     // NL*128*32 = 12288
    int l = idx >> 12;
    int r = idx & 4095;
    int f = r >> 5, k = r & 31;
    float v = (k < NG) ? w1[l*3200 + k*128 + f] : 0.f;
    __nv_bfloat16 hi = __float2bfloat16(v);
    d_w1hi[idx] = hi;
    d_w1lo[idx] = __float2bfloat16(v - __bfloat162float(hi));
}

// -------- prestage: transpose + split [NL][K][128] -> [l][f][K] --------
__global__ void bsplit_kernel(const float* __restrict__ src,
                              __nv_bfloat16* __restrict__ dhi,
                              __nv_bfloat16* __restrict__ dlo, int K) {
    int idx = blockIdx.x * 256 + threadIdx.x;
    int l = idx / (K*128);
    int r = idx % (K*128);
    int k = r >> 7, f = r & 127;
    float v = src[idx];
    __nv_bfloat16 hi = __float2bfloat16(v);
    __nv_bfloat16 lo = __float2bfloat16(v - __bfloat162float(hi));
    int o = l*K*128 + f*K + k;
    dhi[o] = hi;
    dlo[o] = lo;
}

__global__ void w2split_kernel(const float* __restrict__ w2) {
    int idx = blockIdx.x * 256 + threadIdx.x;
    int l = idx >> 14;
    int r = idx & 16383;
    int k = r >> 7, f = r & 127;
    float v = w2[idx];
    __nv_bfloat16 hi = __float2bfloat16(v);
    __nv_bfloat16 lo = __float2bfloat16(v - __bfloat162float(hi));
    int o = l*16384 + f*128 + k;
    d_w2hi[o] = hi;
    d_w2lo[o] = lo;
}

// -------- prestage: composite epilogue weights --------
__global__ __launch_bounds__(128)
void wc_kernel(const float* __restrict__ f2w, const float* __restrict__ dwm) {
    __shared__ float Ash[16][32];
    __shared__ float Bsh[32][128];
    int l = blockIdx.y;
    const float* Am = f2w + (size_t)l*16384;
    const float* Bm = dwm + (size_t)l*16384;
    float* Cm = d_wc + (size_t)l*16384;
    int t = threadIdx.x;
    int row0 = blockIdx.x * 16;
    float acc[16];
    #pragma unroll
    for (int r = 0; r < 16; r++) acc[r] = 0.f;
    for (int kt = 0; kt < 128; kt += 32) {
        #pragma unroll
        for (int p = 0; p < 4; p++) {
            int idx = t + 128*p;
            Ash[idx >> 5][idx & 31] = Am[(row0 + (idx >> 5))*128 + kt + (idx & 31)];
        }
        #pragma unroll 8
        for (int kk = 0; kk < 32; kk++) Bsh[kk][t] = Bm[(kt + kk)*128 + t];
        __syncthreads();
        #pragma unroll
        for (int kk = 0; kk < 32; kk++) {
            float bv = Bsh[kk][t];
            #pragma unroll
            for (int r = 0; r < 16; r++) acc[r] += Ash[r][kk] * bv;
        }
        __syncthreads();
    }
    #pragma unroll
    for (int r = 0; r < 16; r++) Cm[(row0 + r)*128 + t] = acc[r];
}

__global__ void bc_kernel(const float* __restrict__ f2b, const float* __restrict__ dwm,
                          const float* __restrict__ db) {
    int l = blockIdx.x, t = threadIdx.x;
    float acc = db[l*128 + t];
    #pragma unroll 4
    for (int k = 0; k < 128; k++)
        acc += f2b[l*128 + k] * dwm[(size_t)l*16384 + k*128 + t];
    d_bc[l*128 + t] = acc;
}

// -------- tensor GEMM: C[M,128] = A[M,K] @ B[K,128], bf16 hi/lo split --------
#define TG_AHI 0
#define TG_ALO 9216
#define TG_BHI 18432
#define TG_BLO 36864
#define TG_SMEM 55296
#define TG_STRIDE 144

__global__ __launch_bounds__(256, 2)
void tgemm_kernel(const float* __restrict__ Aext,
                  const __nv_bfloat16* __restrict__ BtHi,
                  const __nv_bfloat16* __restrict__ BtLo,
                  int K, int amode, int cmode) {
    extern __shared__ char smc[];
    uint32_t sb = smem_u32(smc);
    int t = threadIdx.x;
    int lane = t & 31;
    int w = t >> 5;
    int l = blockIdx.y;
    int M0 = blockIdx.x * 64;
    const float* Ap = (amode == 1) ? d_x : ((amode == 2) ? d_agg : Aext);
    float* Cp = (cmode == 1) ? (d_vang + (size_t)l*BA*ND) : d_y;
    const __nv_bfloat16* bhiL = BtHi + (size_t)l*128*K;
    const __nv_bfloat16* bloL = BtLo + (size_t)l*128*K;

    int R0 = (w >> 1) * 16;
    int jbase = (w & 1) * 8;

    float acc[8][4];
    #pragma unroll
    for (int j = 0; j < 8; j++)
        #pragma unroll
        for (int q = 0; q < 4; q++) acc[j][q] = 0.f;

    uint32_t aAddr = sb + TG_AHI + (uint32_t)(R0 + (lane & 15))*TG_STRIDE + (uint32_t)(lane & 16);
    uint32_t bAddr = sb + TG_BHI + (uint32_t)(lane & 7)*TG_STRIDE + (uint32_t)((lane & 8) << 1);

    for (int kc = 0; kc < K; kc += 64) {
        #pragma unroll
        for (int p = 0; p < 8; p++) {
            int u = t + 256*p;
            int r = u >> 5, kp = u & 31;
            float2 v = *(const float2*)&Ap[(size_t)(M0 + r)*K + kc + kp*2];
            uint32_t hi, lo;
            split2(v.x, v.y, hi, lo);
            *(uint32_t*)(smc + TG_AHI + r*TG_STRIDE + kp*4) = hi;
            *(uint32_t*)(smc + TG_ALO + r*TG_STRIDE + kp*4) = lo;
        }
        #pragma unroll
        for (int p = 0; p < 4; p++) {
            int u = t + 256*p;
            int f = u >> 3, c = u & 7;
            *(uint4*)(smc + TG_BHI + f*TG_STRIDE + c*16) =
                ((const uint4*)(bhiL + f*K + kc))[c];
            *(uint4*)(smc + TG_BLO + f*TG_STRIDE + c*16) =
                ((const uint4*)(bloL + f*K + kc))[c];
        }
        __syncthreads();

        #pragma unroll
        for (int s = 0; s < 4; s++) {
            uint32_t ah[4], al[4];
            asm volatile("ldmatrix.sync.aligned.m8n8.x4.shared.b16 {%0,%1,%2,%3}, [%4];"
                         : "=r"(ah[0]),"=r"(ah[1]),"=r"(ah[2]),"=r"(ah[3])
                         : "r"(aAddr + s*32));
            asm volatile("ldmatrix.sync.aligned.m8n8.x4.shared.b16 {%0,%1,%2,%3}, [%4];"
                         : "=r"(al[0]),"=r"(al[1]),"=r"(al[2]),"=r"(al[3])
                         : "r"(aAddr + (TG_ALO - TG_AHI) + s*32));
            #pragma unroll
            for (int j = 0; j < 8; j++) {
                uint32_t ba = bAddr + (uint32_t)((jbase + j)*(8*TG_STRIDE) + s*32);
                uint32_t bh0, bh1, bl0, bl1;
                asm volatile("ldmatrix.sync.aligned.m8n8.x2.shared.b16 {%0,%1}, [%2];"
                             : "=r"(bh0), "=r"(bh1) : "r"(ba));
                asm volatile("ldmatrix.sync.aligned.m8n8.x2.shared.b16 {%0,%1}, [%2];"
                             : "=r"(bl0), "=r"(bl1) : "r"(ba + (TG_BLO - TG_BHI)));
                asm volatile("mma.sync.aligned.m16n8k16.row.col.f32.bf16.bf16.f32 "
                             "{%0,%1,%2,%3}, {%4,%5,%6,%7}, {%8,%9}, {%0,%1,%2,%3};"
                             : "+f"(acc[j][0]),"+f"(acc[j][1]),"+f"(acc[j][2]),"+f"(acc[j][3])
                             : "r"(ah[0]),"r"(ah[1]),"r"(ah[2]),"r"(ah[3]),"r"(bh0),"r"(bh1));
                asm volatile("mma.sync.aligned.m16n8k16.row.col.f32.bf16.bf16.f32 "
                             "{%0,%1,%2,%3}, {%4,%5,%6,%7}, {%8,%9}, {%0,%1,%2,%3};"
                             : "+f"(acc[j][0]),"+f"(acc[j][1]),"+f"(acc[j][2]),"+f"(acc[j][3])
                             : "r"(ah[0]),"r"(ah[1]),"r"(ah[2]),"r"(ah[3]),"r"(bl0),"r"(bl1));
                asm volatile("mma.sync.aligned.m16n8k16.row.col.f32.bf16.bf16.f32 "
                             "{%0,%1,%2,%3}, {%4,%5,%6,%7}, {%8,%9}, {%0,%1,%2,%3};"
                             : "+f"(acc[j][0]),"+f"(acc[j][1]),"+f"(acc[j][2]),"+f"(acc[j][3])
                             : "r"(al[0]),"r"(al[1]),"r"(al[2]),"r"(al[3]),"r"(bh0),"r"(bh1));
            }
        }
        __syncthreads();
    }

    {
        int g = lane >> 2, tt = lane & 3;
        int r0 = M0 + R0 + g;
        #pragma unroll
        for (int j = 0; j < 8; j++) {
            int fa = (jbase + j)*8 + 2*tt;
            *(float2*)&Cp[(size_t)r0*128 + fa]     = make_float2(acc[j][0], acc[j][1]);
            *(float2*)&Cp[(size_t)(r0+8)*128 + fa] = make_float2(acc[j][2], acc[j][3]);
        }
    }
}

// -------- filter-network + aggregation, fully tensorized (v4) --------
// Stage A: H = ssp(f@w1+b1) as M128/N128/K32 mma; accumulator fragments map
// 1:1 onto stage-B A-fragments (jn=2s -> klo, jn=2s+1 -> khi). No H smem.
// w2 tiles: 256B stride + XOR swizzle (chunk ^= row&7). f/w1 tiles: 80B stride.
#define OFF_BHI 0
#define OFF_BLO 32768
#define OFF_FHI 65536
#define OFF_FLO 75776
#define OFF_W1HI 86016
#define OFF_W1LO 96256
#define OFF_B1  106496
#define OFF_B2  107008
#define OFF_CM  107520
#define OFF_NB  108032
#define OFF_RED OFF_FHI
#define FA_SMEM 108544

__global__ __launch_bounds__(256, 2)
void filter_agg_kernel(const float* __restrict__ b1g,
                       const float* __restrict__ b2g,
                       const int* __restrict__ nbg, int l)
{
    extern __shared__ char smc[];
    uint32_t sb = smem_u32(smc);
    float* b1s = (float*)(smc + OFF_B1);
    float* b2s = (float*)(smc + OFF_B2);
    float* cms = (float*)(smc + OFF_CM);
    int*   nbs = (int*)(smc + OFF_NB);
    float* red = (float*)(smc + OFF_RED);

    int t = threadIdx.x;
    int lane = t & 31;
    int w = t >> 5;
    int g = lane >> 2;
    int tt = lane & 3;
    int r7 = lane & 7;
    int hb = (lane >> 3) & 1;
    int atom = w >> 2;
    int i0 = blockIdx.x * 2;
    int bofs = (i0 >> 9) << 9;

    // ---- stage 0: cooperative loads ----
    {
        // w2 tiles: [f][128k] -> swizzled 256B rows
        const uint4* hsrc = (const uint4*)(d_w2hi + (size_t)l * 16384);
        const uint4* lsrc = (const uint4*)(d_w2lo + (size_t)l * 16384);
        #pragma unroll
        for (int p = 0; p < 8; p++) {
            int u = t + 256*p;               // 2048 = 128 rows x 16 chunks
            int f = u >> 4, c = u & 15;
            int cs = c ^ (f & 7);
            *(uint4*)(smc + OFF_BHI + f*256 + cs*16) = hsrc[u];
            *(uint4*)(smc + OFF_BLO + f*256 + cs*16) = lsrc[u];
        }
        // f tiles: 128 rows x 32 bf16 (4 uint4), stride 80
        const uint4* fh = (const uint4*)(d_fhi + (size_t)i0 * 64 * 32);
        const uint4* fl = (const uint4*)(d_flo + (size_t)i0 * 64 * 32);
        #pragma unroll
        for (int p = 0; p < 2; p++) {
            int u = t + 256*p;               // 512 = 128 rows x 4 chunks
            int r = u >> 2, c = u & 3;
            *(uint4*)(smc + OFF_FHI + r*80 + c*16) = fh[u];
            *(uint4*)(smc + OFF_FLO + r*80 + c*16) = fl[u];
        }
        // w1 tiles: 128 rows x 32 bf16, stride 80
        const uint4* wh = (const uint4*)(d_w1hi + (size_t)l * 128 * 32);
        const uint4* wl = (const uint4*)(d_w1lo + (size_t)l * 128 * 32);
        #pragma unroll
        for (int p = 0; p < 2; p++) {
            int u = t + 256*p;
            int r = u >> 2, c = u & 3;
            *(uint4*)(smc + OFF_W1HI + r*80 + c*16) = wh[u];
            *(uint4*)(smc + OFF_W1LO + r*80 + c*16) = wl[u];
        }
        if (t < 128) {
            b1s[t] = b1g[l*128 + t];
            b2s[t] = b2g[l*128 + t];
            cms[t] = d_cm[i0*64 + t];
            nbs[t] = nbg[i0*64 + t];
        }
    }
    __syncthreads();

    int row0p = atom*64 + (w & 3)*16 + g;
    int row1p = row0p + 8;

    // ---- stage A: accA = f @ w1 (M128 N128 K32, 3-term split) ----
    float accA[16][4];
    #pragma unroll
    for (int j = 0; j < 16; j++)
        #pragma unroll
        for (int q = 0; q < 4; q++) accA[j][q] = 0.f;
    {
        int R0 = atom*64 + (w & 3)*16;
        uint32_t aAddr = sb + OFF_FHI + (uint32_t)(R0 + (lane & 15))*80 + (uint32_t)(lane & 16);
        uint32_t wBase = sb + OFF_W1HI + (uint32_t)r7*80 + (uint32_t)(hb << 4);
        #pragma unroll
        for (int s2 = 0; s2 < 2; s2++) {
            uint32_t fh[4], fl[4];
            asm volatile("ldmatrix.sync.aligned.m8n8.x4.shared.b16 {%0,%1,%2,%3}, [%4];"
                         : "=r"(fh[0]),"=r"(fh[1]),"=r"(fh[2]),"=r"(fh[3])
                         : "r"(aAddr + s2*32));
            asm volatile("ldmatrix.sync.aligned.m8n8.x4.shared.b16 {%0,%1,%2,%3}, [%4];"
                         : "=r"(fl[0]),"=r"(fl[1]),"=r"(fl[2]),"=r"(fl[3])
                         : "r"(aAddr + (OFF_FLO - OFF_FHI) + s2*32));
            #pragma unroll
            for (int jn = 0; jn < 16; jn++) {
                uint32_t ba = wBase + (uint32_t)(jn*(8*80) + s2*32);
                uint32_t wh0, wh1, wl0, wl1;
                asm volatile("ldmatrix.sync.aligned.m8n8.x2.shared.b16 {%0,%1}, [%2];"
                             : "=r"(wh0), "=r"(wh1) : "r"(ba));
                asm volatile("ldmatrix.sync.aligned.m8n8.x2.shared.b16 {%0,%1}, [%2];"
                             : "=r"(wl0), "=r"(wl1) : "r"(ba + (OFF_W1LO - OFF_W1HI)));
                asm volatile("mma.sync.aligned.m16n8k16.row.col.f32.bf16.bf16.f32 "
                             "{%0,%1,%2,%3}, {%4,%5,%6,%7}, {%8,%9}, {%0,%1,%2,%3};"
                             : "+f"(accA[jn][0]),"+f"(accA[jn][1]),"+f"(accA[jn][2]),"+f"(accA[jn][3])
                             : "r"(fh[0]),"r"(fh[1]),"r"(fh[2]),"r"(fh[3]),"r"(wh0),"r"(wh1));
                asm volatile("mma.sync.aligned.m16n8k16.row.col.f32.bf16.bf16.f32 "
                             "{%0,%1,%2,%3}, {%4,%5,%6,%7}, {%8,%9}, {%0,%1,%2,%3};"
                             : "+f"(accA[jn][0]),"+f"(accA[jn][1]),"+f"(accA[jn][2]),"+f"(accA[jn][3])
                             : "r"(fh[0]),"r"(fh[1]),"r"(fh[2]),"r"(fh[3]),"r"(wl0),"r"(wl1));
                asm volatile("mma.sync.aligned.m16n8k16.row.col.f32.bf16.bf16.f32 "
                             "{%0,%1,%2,%3}, {%4,%5,%6,%7}, {%8,%9}, {%0,%1,%2,%3};"
                             : "+f"(accA[jn][0]),"+f"(accA[jn][1]),"+f"(accA[jn][2]),"+f"(accA[jn][3])
                             : "r"(fl[0]),"r"(fl[1]),"r"(fl[2]),"r"(fl[3]),"r"(wh0),"r"(wh1));
            }
        }
    }

    // ---- convert accA -> stage-B A fragments: H = ssp(accA + b1), split ----
    uint32_t ahi[32], alo[32];
    #pragma unroll
    for (int s = 0; s < 8; s++) {
        int klo = 16*s + 2*tt;
        int khi = klo + 8;
        float2 blo = *(const float2*)&b1s[klo];
        float2 bhi = *(const float2*)&b1s[khi];
        int jl = 2*s, jh = 2*s + 1;
        split2(ssp(accA[jl][0] + blo.x), ssp(accA[jl][1] + blo.y), ahi[s*4+0], alo[s*4+0]);
        split2(ssp(accA[jl][2] + blo.x), ssp(accA[jl][3] + blo.y), ahi[s*4+1], alo[s*4+1]);
        split2(ssp(accA[jh][0] + bhi.x), ssp(accA[jh][1] + bhi.y), ahi[s*4+2], alo[s*4+2]);
        split2(ssp(accA[jh][2] + bhi.x), ssp(accA[jh][3] + bhi.y), ahi[s*4+3], alo[s*4+3]);
    }
    __syncthreads();   // f/w1 tiles dead; red overlays

    // ---- stage B: W = H @ w2^T, fused aggregation fold ----
    float cm0 = cms[row0p], cm1 = cms[row1p];
    const float* yp0 = d_y + (size_t)(bofs + nbs[row0p]) * 128;
    const float* yp1 = d_y + (size_t)(bofs + nbs[row1p]) * 128;

    float part[32];
    #pragma unroll
    for (int q = 0; q < 32; q++) part[q] = 0.f;

    #pragma unroll
    for (int j = 0; j < 16; j++) {
        float c0 = 0.f, c1 = 0.f, c2 = 0.f, c3 = 0.f;
        uint32_t rowAddr = sb + OFF_BHI + (uint32_t)((j*8 + r7) * 256);
        #pragma unroll
        for (int s = 0; s < 8; s++) {
            uint32_t cs = (uint32_t)((2*s + hb) ^ r7);
            uint32_t ba = rowAddr + cs*16;
            uint32_t bh0, bh1, bl0, bl1;
            asm volatile("ldmatrix.sync.aligned.m8n8.x2.shared.b16 {%0,%1}, [%2];"
                         : "=r"(bh0), "=r"(bh1) : "r"(ba));
            asm volatile("ldmatrix.sync.aligned.m8n8.x2.shared.b16 {%0,%1}, [%2];"
                         : "=r"(bl0), "=r"(bl1) : "r"(ba + (OFF_BLO - OFF_BHI)));
            asm volatile("mma.sync.aligned.m16n8k16.row.col.f32.bf16.bf16.f32 "
                         "{%0,%1,%2,%3}, {%4,%5,%6,%7}, {%8,%9}, {%0,%1,%2,%3};"
                         : "+f"(c0), "+f"(c1), "+f"(c2), "+f"(c3)
                         : "r"(ahi[s*4+0]), "r"(ahi[s*4+1]), "r"(ahi[s*4+2]), "r"(ahi[s*4+3]),
                           "r"(bh0), "r"(bh1));
            asm volatile("mma.sync.aligned.m16n8k16.row.col.f32.bf16.bf16.f32 "
                         "{%0,%1,%2,%3}, {%4,%5,%6,%7}, {%8,%9}, {%0,%1,%2,%3};"
                         : "+f"(c0), "+f"(c1), "+f"(c2), "+f"(c3)
                         : "r"(ahi[s*4+0]), "r"(ahi[s*4+1]), "r"(ahi[s*4+2]), "r"(ahi[s*4+3]),
                           "r"(bl0), "r"(bl1));
            asm volatile("mma.sync.aligned.m16n8k16.row.col.f32.bf16.bf16.f32 "
                         "{%0,%1,%2,%3}, {%4,%5,%6,%7}, {%8,%9}, {%0,%1,%2,%3};"
                         : "+f"(c0), "+f"(c1), "+f"(c2), "+f"(c3)
                         : "r"(alo[s*4+0]), "r"(alo[s*4+1]), "r"(alo[s*4+2]), "r"(alo[s*4+3]),
                           "r"(bh0), "r"(bh1));
        }
        int fa = 8*j + 2*tt;
        float2 b2v = *(const float2*)&b2s[fa];
        float2 ya  = *(const float2*)(yp0 + fa);
        float2 yb  = *(const float2*)(yp1 + fa);
        part[2*j]   += cm0*ya.x*(c0 + b2v.x) + cm1*yb.x*(c2 + b2v.x);
        part[2*j+1] += cm0*ya.y*(c1 + b2v.y) + cm1*yb.y*(c3 + b2v.y);
    }

    #pragma unroll
    for (int q = 0; q < 32; q++) {
        part[q] += __shfl_xor_sync(0xffffffffu, part[q], 4);
        part[q] += __shfl_xor_sync(0xffffffffu, part[q], 8);
        part[q] += __shfl_xor_sync(0xffffffffu, part[q], 16);
    }
    if (lane < 4) {
        #pragma unroll
        for (int j = 0; j < 16; j++)
            *(float2*)&red[w*128 + 8*j + 2*tt] = make_float2(part[2*j], part[2*j+1]);
    }
    __syncthreads();
    {
        int a = t >> 7, f = t & 127;
        const float* rb = red + (a*4)*128 + f;
        d_agg[(size_t)(i0 + a)*128 + f] = rb[0] + rb[128] + rb[256] + rb[384];
    }
}

// -------- elementwise residual: x += ssp(v_rad + bc + vang) --------
__global__ __launch_bounds__(128)
void out_elem_kernel(int l) {
    int i = blockIdx.x, t = threadIdx.x;
    float v = d_y[(size_t)i*128 + t] + d_bc[l*128 + t]
            + d_vang[(size_t)l*BA*ND + (size_t)i*128 + t];
    d_x[(size_t)i*128 + t] += ssp(v);
}

__global__ void copy_out_kernel(float* __restrict__ out) {
    int idx = blockIdx.x * 256 + threadIdx.x;
    out[idx] = d_x[idx];
}

extern "C" void kernel_launch(void* const* d_in, const int* in_sizes, int n_in,
                              void* d_out, int out_size) {
    const int*   z      = (const int*)  d_in[0];
    const float* pos    = (const float*)d_in[1];
    const int*   nb     = (const int*)  d_in[2];
    const int*   nmask  = (const int*)  d_in[3];
    const float* Gi     = (const float*)d_in[4];
    const float* emb    = (const float*)d_in[5];
    const float* fw1    = (const float*)d_in[6];
    const float* fb1    = (const float*)d_in[7];
    const float* fw2    = (const float*)d_in[8];
    const float* fb2    = (const float*)d_in[9];
    const float* in2f   = (const float*)d_in[10];
    const float* f2o    = (const float*)d_in[11];
    const float* f2ob   = (const float*)d_in[12];
    const float* dw     = (const float*)d_in[13];
    const float* db     = (const float*)d_in[14];
    const float* angw   = (const float*)d_in[15];
    float* out = (float*)d_out;

    static __nv_bfloat16 *p_i2fhi, *p_i2flo, *p_anghi, *p_anglo, *p_wchi, *p_wclo;
    static float *p_wc;
    cudaGetSymbolAddress((void**)&p_i2fhi, d_i2fhi);
    cudaGetSymbolAddress((void**)&p_i2flo, d_i2flo);
    cudaGetSymbolAddress((void**)&p_anghi, d_anghi);
    cudaGetSymbolAddress((void**)&p_anglo, d_anglo);
    cudaGetSymbolAddress((void**)&p_wchi, d_wchi);
    cudaGetSymbolAddress((void**)&p_wclo, d_wclo);
    cudaGetSymbolAddress((void**)&p_wc, d_wc);

    cudaFuncSetAttribute(filter_agg_kernel,
                         cudaFuncAttributeMaxDynamicSharedMemorySize, FA_SMEM);
    cudaFuncSetAttribute(tgemm_kernel,
                         cudaFuncAttributeMaxDynamicSharedMemorySize, TG_SMEM);

    // prep (layer-invariant)
    embed_kernel<<<BA, 128>>>(z, emb);
    dist_kernel<<<BA, NN>>>(pos, nb, nmask);
    w1split_kernel<<<NL*NF*32/256, 256>>>(fw1);
    w2split_kernel<<<NL*64, 256>>>(fw2);
    bsplit_kernel<<<NL*ND*NF/256, 256>>>(in2f, p_i2fhi, p_i2flo, ND);
    bsplit_kernel<<<NL*NGA*ND/256, 256>>>(angw, p_anghi, p_anglo, NGA);
    wc_kernel<<<dim3(8, NL), 128>>>(f2o, dw);
    bc_kernel<<<NL, 128>>>(f2ob, dw, db);
    bsplit_kernel<<<NL*ND*ND/256, 256>>>(p_wc, p_wchi, p_wclo, ND);

    // angular projections (all layers)
    tgemm_kernel<<<dim3(BA/64, NL), 256, TG_SMEM>>>(Gi, p_anghi, p_anglo, NGA, 0, 1);

    for (int l = 0; l < NL; l++) {
        tgemm_kernel<<<dim3(BA/64, 1), 256, TG_SMEM>>>(nullptr,
            p_i2fhi + (size_t)l*NF*ND, p_i2flo + (size_t)l*NF*ND, ND, 1, 0);
        filter_agg_kernel<<<BA/2, 256, FA_SMEM>>>(fb1, fb2, nb, l);
        tgemm_kernel<<<dim3(BA/64, 1), 256, TG_SMEM>>>(nullptr,
            p_wchi + (size_t)l*ND*ND, p_wclo + (size_t)l*ND*ND, ND, 2, 0);
        out_elem_kernel<<<BA, 128>>>(l);
    }

    copy_out_kernel<<<BA*ND/256, 256>>>(out);
}

// round 13
// speedup vs baseline: 1.5168x; 1.5168x over previous
#include <cuda_runtime.h>
#include <cuda_bf16.h>
#include <math.h>
#include <stdint.h>

#define NB 8
#define NA 512
#define NN 64
#define ND 128
#define NF 128
#define NG 25
#define NL 3
#define NGA 512
#define BA (NB*NA)          // 4096
#define CUTOFF 5.0f
#define RSTART 1.2f
#define LN2F 0.6931471805599453f

// -------- device scratch --------
__device__ float d_x[BA*ND];
__device__ float d_y[BA*NF];
__device__ float d_agg[BA*NF];
__device__ float d_vang[NL*BA*ND];
__device__ float d_cm[BA*NN];
__device__ __nv_bfloat16 d_fhi[BA*NN*32];       // f_ij split, k padded to 32
__device__ __nv_bfloat16 d_flo[BA*NN*32];
__device__ __nv_bfloat16 d_w1hi[NL*NF*32];      // w1^T split [l][f][k32]
__device__ __nv_bfloat16 d_w1lo[NL*NF*32];
__device__ __nv_bfloat16 d_w2hi[NL*NF*NF];      // w2^T split [l][f][k]
__device__ __nv_bfloat16 d_w2lo[NL*NF*NF];
__device__ __nv_bfloat16 d_i2fhi[NL*NF*ND];
__device__ __nv_bfloat16 d_i2flo[NL*NF*ND];
__device__ __nv_bfloat16 d_anghi[NL*ND*NGA];
__device__ __nv_bfloat16 d_anglo[NL*ND*NGA];
__device__ float d_wc[NL*ND*ND];
__device__ __nv_bfloat16 d_wchi[NL*ND*ND];
__device__ __nv_bfloat16 d_wclo[NL*ND*ND];
__device__ float d_bc[NL*ND];

__device__ __forceinline__ float ssp(float v) {
    return fmaxf(v, 0.f) + __logf(1.f + __expf(-fabsf(v))) - LN2F;
}

__device__ __forceinline__ uint32_t smem_u32(const void* p) {
    uint32_t a;
    asm("{ .reg .u64 t; cvta.to.shared.u64 t, %1; cvt.u32.u64 %0, t; }" : "=r"(a) : "l"(p));
    return a;
}

__device__ __forceinline__ void split2(float a, float b, uint32_t& hi, uint32_t& lo) {
    __nv_bfloat16 ah = __float2bfloat16(a), bh = __float2bfloat16(b);
    float ar = a - __bfloat162float(ah);
    float br = b - __bfloat162float(bh);
    __nv_bfloat162 hp; hp.x = ah; hp.y = bh;
    __nv_bfloat162 lp = __floats2bfloat162_rn(ar, br);
    hi = *(uint32_t*)&hp;
    lo = *(uint32_t*)&lp;
}

// -------- embedding gather --------
__global__ void embed_kernel(const int* __restrict__ z, const float* __restrict__ emb) {
    int i = blockIdx.x, t = threadIdx.x;
    d_x[i*ND + t] = emb[z[i]*ND + t];
}

// -------- distances + gaussian smearing (bf16-split) + cutoff*mask --------
__global__ void dist_kernel(const float* __restrict__ pos,
                            const int* __restrict__ nb,
                            const int* __restrict__ nmask) {
    int i = blockIdx.x;
    int n = threadIdx.x;
    int bofs = (i >> 9) << 9;
    float px = pos[i*3+0], py = pos[i*3+1], pz = pos[i*3+2];
    int j = nb[i*NN + n];
    int gj = bofs + j;
    float dx = pos[gj*3+0] - px;
    float dy = pos[gj*3+1] - py;
    float dz = pos[gj*3+2] - pz;
    float r = sqrtf(dx*dx + dy*dy + dz*dz + 1e-12f);
    float m = (float)nmask[i*NN + n];
    d_cm[i*NN + n] = (r <= CUTOFF) ? m : 0.f;
    const float width = (CUTOFF - RSTART) / (float)(NG - 1);
    const float coeff = -0.5f / (width * width);
    __nv_bfloat16* oh = d_fhi + (size_t)(i*NN + n) * 32;
    __nv_bfloat16* ol = d_flo + (size_t)(i*NN + n) * 32;
    #pragma unroll
    for (int g = 0; g < 32; g++) {
        float v = 0.f;
        if (g < NG) {
            float d = r - (RSTART + width * (float)g);
            v = __expf(coeff * d * d);
        }
        __nv_bfloat16 hi = __float2bfloat16(v);
        oh[g] = hi;
        ol[g] = __float2bfloat16(v - __bfloat162float(hi));
    }
}

// -------- prestage: transpose + split w1 [L][25][128] -> [l][f][k32] --------
__global__ void w1split_kernel(const float* __restrict__ w1) {
    int idx = blockIdx.x * 256 + threadIdx.x;     // NL*128*32 = 12288
    int l = idx >> 12;
    int r = idx & 4095;
    int f = r >> 5, k = r & 31;
    float v = (k < NG) ? w1[l*3200 + k*128 + f] : 0.f;
    __nv_bfloat16 hi = __float2bfloat16(v);
    d_w1hi[idx] = hi;
    d_w1lo[idx] = __float2bfloat16(v - __bfloat162float(hi));
}

// -------- prestage: transpose + split [NL][K][128] -> [l][f][K] --------
__global__ void bsplit_kernel(const float* __restrict__ src,
                              __nv_bfloat16* __restrict__ dhi,
                              __nv_bfloat16* __restrict__ dlo, int K) {
    int idx = blockIdx.x * 256 + threadIdx.x;
    int l = idx / (K*128);
    int r = idx % (K*128);
    int k = r >> 7, f = r & 127;
    float v = src[idx];
    __nv_bfloat16 hi = __float2bfloat16(v);
    __nv_bfloat16 lo = __float2bfloat16(v - __bfloat162float(hi));
    int o = l*K*128 + f*K + k;
    dhi[o] = hi;
    dlo[o] = lo;
}

__global__ void w2split_kernel(const float* __restrict__ w2) {
    int idx = blockIdx.x * 256 + threadIdx.x;
    int l = idx >> 14;
    int r = idx & 16383;
    int k = r >> 7, f = r & 127;
    float v = w2[idx];
    __nv_bfloat16 hi = __float2bfloat16(v);
    __nv_bfloat16 lo = __float2bfloat16(v - __bfloat162float(hi));
    int o = l*16384 + f*128 + k;
    d_w2hi[o] = hi;
    d_w2lo[o] = lo;
}

// -------- prestage: composite epilogue weights --------
__global__ __launch_bounds__(128)
void wc_kernel(const float* __restrict__ f2w, const float* __restrict__ dwm) {
    __shared__ float Ash[16][32];
    __shared__ float Bsh[32][128];
    int l = blockIdx.y;
    const float* Am = f2w + (size_t)l*16384;
    const float* Bm = dwm + (size_t)l*16384;
    float* Cm = d_wc + (size_t)l*16384;
    int t = threadIdx.x;
    int row0 = blockIdx.x * 16;
    float acc[16];
    #pragma unroll
    for (int r = 0; r < 16; r++) acc[r] = 0.f;
    for (int kt = 0; kt < 128; kt += 32) {
        #pragma unroll
        for (int p = 0; p < 4; p++) {
            int idx = t + 128*p;
            Ash[idx >> 5][idx & 31] = Am[(row0 + (idx >> 5))*128 + kt + (idx & 31)];
        }
        #pragma unroll 8
        for (int kk = 0; kk < 32; kk++) Bsh[kk][t] = Bm[(kt + kk)*128 + t];
        __syncthreads();
        #pragma unroll
        for (int kk = 0; kk < 32; kk++) {
            float bv = Bsh[kk][t];
            #pragma unroll
            for (int r = 0; r < 16; r++) acc[r] += Ash[r][kk] * bv;
        }
        __syncthreads();
    }
    #pragma unroll
    for (int r = 0; r < 16; r++) Cm[(row0 + r)*128 + t] = acc[r];
}

__global__ void bc_kernel(const float* __restrict__ f2b, const float* __restrict__ dwm,
                          const float* __restrict__ db) {
    int l = blockIdx.x, t = threadIdx.x;
    float acc = db[l*128 + t];
    #pragma unroll 4
    for (int k = 0; k < 128; k++)
        acc += f2b[l*128 + k] * dwm[(size_t)l*16384 + k*128 + t];
    d_bc[l*128 + t] = acc;
}

// -------- tensor GEMM: C[M,128] = A[M,K] @ B[K,128], bf16 hi/lo split --------
#define TG_AHI 0
#define TG_ALO 9216
#define TG_BHI 18432
#define TG_BLO 36864
#define TG_SMEM 55296
#define TG_STRIDE 144

__global__ __launch_bounds__(256, 2)
void tgemm_kernel(const float* __restrict__ Aext,
                  const __nv_bfloat16* __restrict__ BtHi,
                  const __nv_bfloat16* __restrict__ BtLo,
                  int K, int amode, int cmode) {
    extern __shared__ char smc[];
    uint32_t sb = smem_u32(smc);
    int t = threadIdx.x;
    int lane = t & 31;
    int w = t >> 5;
    int l = blockIdx.y;
    int M0 = blockIdx.x * 64;
    const float* Ap = (amode == 1) ? d_x : ((amode == 2) ? d_agg : Aext);
    float* Cp = (cmode == 1) ? (d_vang + (size_t)l*BA*ND) : d_y;
    const __nv_bfloat16* bhiL = BtHi + (size_t)l*128*K;
    const __nv_bfloat16* bloL = BtLo + (size_t)l*128*K;

    int R0 = (w >> 1) * 16;
    int jbase = (w & 1) * 8;

    float acc[8][4];
    #pragma unroll
    for (int j = 0; j < 8; j++)
        #pragma unroll
        for (int q = 0; q < 4; q++) acc[j][q] = 0.f;

    uint32_t aAddr = sb + TG_AHI + (uint32_t)(R0 + (lane & 15))*TG_STRIDE + (uint32_t)(lane & 16);
    uint32_t bAddr = sb + TG_BHI + (uint32_t)(lane & 7)*TG_STRIDE + (uint32_t)((lane & 8) << 1);

    for (int kc = 0; kc < K; kc += 64) {
        #pragma unroll
        for (int p = 0; p < 8; p++) {
            int u = t + 256*p;
            int r = u >> 5, kp = u & 31;
            float2 v = *(const float2*)&Ap[(size_t)(M0 + r)*K + kc + kp*2];
            uint32_t hi, lo;
            split2(v.x, v.y, hi, lo);
            *(uint32_t*)(smc + TG_AHI + r*TG_STRIDE + kp*4) = hi;
            *(uint32_t*)(smc + TG_ALO + r*TG_STRIDE + kp*4) = lo;
        }
        #pragma unroll
        for (int p = 0; p < 4; p++) {
            int u = t + 256*p;
            int f = u >> 3, c = u & 7;
            *(uint4*)(smc + TG_BHI + f*TG_STRIDE + c*16) =
                ((const uint4*)(bhiL + f*K + kc))[c];
            *(uint4*)(smc + TG_BLO + f*TG_STRIDE + c*16) =
                ((const uint4*)(bloL + f*K + kc))[c];
        }
        __syncthreads();

        #pragma unroll
        for (int s = 0; s < 4; s++) {
            uint32_t ah[4], al[4];
            asm volatile("ldmatrix.sync.aligned.m8n8.x4.shared.b16 {%0,%1,%2,%3}, [%4];"
                         : "=r"(ah[0]),"=r"(ah[1]),"=r"(ah[2]),"=r"(ah[3])
                         : "r"(aAddr + s*32));
            asm volatile("ldmatrix.sync.aligned.m8n8.x4.shared.b16 {%0,%1,%2,%3}, [%4];"
                         : "=r"(al[0]),"=r"(al[1]),"=r"(al[2]),"=r"(al[3])
                         : "r"(aAddr + (TG_ALO - TG_AHI) + s*32));
            #pragma unroll
            for (int j = 0; j < 8; j++) {
                uint32_t ba = bAddr + (uint32_t)((jbase + j)*(8*TG_STRIDE) + s*32);
                uint32_t bh0, bh1, bl0, bl1;
                asm volatile("ldmatrix.sync.aligned.m8n8.x2.shared.b16 {%0,%1}, [%2];"
                             : "=r"(bh0), "=r"(bh1) : "r"(ba));
                asm volatile("ldmatrix.sync.aligned.m8n8.x2.shared.b16 {%0,%1}, [%2];"
                             : "=r"(bl0), "=r"(bl1) : "r"(ba + (TG_BLO - TG_BHI)));
                asm volatile("mma.sync.aligned.m16n8k16.row.col.f32.bf16.bf16.f32 "
                             "{%0,%1,%2,%3}, {%4,%5,%6,%7}, {%8,%9}, {%0,%1,%2,%3};"
                             : "+f"(acc[j][0]),"+f"(acc[j][1]),"+f"(acc[j][2]),"+f"(acc[j][3])
                             : "r"(ah[0]),"r"(ah[1]),"r"(ah[2]),"r"(ah[3]),"r"(bh0),"r"(bh1));
                asm volatile("mma.sync.aligned.m16n8k16.row.col.f32.bf16.bf16.f32 "
                             "{%0,%1,%2,%3}, {%4,%5,%6,%7}, {%8,%9}, {%0,%1,%2,%3};"
                             : "+f"(acc[j][0]),"+f"(acc[j][1]),"+f"(acc[j][2]),"+f"(acc[j][3])
                             : "r"(ah[0]),"r"(ah[1]),"r"(ah[2]),"r"(ah[3]),"r"(bl0),"r"(bl1));
                asm volatile("mma.sync.aligned.m16n8k16.row.col.f32.bf16.bf16.f32 "
                             "{%0,%1,%2,%3}, {%4,%5,%6,%7}, {%8,%9}, {%0,%1,%2,%3};"
                             : "+f"(acc[j][0]),"+f"(acc[j][1]),"+f"(acc[j][2]),"+f"(acc[j][3])
                             : "r"(al[0]),"r"(al[1]),"r"(al[2]),"r"(al[3]),"r"(bh0),"r"(bh1));
            }
        }
        __syncthreads();
    }

    {
        int g = lane >> 2, tt = lane & 3;
        int r0 = M0 + R0 + g;
        #pragma unroll
        for (int j = 0; j < 8; j++) {
            int fa = (jbase + j)*8 + 2*tt;
            *(float2*)&Cp[(size_t)r0*128 + fa]     = make_float2(acc[j][0], acc[j][1]);
            *(float2*)&Cp[(size_t)(r0+8)*128 + fa] = make_float2(acc[j][2], acc[j][3]);
        }
    }
}

// -------- filter-network + aggregation, tensorized, register-lean (v5) --------
// Stage A interleaved per k-step: accumulator pair (8 regs) converted to
// A-fragments immediately -> peak regs ~100, no spills at 2 CTAs/SM.
#define OFF_BHI 0
#define OFF_BLO 32768
#define OFF_FHI 65536
#define OFF_FLO 75776
#define OFF_W1HI 86016
#define OFF_W1LO 96256
#define OFF_B1  106496
#define OFF_B2  107008
#define OFF_CM  107520
#define OFF_NB  108032
#define OFF_RED OFF_FHI
#define FA_SMEM 108544

__global__ __launch_bounds__(256, 2)
void filter_agg_kernel(const float* __restrict__ b1g,
                       const float* __restrict__ b2g,
                       const int* __restrict__ nbg, int l)
{
    extern __shared__ char smc[];
    uint32_t sb = smem_u32(smc);
    float* b1s = (float*)(smc + OFF_B1);
    float* b2s = (float*)(smc + OFF_B2);
    float* cms = (float*)(smc + OFF_CM);
    int*   nbs = (int*)(smc + OFF_NB);
    float* red = (float*)(smc + OFF_RED);

    int t = threadIdx.x;
    int lane = t & 31;
    int w = t >> 5;
    int g = lane >> 2;
    int tt = lane & 3;
    int r7 = lane & 7;
    int hb = (lane >> 3) & 1;
    int atom = w >> 2;
    int i0 = blockIdx.x * 2;
    int bofs = (i0 >> 9) << 9;

    // ---- stage 0: cooperative loads ----
    {
        const uint4* hsrc = (const uint4*)(d_w2hi + (size_t)l * 16384);
        const uint4* lsrc = (const uint4*)(d_w2lo + (size_t)l * 16384);
        #pragma unroll
        for (int p = 0; p < 8; p++) {
            int u = t + 256*p;               // 2048 = 128 rows x 16 chunks
            int f = u >> 4, c = u & 15;
            int cs = c ^ (f & 7);
            *(uint4*)(smc + OFF_BHI + f*256 + cs*16) = hsrc[u];
            *(uint4*)(smc + OFF_BLO + f*256 + cs*16) = lsrc[u];
        }
        const uint4* fh = (const uint4*)(d_fhi + (size_t)i0 * 64 * 32);
        const uint4* fl = (const uint4*)(d_flo + (size_t)i0 * 64 * 32);
        #pragma unroll
        for (int p = 0; p < 2; p++) {
            int u = t + 256*p;               // 512 = 128 rows x 4 chunks
            int r = u >> 2, c = u & 3;
            *(uint4*)(smc + OFF_FHI + r*80 + c*16) = fh[u];
            *(uint4*)(smc + OFF_FLO + r*80 + c*16) = fl[u];
        }
        const uint4* wh = (const uint4*)(d_w1hi + (size_t)l * 128 * 32);
        const uint4* wl = (const uint4*)(d_w1lo + (size_t)l * 128 * 32);
        #pragma unroll
        for (int p = 0; p < 2; p++) {
            int u = t + 256*p;
            int r = u >> 2, c = u & 3;
            *(uint4*)(smc + OFF_W1HI + r*80 + c*16) = wh[u];
            *(uint4*)(smc + OFF_W1LO + r*80 + c*16) = wl[u];
        }
        if (t < 128) {
            b1s[t] = b1g[l*128 + t];
            b2s[t] = b2g[l*128 + t];
            cms[t] = d_cm[i0*64 + t];
            nbs[t] = nbg[i0*64 + t];
        }
    }
    __syncthreads();

    int row0p = atom*64 + (w & 3)*16 + g;
    int row1p = row0p + 8;

    // ---- stage A (interleaved): per k-step s, compute 2 acc pairs, convert ----
    uint32_t ahi[32], alo[32];
    {
        int R0 = atom*64 + (w & 3)*16;
        uint32_t aAddr = sb + OFF_FHI + (uint32_t)(R0 + (lane & 15))*80 + (uint32_t)(lane & 16);
        uint32_t wBase = sb + OFF_W1HI + (uint32_t)r7*80 + (uint32_t)(hb << 4);
        // f fragments for both k-chunks of the K=32 input
        uint32_t fh[2][4], fl[2][4];
        #pragma unroll
        for (int s2 = 0; s2 < 2; s2++) {
            asm volatile("ldmatrix.sync.aligned.m8n8.x4.shared.b16 {%0,%1,%2,%3}, [%4];"
                         : "=r"(fh[s2][0]),"=r"(fh[s2][1]),"=r"(fh[s2][2]),"=r"(fh[s2][3])
                         : "r"(aAddr + s2*32));
            asm volatile("ldmatrix.sync.aligned.m8n8.x4.shared.b16 {%0,%1,%2,%3}, [%4];"
                         : "=r"(fl[s2][0]),"=r"(fl[s2][1]),"=r"(fl[s2][2]),"=r"(fl[s2][3])
                         : "r"(aAddr + (OFF_FLO - OFF_FHI) + s2*32));
        }
        #pragma unroll
        for (int s = 0; s < 8; s++) {
            float aP[2][4];
            #pragma unroll
            for (int h = 0; h < 2; h++)
                #pragma unroll
                for (int q = 0; q < 4; q++) aP[h][q] = 0.f;
            #pragma unroll
            for (int h = 0; h < 2; h++) {          // jn = 2s + h
                int jn = 2*s + h;
                #pragma unroll
                for (int s2 = 0; s2 < 2; s2++) {
                    uint32_t ba = wBase + (uint32_t)(jn*(8*80) + s2*32);
                    uint32_t wh0, wh1, wl0, wl1;
                    asm volatile("ldmatrix.sync.aligned.m8n8.x2.shared.b16 {%0,%1}, [%2];"
                                 : "=r"(wh0), "=r"(wh1) : "r"(ba));
                    asm volatile("ldmatrix.sync.aligned.m8n8.x2.shared.b16 {%0,%1}, [%2];"
                                 : "=r"(wl0), "=r"(wl1) : "r"(ba + (OFF_W1LO - OFF_W1HI)));
                    asm volatile("mma.sync.aligned.m16n8k16.row.col.f32.bf16.bf16.f32 "
                                 "{%0,%1,%2,%3}, {%4,%5,%6,%7}, {%8,%9}, {%0,%1,%2,%3};"
                                 : "+f"(aP[h][0]),"+f"(aP[h][1]),"+f"(aP[h][2]),"+f"(aP[h][3])
                                 : "r"(fh[s2][0]),"r"(fh[s2][1]),"r"(fh[s2][2]),"r"(fh[s2][3]),
                                   "r"(wh0),"r"(wh1));
                    asm volatile("mma.sync.aligned.m16n8k16.row.col.f32.bf16.bf16.f32 "
                                 "{%0,%1,%2,%3}, {%4,%5,%6,%7}, {%8,%9}, {%0,%1,%2,%3};"
                                 : "+f"(aP[h][0]),"+f"(aP[h][1]),"+f"(aP[h][2]),"+f"(aP[h][3])
                                 : "r"(fh[s2][0]),"r"(fh[s2][1]),"r"(fh[s2][2]),"r"(fh[s2][3]),
                                   "r"(wl0),"r"(wl1));
                    asm volatile("mma.sync.aligned.m16n8k16.row.col.f32.bf16.bf16.f32 "
                                 "{%0,%1,%2,%3}, {%4,%5,%6,%7}, {%8,%9}, {%0,%1,%2,%3};"
                                 : "+f"(aP[h][0]),"+f"(aP[h][1]),"+f"(aP[h][2]),"+f"(aP[h][3])
                                 : "r"(fl[s2][0]),"r"(fl[s2][1]),"r"(fl[s2][2]),"r"(fl[s2][3]),
                                   "r"(wh0),"r"(wh1));
                }
            }
            // convert to stage-B A fragments: H = ssp(acc + b1), bf16 split
            int klo = 16*s + 2*tt;
            float2 blo = *(const float2*)&b1s[klo];
            float2 bhi = *(const float2*)&b1s[klo + 8];
            split2(ssp(aP[0][0] + blo.x), ssp(aP[0][1] + blo.y), ahi[s*4+0], alo[s*4+0]);
            split2(ssp(aP[0][2] + blo.x), ssp(aP[0][3] + blo.y), ahi[s*4+1], alo[s*4+1]);
            split2(ssp(aP[1][0] + bhi.x), ssp(aP[1][1] + bhi.y), ahi[s*4+2], alo[s*4+2]);
            split2(ssp(aP[1][2] + bhi.x), ssp(aP[1][3] + bhi.y), ahi[s*4+3], alo[s*4+3]);
        }
    }
    __syncthreads();   // f/w1 tiles dead; red overlays

    // ---- stage B: W = H @ w2^T, fused aggregation fold ----
    float cm0 = cms[row0p], cm1 = cms[row1p];
    const float* yp0 = d_y + (size_t)(bofs + nbs[row0p]) * 128;
    const float* yp1 = d_y + (size_t)(bofs + nbs[row1p]) * 128;

    float part[32];
    #pragma unroll
    for (int q = 0; q < 32; q++) part[q] = 0.f;

    #pragma unroll
    for (int j = 0; j < 16; j++) {
        float c0 = 0.f, c1 = 0.f, c2 = 0.f, c3 = 0.f;
        uint32_t rowAddr = sb + OFF_BHI + (uint32_t)((j*8 + r7) * 256);
        #pragma unroll
        for (int s = 0; s < 8; s++) {
            uint32_t cs = (uint32_t)((2*s + hb) ^ r7);
            uint32_t ba = rowAddr + cs*16;
            uint32_t bh0, bh1, bl0, bl1;
            asm volatile("ldmatrix.sync.aligned.m8n8.x2.shared.b16 {%0,%1}, [%2];"
                         : "=r"(bh0), "=r"(bh1) : "r"(ba));
            asm volatile("ldmatrix.sync.aligned.m8n8.x2.shared.b16 {%0,%1}, [%2];"
                         : "=r"(bl0), "=r"(bl1) : "r"(ba + (OFF_BLO - OFF_BHI)));
            asm volatile("mma.sync.aligned.m16n8k16.row.col.f32.bf16.bf16.f32 "
                         "{%0,%1,%2,%3}, {%4,%5,%6,%7}, {%8,%9}, {%0,%1,%2,%3};"
                         : "+f"(c0), "+f"(c1), "+f"(c2), "+f"(c3)
                         : "r"(ahi[s*4+0]), "r"(ahi[s*4+1]), "r"(ahi[s*4+2]), "r"(ahi[s*4+3]),
                           "r"(bh0), "r"(bh1));
            asm volatile("mma.sync.aligned.m16n8k16.row.col.f32.bf16.bf16.f32 "
                         "{%0,%1,%2,%3}, {%4,%5,%6,%7}, {%8,%9}, {%0,%1,%2,%3};"
                         : "+f"(c0), "+f"(c1), "+f"(c2), "+f"(c3)
                         : "r"(ahi[s*4+0]), "r"(ahi[s*4+1]), "r"(ahi[s*4+2]), "r"(ahi[s*4+3]),
                           "r"(bl0), "r"(bl1));
            asm volatile("mma.sync.aligned.m16n8k16.row.col.f32.bf16.bf16.f32 "
                         "{%0,%1,%2,%3}, {%4,%5,%6,%7}, {%8,%9}, {%0,%1,%2,%3};"
                         : "+f"(c0), "+f"(c1), "+f"(c2), "+f"(c3)
                         : "r"(alo[s*4+0]), "r"(alo[s*4+1]), "r"(alo[s*4+2]), "r"(alo[s*4+3]),
                           "r"(bh0), "r"(bh1));
        }
        int fa = 8*j + 2*tt;
        float2 b2v = *(const float2*)&b2s[fa];
        float2 ya  = *(const float2*)(yp0 + fa);
        float2 yb  = *(const float2*)(yp1 + fa);
        part[2*j]   += cm0*ya.x*(c0 + b2v.x) + cm1*yb.x*(c2 + b2v.x);
        part[2*j+1] += cm0*ya.y*(c1 + b2v.y) + cm1*yb.y*(c3 + b2v.y);
    }

    #pragma unroll
    for (int q = 0; q < 32; q++) {
        part[q] += __shfl_xor_sync(0xffffffffu, part[q], 4);
        part[q] += __shfl_xor_sync(0xffffffffu, part[q], 8);
        part[q] += __shfl_xor_sync(0xffffffffu, part[q], 16);
    }
    if (lane < 4) {
        #pragma unroll
        for (int j = 0; j < 16; j++)
            *(float2*)&red[w*128 + 8*j + 2*tt] = make_float2(part[2*j], part[2*j+1]);
    }
    __syncthreads();
    {
        int a = t >> 7, f = t & 127;
        const float* rb = red + (a*4)*128 + f;
        d_agg[(size_t)(i0 + a)*128 + f] = rb[0] + rb[128] + rb[256] + rb[384];
    }
}

// -------- elementwise residual: x += ssp(v_rad + bc + vang) --------
__global__ __launch_bounds__(128)
void out_elem_kernel(int l) {
    int i = blockIdx.x, t = threadIdx.x;
    float v = d_y[(size_t)i*128 + t] + d_bc[l*128 + t]
            + d_vang[(size_t)l*BA*ND + (size_t)i*128 + t];
    d_x[(size_t)i*128 + t] += ssp(v);
}

__global__ void copy_out_kernel(float* __restrict__ out) {
    int idx = blockIdx.x * 256 + threadIdx.x;
    out[idx] = d_x[idx];
}

extern "C" void kernel_launch(void* const* d_in, const int* in_sizes, int n_in,
                              void* d_out, int out_size) {
    const int*   z      = (const int*)  d_in[0];
    const float* pos    = (const float*)d_in[1];
    const int*   nb     = (const int*)  d_in[2];
    const int*   nmask  = (const int*)  d_in[3];
    const float* Gi     = (const float*)d_in[4];
    const float* emb    = (const float*)d_in[5];
    const float* fw1    = (const float*)d_in[6];
    const float* fb1    = (const float*)d_in[7];
    const float* fw2    = (const float*)d_in[8];
    const float* fb2    = (const float*)d_in[9];
    const float* in2f   = (const float*)d_in[10];
    const float* f2o    = (const float*)d_in[11];
    const float* f2ob   = (const float*)d_in[12];
    const float* dw     = (const float*)d_in[13];
    const float* db     = (const float*)d_in[14];
    const float* angw   = (const float*)d_in[15];
    float* out = (float*)d_out;

    static __nv_bfloat16 *p_i2fhi, *p_i2flo, *p_anghi, *p_anglo, *p_wchi, *p_wclo;
    static float *p_wc;
    cudaGetSymbolAddress((void**)&p_i2fhi, d_i2fhi);
    cudaGetSymbolAddress((void**)&p_i2flo, d_i2flo);
    cudaGetSymbolAddress((void**)&p_anghi, d_anghi);
    cudaGetSymbolAddress((void**)&p_anglo, d_anglo);
    cudaGetSymbolAddress((void**)&p_wchi, d_wchi);
    cudaGetSymbolAddress((void**)&p_wclo, d_wclo);
    cudaGetSymbolAddress((void**)&p_wc, d_wc);

    cudaFuncSetAttribute(filter_agg_kernel,
                         cudaFuncAttributeMaxDynamicSharedMemorySize, FA_SMEM);
    cudaFuncSetAttribute(tgemm_kernel,
                         cudaFuncAttributeMaxDynamicSharedMemorySize, TG_SMEM);

    // prep (layer-invariant)
    embed_kernel<<<BA, 128>>>(z, emb);
    dist_kernel<<<BA, NN>>>(pos, nb, nmask);
    w1split_kernel<<<NL*NF*32/256, 256>>>(fw1);
    w2split_kernel<<<NL*64, 256>>>(fw2);
    bsplit_kernel<<<NL*ND*NF/256, 256>>>(in2f, p_i2fhi, p_i2flo, ND);
    bsplit_kernel<<<NL*NGA*ND/256, 256>>>(angw, p_anghi, p_anglo, NGA);
    wc_kernel<<<dim3(8, NL), 128>>>(f2o, dw);
    bc_kernel<<<NL, 128>>>(f2ob, dw, db);
    bsplit_kernel<<<NL*ND*ND/256, 256>>>(p_wc, p_wchi, p_wclo, ND);

    // angular projections (all layers)
    tgemm_kernel<<<dim3(BA/64, NL), 256, TG_SMEM>>>(Gi, p_anghi, p_anglo, NGA, 0, 1);

    for (int l = 0; l < NL; l++) {
        tgemm_kernel<<<dim3(BA/64, 1), 256, TG_SMEM>>>(nullptr,
            p_i2fhi + (size_t)l*NF*ND, p_i2flo + (size_t)l*NF*ND, ND, 1, 0);
        filter_agg_kernel<<<BA/2, 256, FA_SMEM>>>(fb1, fb2, nb, l);
        tgemm_kernel<<<dim3(BA/64, 1), 256, TG_SMEM>>>(nullptr,
            p_wchi + (size_t)l*ND*ND, p_wclo + (size_t)l*ND*ND, ND, 2, 0);
        out_elem_kernel<<<BA, 128>>>(l);
    }

    copy_out_kernel<<<BA*ND/256, 256>>>(out);
}

// round 14
// speedup vs baseline: 1.5658x; 1.0323x over previous
#include <cuda_runtime.h>
#include <cuda_bf16.h>
#include <math.h>
#include <stdint.h>

#define NB 8
#define NA 512
#define NN 64
#define ND 128
#define NF 128
#define NG 25
#define NL 3
#define NGA 512
#define BA (NB*NA)          // 4096
#define CUTOFF 5.0f
#define RSTART 1.2f
#define LN2F 0.6931471805599453f

// -------- device scratch --------
__device__ float d_x[BA*ND];
__device__ float d_y[BA*NF];
__device__ float d_agg[BA*NF];
__device__ float d_vang[NL*BA*ND];
__device__ float d_cm[BA*NN];
__device__ __nv_bfloat16 d_fhi[BA*NN*32];
__device__ __nv_bfloat16 d_flo[BA*NN*32];
__device__ __nv_bfloat16 d_w1hi[NL*NF*32];
__device__ __nv_bfloat16 d_w1lo[NL*NF*32];
__device__ __nv_bfloat16 d_w2hi[NL*NF*NF];
__device__ __nv_bfloat16 d_w2lo[NL*NF*NF];
__device__ __nv_bfloat16 d_i2fhi[NL*NF*ND];
__device__ __nv_bfloat16 d_i2flo[NL*NF*ND];
__device__ __nv_bfloat16 d_anghi[NL*ND*NGA];
__device__ __nv_bfloat16 d_anglo[NL*ND*NGA];
__device__ float d_wc[NL*ND*ND];
__device__ __nv_bfloat16 d_wchi[NL*ND*ND];
__device__ __nv_bfloat16 d_wclo[NL*ND*ND];
__device__ float d_bc[NL*ND];

__device__ __forceinline__ float ssp(float v) {
    return fmaxf(v, 0.f) + __logf(1.f + __expf(-fabsf(v))) - LN2F;
}

__device__ __forceinline__ uint32_t smem_u32(const void* p) {
    uint32_t a;
    asm("{ .reg .u64 t; cvta.to.shared.u64 t, %1; cvt.u32.u64 %0, t; }" : "=r"(a) : "l"(p));
    return a;
}

__device__ __forceinline__ void split2(float a, float b, uint32_t& hi, uint32_t& lo) {
    __nv_bfloat16 ah = __float2bfloat16(a), bh = __float2bfloat16(b);
    float ar = a - __bfloat162float(ah);
    float br = b - __bfloat162float(bh);
    __nv_bfloat162 hp; hp.x = ah; hp.y = bh;
    __nv_bfloat162 lp = __floats2bfloat162_rn(ar, br);
    hi = *(uint32_t*)&hp;
    lo = *(uint32_t*)&lp;
}

// -------- embedding gather --------
__global__ void embed_kernel(const int* __restrict__ z, const float* __restrict__ emb) {
    int i = blockIdx.x, t = threadIdx.x;
    d_x[i*ND + t] = emb[z[i]*ND + t];
}

// -------- distances + gaussian smearing (bf16-split) + cutoff*mask --------
__global__ void dist_kernel(const float* __restrict__ pos,
                            const int* __restrict__ nb,
                            const int* __restrict__ nmask) {
    int i = blockIdx.x;
    int n = threadIdx.x;
    int bofs = (i >> 9) << 9;
    float px = pos[i*3+0], py = pos[i*3+1], pz = pos[i*3+2];
    int j = nb[i*NN + n];
    int gj = bofs + j;
    float dx = pos[gj*3+0] - px;
    float dy = pos[gj*3+1] - py;
    float dz = pos[gj*3+2] - pz;
    float r = sqrtf(dx*dx + dy*dy + dz*dz + 1e-12f);
    float m = (float)nmask[i*NN + n];
    d_cm[i*NN + n] = (r <= CUTOFF) ? m : 0.f;
    const float width = (CUTOFF - RSTART) / (float)(NG - 1);
    const float coeff = -0.5f / (width * width);
    __nv_bfloat16* oh = d_fhi + (size_t)(i*NN + n) * 32;
    __nv_bfloat16* ol = d_flo + (size_t)(i*NN + n) * 32;
    #pragma unroll
    for (int g = 0; g < 32; g++) {
        float v = 0.f;
        if (g < NG) {
            float d = r - (RSTART + width * (float)g);
            v = __expf(coeff * d * d);
        }
        __nv_bfloat16 hi = __float2bfloat16(v);
        oh[g] = hi;
        ol[g] = __float2bfloat16(v - __bfloat162float(hi));
    }
}

// -------- prestage: all weight transpose+splits in ONE launch --------
// seg0 w1 [0,12288)  seg1 w2 [12288,61440)  seg2 i2f [61440,110592)
// seg3 ang [110592,307200)
__global__ void allsplit_kernel(const float* __restrict__ w1,
                                const float* __restrict__ w2,
                                const float* __restrict__ i2f,
                                const float* __restrict__ ang) {
    int idx = blockIdx.x * 256 + threadIdx.x;
    float v;
    __nv_bfloat16 *ph, *pl;
    int o;
    if (idx < 12288) {
        int l = idx >> 12, r = idx & 4095;
        int f = r >> 5, k = r & 31;
        v = (k < NG) ? w1[l*3200 + k*128 + f] : 0.f;
        ph = d_w1hi; pl = d_w1lo; o = idx;
    } else if (idx < 61440) {
        int u = idx - 12288;
        int l = u >> 14, r = u & 16383;
        int k = r >> 7, f = r & 127;
        v = w2[u];
        ph = d_w2hi; pl = d_w2lo; o = l*16384 + f*128 + k;
    } else if (idx < 110592) {
        int u = idx - 61440;
        int l = u >> 14, r = u & 16383;
        int k = r >> 7, f = r & 127;
        v = i2f[u];
        ph = d_i2fhi; pl = d_i2flo; o = l*16384 + f*128 + k;
    } else {
        int u = idx - 110592;
        int l = u >> 16, r = u & 65535;
        int k = r >> 7, f = r & 127;
        v = ang[u];
        ph = d_anghi; pl = d_anglo; o = l*65536 + f*512 + k;
    }
    __nv_bfloat16 hi = __float2bfloat16(v);
    ph[o] = hi;
    pl[o] = __float2bfloat16(v - __bfloat162float(hi));
}

// -------- prestage: transpose + split [NL][K][128] -> [l][f][K] (for Wc) --------
__global__ void bsplit_kernel(const float* __restrict__ src,
                              __nv_bfloat16* __restrict__ dhi,
                              __nv_bfloat16* __restrict__ dlo, int K) {
    int idx = blockIdx.x * 256 + threadIdx.x;
    int l = idx / (K*128);
    int r = idx % (K*128);
    int k = r >> 7, f = r & 127;
    float v = src[idx];
    __nv_bfloat16 hi = __float2bfloat16(v);
    __nv_bfloat16 lo = __float2bfloat16(v - __bfloat162float(hi));
    int o = l*K*128 + f*K + k;
    dhi[o] = hi;
    dlo[o] = lo;
}

// -------- prestage: composite epilogue weights --------
__global__ __launch_bounds__(128)
void wc_kernel(const float* __restrict__ f2w, const float* __restrict__ dwm) {
    __shared__ float Ash[16][32];
    __shared__ float Bsh[32][128];
    int l = blockIdx.y;
    const float* Am = f2w + (size_t)l*16384;
    const float* Bm = dwm + (size_t)l*16384;
    float* Cm = d_wc + (size_t)l*16384;
    int t = threadIdx.x;
    int row0 = blockIdx.x * 16;
    float acc[16];
    #pragma unroll
    for (int r = 0; r < 16; r++) acc[r] = 0.f;
    for (int kt = 0; kt < 128; kt += 32) {
        #pragma unroll
        for (int p = 0; p < 4; p++) {
            int idx = t + 128*p;
            Ash[idx >> 5][idx & 31] = Am[(row0 + (idx >> 5))*128 + kt + (idx & 31)];
        }
        #pragma unroll 8
        for (int kk = 0; kk < 32; kk++) Bsh[kk][t] = Bm[(kt + kk)*128 + t];
        __syncthreads();
        #pragma unroll
        for (int kk = 0; kk < 32; kk++) {
            float bv = Bsh[kk][t];
            #pragma unroll
            for (int r = 0; r < 16; r++) acc[r] += Ash[r][kk] * bv;
        }
        __syncthreads();
    }
    #pragma unroll
    for (int r = 0; r < 16; r++) Cm[(row0 + r)*128 + t] = acc[r];
}

__global__ void bc_kernel(const float* __restrict__ f2b, const float* __restrict__ dwm,
                          const float* __restrict__ db) {
    int l = blockIdx.x, t = threadIdx.x;
    float acc = db[l*128 + t];
    #pragma unroll 4
    for (int k = 0; k < 128; k++)
        acc += f2b[l*128 + k] * dwm[(size_t)l*16384 + k*128 + t];
    d_bc[l*128 + t] = acc;
}

// -------- tensor GEMM: C[M,128] = A[M,K] @ B[K,128], bf16 hi/lo split --------
// cmode 0: C=d_y  1: C=d_vang[blockIdx.y]  3: fused residual x += ssp(acc+bc+vang)
#define TG_AHI 0
#define TG_ALO 9216
#define TG_BHI 18432
#define TG_BLO 36864
#define TG_SMEM 55296
#define TG_STRIDE 144

__global__ __launch_bounds__(256, 2)
void tgemm_kernel(const float* __restrict__ Aext,
                  const __nv_bfloat16* __restrict__ BtHi,
                  const __nv_bfloat16* __restrict__ BtLo,
                  int K, int amode, int cmode, int layer) {
    extern __shared__ char smc[];
    uint32_t sb = smem_u32(smc);
    int t = threadIdx.x;
    int lane = t & 31;
    int w = t >> 5;
    int l = blockIdx.y;
    int M0 = blockIdx.x * 64;
    const float* Ap = (amode == 1) ? d_x : ((amode == 2) ? d_agg : Aext);
    const __nv_bfloat16* bhiL = BtHi + (size_t)l*128*K;
    const __nv_bfloat16* bloL = BtLo + (size_t)l*128*K;

    int R0 = (w >> 1) * 16;
    int jbase = (w & 1) * 8;

    float acc[8][4];
    #pragma unroll
    for (int j = 0; j < 8; j++)
        #pragma unroll
        for (int q = 0; q < 4; q++) acc[j][q] = 0.f;

    uint32_t aAddr = sb + TG_AHI + (uint32_t)(R0 + (lane & 15))*TG_STRIDE + (uint32_t)(lane & 16);
    uint32_t bAddr = sb + TG_BHI + (uint32_t)(lane & 7)*TG_STRIDE + (uint32_t)((lane & 8) << 1);

    for (int kc = 0; kc < K; kc += 64) {
        #pragma unroll
        for (int p = 0; p < 8; p++) {
            int u = t + 256*p;
            int r = u >> 5, kp = u & 31;
            float2 v = *(const float2*)&Ap[(size_t)(M0 + r)*K + kc + kp*2];
            uint32_t hi, lo;
            split2(v.x, v.y, hi, lo);
            *(uint32_t*)(smc + TG_AHI + r*TG_STRIDE + kp*4) = hi;
            *(uint32_t*)(smc + TG_ALO + r*TG_STRIDE + kp*4) = lo;
        }
        #pragma unroll
        for (int p = 0; p < 4; p++) {
            int u = t + 256*p;
            int f = u >> 3, c = u & 7;
            *(uint4*)(smc + TG_BHI + f*TG_STRIDE + c*16) =
                ((const uint4*)(bhiL + f*K + kc))[c];
            *(uint4*)(smc + TG_BLO + f*TG_STRIDE + c*16) =
                ((const uint4*)(bloL + f*K + kc))[c];
        }
        __syncthreads();

        #pragma unroll
        for (int s = 0; s < 4; s++) {
            uint32_t ah[4], al[4];
            asm volatile("ldmatrix.sync.aligned.m8n8.x4.shared.b16 {%0,%1,%2,%3}, [%4];"
                         : "=r"(ah[0]),"=r"(ah[1]),"=r"(ah[2]),"=r"(ah[3])
                         : "r"(aAddr + s*32));
            asm volatile("ldmatrix.sync.aligned.m8n8.x4.shared.b16 {%0,%1,%2,%3}, [%4];"
                         : "=r"(al[0]),"=r"(al[1]),"=r"(al[2]),"=r"(al[3])
                         : "r"(aAddr + (TG_ALO - TG_AHI) + s*32));
            #pragma unroll
            for (int j = 0; j < 8; j++) {
                uint32_t ba = bAddr + (uint32_t)((jbase + j)*(8*TG_STRIDE) + s*32);
                uint32_t bh0, bh1, bl0, bl1;
                asm volatile("ldmatrix.sync.aligned.m8n8.x2.shared.b16 {%0,%1}, [%2];"
                             : "=r"(bh0), "=r"(bh1) : "r"(ba));
                asm volatile("ldmatrix.sync.aligned.m8n8.x2.shared.b16 {%0,%1}, [%2];"
                             : "=r"(bl0), "=r"(bl1) : "r"(ba + (TG_BLO - TG_BHI)));
                asm volatile("mma.sync.aligned.m16n8k16.row.col.f32.bf16.bf16.f32 "
                             "{%0,%1,%2,%3}, {%4,%5,%6,%7}, {%8,%9}, {%0,%1,%2,%3};"
                             : "+f"(acc[j][0]),"+f"(acc[j][1]),"+f"(acc[j][2]),"+f"(acc[j][3])
                             : "r"(ah[0]),"r"(ah[1]),"r"(ah[2]),"r"(ah[3]),"r"(bh0),"r"(bh1));
                asm volatile("mma.sync.aligned.m16n8k16.row.col.f32.bf16.bf16.f32 "
                             "{%0,%1,%2,%3}, {%4,%5,%6,%7}, {%8,%9}, {%0,%1,%2,%3};"
                             : "+f"(acc[j][0]),"+f"(acc[j][1]),"+f"(acc[j][2]),"+f"(acc[j][3])
                             : "r"(ah[0]),"r"(ah[1]),"r"(ah[2]),"r"(ah[3]),"r"(bl0),"r"(bl1));
                asm volatile("mma.sync.aligned.m16n8k16.row.col.f32.bf16.bf16.f32 "
                             "{%0,%1,%2,%3}, {%4,%5,%6,%7}, {%8,%9}, {%0,%1,%2,%3};"
                             : "+f"(acc[j][0]),"+f"(acc[j][1]),"+f"(acc[j][2]),"+f"(acc[j][3])
                             : "r"(al[0]),"r"(al[1]),"r"(al[2]),"r"(al[3]),"r"(bh0),"r"(bh1));
            }
        }
        __syncthreads();
    }

    {
        int g = lane >> 2, tt = lane & 3;
        int r0 = M0 + R0 + g;
        if (cmode == 3) {
            const float* bcL = d_bc + layer*128;
            const float* vaL = d_vang + (size_t)layer*BA*ND;
            #pragma unroll
            for (int j = 0; j < 8; j++) {
                int fa = (jbase + j)*8 + 2*tt;
                float2 bcv = *(const float2*)&bcL[fa];
                float2 va0 = *(const float2*)&vaL[(size_t)r0*128 + fa];
                float2 va1 = *(const float2*)&vaL[(size_t)(r0+8)*128 + fa];
                float2 x0 = *(float2*)&d_x[(size_t)r0*128 + fa];
                float2 x1 = *(float2*)&d_x[(size_t)(r0+8)*128 + fa];
                x0.x += ssp(acc[j][0] + bcv.x + va0.x);
                x0.y += ssp(acc[j][1] + bcv.y + va0.y);
                x1.x += ssp(acc[j][2] + bcv.x + va1.x);
                x1.y += ssp(acc[j][3] + bcv.y + va1.y);
                *(float2*)&d_x[(size_t)r0*128 + fa]     = x0;
                *(float2*)&d_x[(size_t)(r0+8)*128 + fa] = x1;
            }
        } else {
            float* Cp = (cmode == 1) ? (d_vang + (size_t)l*BA*ND) : d_y;
            #pragma unroll
            for (int j = 0; j < 8; j++) {
                int fa = (jbase + j)*8 + 2*tt;
                *(float2*)&Cp[(size_t)r0*128 + fa]     = make_float2(acc[j][0], acc[j][1]);
                *(float2*)&Cp[(size_t)(r0+8)*128 + fa] = make_float2(acc[j][2], acc[j][3]);
            }
        }
    }
}

// -------- filter-network + aggregation, tensorized (v6) --------
// Stage B: ldmatrix.x4 j-pairing; per-j immediate shfl reduce (no part[32]).
#define OFF_BHI 0
#define OFF_BLO 32768
#define OFF_FHI 65536
#define OFF_FLO 75776
#define OFF_W1HI 86016
#define OFF_W1LO 96256
#define OFF_B1  106496
#define OFF_B2  107008
#define OFF_CM  107520
#define OFF_NB  108032
#define OFF_RED OFF_FHI
#define FA_SMEM 108544

__global__ __launch_bounds__(256, 2)
void filter_agg_kernel(const float* __restrict__ b1g,
                       const float* __restrict__ b2g,
                       const int* __restrict__ nbg, int l)
{
    extern __shared__ char smc[];
    uint32_t sb = smem_u32(smc);
    float* b1s = (float*)(smc + OFF_B1);
    float* b2s = (float*)(smc + OFF_B2);
    float* cms = (float*)(smc + OFF_CM);
    int*   nbs = (int*)(smc + OFF_NB);
    float* red = (float*)(smc + OFF_RED);

    int t = threadIdx.x;
    int lane = t & 31;
    int w = t >> 5;
    int g = lane >> 2;
    int tt = lane & 3;
    int r7 = lane & 7;
    int hb = (lane >> 3) & 1;
    int jbit = (lane >> 4) & 1;
    int atom = w >> 2;
    int i0 = blockIdx.x * 2;
    int bofs = (i0 >> 9) << 9;

    // ---- stage 0: cooperative loads ----
    {
        const uint4* hsrc = (const uint4*)(d_w2hi + (size_t)l * 16384);
        const uint4* lsrc = (const uint4*)(d_w2lo + (size_t)l * 16384);
        #pragma unroll
        for (int p = 0; p < 8; p++) {
            int u = t + 256*p;
            int f = u >> 4, c = u & 15;
            int cs = c ^ (f & 7);
            *(uint4*)(smc + OFF_BHI + f*256 + cs*16) = hsrc[u];
            *(uint4*)(smc + OFF_BLO + f*256 + cs*16) = lsrc[u];
        }
        const uint4* fh = (const uint4*)(d_fhi + (size_t)i0 * 64 * 32);
        const uint4* fl = (const uint4*)(d_flo + (size_t)i0 * 64 * 32);
        #pragma unroll
        for (int p = 0; p < 2; p++) {
            int u = t + 256*p;
            int r = u >> 2, c = u & 3;
            *(uint4*)(smc + OFF_FHI + r*80 + c*16) = fh[u];
            *(uint4*)(smc + OFF_FLO + r*80 + c*16) = fl[u];
        }
        const uint4* wh = (const uint4*)(d_w1hi + (size_t)l * 128 * 32);
        const uint4* wl = (const uint4*)(d_w1lo + (size_t)l * 128 * 32);
        #pragma unroll
        for (int p = 0; p < 2; p++) {
            int u = t + 256*p;
            int r = u >> 2, c = u & 3;
            *(uint4*)(smc + OFF_W1HI + r*80 + c*16) = wh[u];
            *(uint4*)(smc + OFF_W1LO + r*80 + c*16) = wl[u];
        }
        if (t < 128) {
            b1s[t] = b1g[l*128 + t];
            b2s[t] = b2g[l*128 + t];
            cms[t] = d_cm[i0*64 + t];
            nbs[t] = nbg[i0*64 + t];
        }
    }
    __syncthreads();

    int row0p = atom*64 + (w & 3)*16 + g;
    int row1p = row0p + 8;

    // ---- stage A (interleaved): per k-step s compute 2 acc pairs, convert ----
    uint32_t ahi[32], alo[32];
    {
        int R0 = atom*64 + (w & 3)*16;
        uint32_t aAddr = sb + OFF_FHI + (uint32_t)(R0 + (lane & 15))*80 + (uint32_t)(lane & 16);
        uint32_t fh[2][4], fl[2][4];
        #pragma unroll
        for (int s2 = 0; s2 < 2; s2++) {
            asm volatile("ldmatrix.sync.aligned.m8n8.x4.shared.b16 {%0,%1,%2,%3}, [%4];"
                         : "=r"(fh[s2][0]),"=r"(fh[s2][1]),"=r"(fh[s2][2]),"=r"(fh[s2][3])
                         : "r"(aAddr + s2*32));
            asm volatile("ldmatrix.sync.aligned.m8n8.x4.shared.b16 {%0,%1,%2,%3}, [%4];"
                         : "=r"(fl[s2][0]),"=r"(fl[s2][1]),"=r"(fl[s2][2]),"=r"(fl[s2][3])
                         : "r"(aAddr + (OFF_FLO - OFF_FHI) + s2*32));
        }
        #pragma unroll
        for (int s = 0; s < 8; s++) {
            float aP[2][4];
            #pragma unroll
            for (int h = 0; h < 2; h++)
                #pragma unroll
                for (int q = 0; q < 4; q++) aP[h][q] = 0.f;
            // w1 row for this thread's x4: jn = 2s + jbit
            uint32_t wAddr = sb + OFF_W1HI
                           + (uint32_t)(((2*s + jbit)*8 + r7)*80) + (uint32_t)(hb << 4);
            #pragma unroll
            for (int s2 = 0; s2 < 2; s2++) {
                uint32_t wh[4], wl[4];
                asm volatile("ldmatrix.sync.aligned.m8n8.x4.shared.b16 {%0,%1,%2,%3}, [%4];"
                             : "=r"(wh[0]),"=r"(wh[1]),"=r"(wh[2]),"=r"(wh[3])
                             : "r"(wAddr + s2*32));
                asm volatile("ldmatrix.sync.aligned.m8n8.x4.shared.b16 {%0,%1,%2,%3}, [%4];"
                             : "=r"(wl[0]),"=r"(wl[1]),"=r"(wl[2]),"=r"(wl[3])
                             : "r"(wAddr + (OFF_W1LO - OFF_W1HI) + s2*32));
                asm volatile("mma.sync.aligned.m16n8k16.row.col.f32.bf16.bf16.f32 "
                             "{%0,%1,%2,%3}, {%4,%5,%6,%7}, {%8,%9}, {%0,%1,%2,%3};"
                             : "+f"(aP[0][0]),"+f"(aP[0][1]),"+f"(aP[0][2]),"+f"(aP[0][3])
                             : "r"(fh[s2][0]),"r"(fh[s2][1]),"r"(fh[s2][2]),"r"(fh[s2][3]),
                               "r"(wh[0]),"r"(wh[1]));
                asm volatile("mma.sync.aligned.m16n8k16.row.col.f32.bf16.bf16.f32 "
                             "{%0,%1,%2,%3}, {%4,%5,%6,%7}, {%8,%9}, {%0,%1,%2,%3};"
                             : "+f"(aP[0][0]),"+f"(aP[0][1]),"+f"(aP[0][2]),"+f"(aP[0][3])
                             : "r"(fh[s2][0]),"r"(fh[s2][1]),"r"(fh[s2][2]),"r"(fh[s2][3]),
                               "r"(wl[0]),"r"(wl[1]));
                asm volatile("mma.sync.aligned.m16n8k16.row.col.f32.bf16.bf16.f32 "
                             "{%0,%1,%2,%3}, {%4,%5,%6,%7}, {%8,%9}, {%0,%1,%2,%3};"
                             : "+f"(aP[0][0]),"+f"(aP[0][1]),"+f"(aP[0][2]),"+f"(aP[0][3])
                             : "r"(fl[s2][0]),"r"(fl[s2][1]),"r"(fl[s2][2]),"r"(fl[s2][3]),
                               "r"(wh[0]),"r"(wh[1]));
                asm volatile("mma.sync.aligned.m16n8k16.row.col.f32.bf16.bf16.f32 "
                             "{%0,%1,%2,%3}, {%4,%5,%6,%7}, {%8,%9}, {%0,%1,%2,%3};"
                             : "+f"(aP[1][0]),"+f"(aP[1][1]),"+f"(aP[1][2]),"+f"(aP[1][3])
                             : "r"(fh[s2][0]),"r"(fh[s2][1]),"r"(fh[s2][2]),"r"(fh[s2][3]),
                               "r"(wh[2]),"r"(wh[3]));
                asm volatile("mma.sync.aligned.m16n8k16.row.col.f32.bf16.bf16.f32 "
                             "{%0,%1,%2,%3}, {%4,%5,%6,%7}, {%8,%9}, {%0,%1,%2,%3};"
                             : "+f"(aP[1][0]),"+f"(aP[1][1]),"+f"(aP[1][2]),"+f"(aP[1][3])
                             : "r"(fh[s2][0]),"r"(fh[s2][1]),"r"(fh[s2][2]),"r"(fh[s2][3]),
                               "r"(wl[2]),"r"(wl[3]));
                asm volatile("mma.sync.aligned.m16n8k16.row.col.f32.bf16.bf16.f32 "
                             "{%0,%1,%2,%3}, {%4,%5,%6,%7}, {%8,%9}, {%0,%1,%2,%3};"
                             : "+f"(aP[1][0]),"+f"(aP[1][1]),"+f"(aP[1][2]),"+f"(aP[1][3])
                             : "r"(fl[s2][0]),"r"(fl[s2][1]),"r"(fl[s2][2]),"r"(fl[s2][3]),
                               "r"(wh[2]),"r"(wh[3]));
            }
            // convert: H = ssp(acc + b1), bf16 split
            int klo = 16*s + 2*tt;
            float2 blo = *(const float2*)&b1s[klo];
            float2 bhi = *(const float2*)&b1s[klo + 8];
            split2(ssp(aP[0][0] + blo.x), ssp(aP[0][1] + blo.y), ahi[s*4+0], alo[s*4+0]);
            split2(ssp(aP[0][2] + blo.x), ssp(aP[0][3] + blo.y), ahi[s*4+1], alo[s*4+1]);
            split2(ssp(aP[1][0] + bhi.x), ssp(aP[1][1] + bhi.y), ahi[s*4+2], alo[s*4+2]);
            split2(ssp(aP[1][2] + bhi.x), ssp(aP[1][3] + bhi.y), ahi[s*4+3], alo[s*4+3]);
        }
    }
    __syncthreads();   // f/w1 tiles dead; red overlays

    // ---- stage B: x4 j-paired mma + per-j immediate reduce ----
    float cm0 = cms[row0p], cm1 = cms[row1p];
    const float* yp0 = d_y + (size_t)(bofs + nbs[row0p]) * 128;
    const float* yp1 = d_y + (size_t)(bofs + nbs[row1p]) * 128;

    #pragma unroll
    for (int jq = 0; jq < 8; jq++) {
        float c0[4], c1[4];
        #pragma unroll
        for (int q = 0; q < 4; q++) { c0[q] = 0.f; c1[q] = 0.f; }
        uint32_t baseAddr = sb + OFF_BHI + (uint32_t)(((jq*2 + jbit)*8 + r7) * 256);
        #pragma unroll
        for (int s = 0; s < 8; s++) {
            uint32_t ba = baseAddr + (uint32_t)((((2*s + hb) ^ r7)) * 16);
            uint32_t bh[4], bl[4];
            asm volatile("ldmatrix.sync.aligned.m8n8.x4.shared.b16 {%0,%1,%2,%3}, [%4];"
                         : "=r"(bh[0]),"=r"(bh[1]),"=r"(bh[2]),"=r"(bh[3]) : "r"(ba));
            asm volatile("ldmatrix.sync.aligned.m8n8.x4.shared.b16 {%0,%1,%2,%3}, [%4];"
                         : "=r"(bl[0]),"=r"(bl[1]),"=r"(bl[2]),"=r"(bl[3])
                         : "r"(ba + (OFF_BLO - OFF_BHI)));
            asm volatile("mma.sync.aligned.m16n8k16.row.col.f32.bf16.bf16.f32 "
                         "{%0,%1,%2,%3}, {%4,%5,%6,%7}, {%8,%9}, {%0,%1,%2,%3};"
                         : "+f"(c0[0]),"+f"(c0[1]),"+f"(c0[2]),"+f"(c0[3])
                         : "r"(ahi[s*4+0]),"r"(ahi[s*4+1]),"r"(ahi[s*4+2]),"r"(ahi[s*4+3]),
                           "r"(bh[0]),"r"(bh[1]));
            asm volatile("mma.sync.aligned.m16n8k16.row.col.f32.bf16.bf16.f32 "
                         "{%0,%1,%2,%3}, {%4,%5,%6,%7}, {%8,%9}, {%0,%1,%2,%3};"
                         : "+f"(c0[0]),"+f"(c0[1]),"+f"(c0[2]),"+f"(c0[3])
                         : "r"(ahi[s*4+0]),"r"(ahi[s*4+1]),"r"(ahi[s*4+2]),"r"(ahi[s*4+3]),
                           "r"(bl[0]),"r"(bl[1]));
            asm volatile("mma.sync.aligned.m16n8k16.row.col.f32.bf16.bf16.f32 "
                         "{%0,%1,%2,%3}, {%4,%5,%6,%7}, {%8,%9}, {%0,%1,%2,%3};"
                         : "+f"(c0[0]),"+f"(c0[1]),"+f"(c0[2]),"+f"(c0[3])
                         : "r"(alo[s*4+0]),"r"(alo[s*4+1]),"r"(alo[s*4+2]),"r"(alo[s*4+3]),
                           "r"(bh[0]),"r"(bh[1]));
            asm volatile("mma.sync.aligned.m16n8k16.row.col.f32.bf16.bf16.f32 "
                         "{%0,%1,%2,%3}, {%4,%5,%6,%7}, {%8,%9}, {%0,%1,%2,%3};"
                         : "+f"(c1[0]),"+f"(c1[1]),"+f"(c1[2]),"+f"(c1[3])
                         : "r"(ahi[s*4+0]),"r"(ahi[s*4+1]),"r"(ahi[s*4+2]),"r"(ahi[s*4+3]),
                           "r"(bh[2]),"r"(bh[3]));
            asm volatile("mma.sync.aligned.m16n8k16.row.col.f32.bf16.bf16.f32 "
                         "{%0,%1,%2,%3}, {%4,%5,%6,%7}, {%8,%9}, {%0,%1,%2,%3};"
                         : "+f"(c1[0]),"+f"(c1[1]),"+f"(c1[2]),"+f"(c1[3])
                         : "r"(ahi[s*4+0]),"r"(ahi[s*4+1]),"r"(ahi[s*4+2]),"r"(ahi[s*4+3]),
                           "r"(bl[2]),"r"(bl[3]));
            asm volatile("mma.sync.aligned.m16n8k16.row.col.f32.bf16.bf16.f32 "
                         "{%0,%1,%2,%3}, {%4,%5,%6,%7}, {%8,%9}, {%0,%1,%2,%3};"
                         : "+f"(c1[0]),"+f"(c1[1]),"+f"(c1[2]),"+f"(c1[3])
                         : "r"(alo[s*4+0]),"r"(alo[s*4+1]),"r"(alo[s*4+2]),"r"(alo[s*4+3]),
                           "r"(bh[2]),"r"(bh[3]));
        }
        #pragma unroll
        for (int h = 0; h < 2; h++) {
            int j = 2*jq + h;
            float q0 = h ? c1[0] : c0[0], q1 = h ? c1[1] : c0[1];
            float q2 = h ? c1[2] : c0[2], q3 = h ? c1[3] : c0[3];
            int fa = 8*j + 2*tt;
            float2 b2v = *(const float2*)&b2s[fa];
            float2 ya  = *(const float2*)(yp0 + fa);
            float2 yb  = *(const float2*)(yp1 + fa);
            float p0 = cm0*ya.x*(q0 + b2v.x) + cm1*yb.x*(q2 + b2v.x);
            float p1 = cm0*ya.y*(q1 + b2v.y) + cm1*yb.y*(q3 + b2v.y);
            p0 += __shfl_xor_sync(0xffffffffu, p0, 4);
            p0 += __shfl_xor_sync(0xffffffffu, p0, 8);
            p0 += __shfl_xor_sync(0xffffffffu, p0, 16);
            p1 += __shfl_xor_sync(0xffffffffu, p1, 4);
            p1 += __shfl_xor_sync(0xffffffffu, p1, 8);
            p1 += __shfl_xor_sync(0xffffffffu, p1, 16);
            if (lane < 4)
                *(float2*)&red[w*128 + fa] = make_float2(p0, p1);
        }
    }

    __syncthreads();
    {
        int a = t >> 7, f = t & 127;
        const float* rb = red + (a*4)*128 + f;
        d_agg[(size_t)(i0 + a)*128 + f] = rb[0] + rb[128] + rb[256] + rb[384];
    }
}

__global__ void copy_out_kernel(float* __restrict__ out) {
    int idx = blockIdx.x * 256 + threadIdx.x;
    out[idx] = d_x[idx];
}

extern "C" void kernel_launch(void* const* d_in, const int* in_sizes, int n_in,
                              void* d_out, int out_size) {
    const int*   z      = (const int*)  d_in[0];
    const float* pos    = (const float*)d_in[1];
    const int*   nb     = (const int*)  d_in[2];
    const int*   nmask  = (const int*)  d_in[3];
    const float* Gi     = (const float*)d_in[4];
    const float* emb    = (const float*)d_in[5];
    const float* fw1    = (const float*)d_in[6];
    const float* fb1    = (const float*)d_in[7];
    const float* fw2    = (const float*)d_in[8];
    const float* fb2    = (const float*)d_in[9];
    const float* in2f   = (const float*)d_in[10];
    const float* f2o    = (const float*)d_in[11];
    const float* f2ob   = (const float*)d_in[12];
    const float* dw     = (const float*)d_in[13];
    const float* db     = (const float*)d_in[14];
    const float* angw   = (const float*)d_in[15];
    float* out = (float*)d_out;

    static __nv_bfloat16 *p_i2fhi, *p_i2flo, *p_anghi, *p_anglo, *p_wchi, *p_wclo;
    static float *p_wc;
    cudaGetSymbolAddress((void**)&p_i2fhi, d_i2fhi);
    cudaGetSymbolAddress((void**)&p_i2flo, d_i2flo);
    cudaGetSymbolAddress((void**)&p_anghi, d_anghi);
    cudaGetSymbolAddress((void**)&p_anglo, d_anglo);
    cudaGetSymbolAddress((void**)&p_wchi, d_wchi);
    cudaGetSymbolAddress((void**)&p_wclo, d_wclo);
    cudaGetSymbolAddress((void**)&p_wc, d_wc);

    cudaFuncSetAttribute(filter_agg_kernel,
                         cudaFuncAttributeMaxDynamicSharedMemorySize, FA_SMEM);
    cudaFuncSetAttribute(tgemm_kernel,
                         cudaFuncAttributeMaxDynamicSharedMemorySize, TG_SMEM);

    // prep (layer-invariant)
    embed_kernel<<<BA, 128>>>(z, emb);
    dist_kernel<<<BA, NN>>>(pos, nb, nmask);
    allsplit_kernel<<<1200, 256>>>(fw1, fw2, in2f, angw);
    wc_kernel<<<dim3(8, NL), 128>>>(f2o, dw);
    bc_kernel<<<NL, 128>>>(f2ob, dw, db);
    bsplit_kernel<<<NL*ND*ND/256, 256>>>(p_wc, p_wchi, p_wclo, ND);

    // angular projections (all layers)
    tgemm_kernel<<<dim3(BA/64, NL), 256, TG_SMEM>>>(Gi, p_anghi, p_anglo, NGA, 0, 1, 0);

    for (int l = 0; l < NL; l++) {
        tgemm_kernel<<<dim3(BA/64, 1), 256, TG_SMEM>>>(nullptr,
            p_i2fhi + (size_t)l*NF*ND, p_i2flo + (size_t)l*NF*ND, ND, 1, 0, l);
        filter_agg_kernel<<<BA/2, 256, FA_SMEM>>>(fb1, fb2, nb, l);
        tgemm_kernel<<<dim3(BA/64, 1), 256, TG_SMEM>>>(nullptr,
            p_wchi + (size_t)l*ND*ND, p_wclo + (size_t)l*ND*ND, ND, 2, 3, l);
    }

    copy_out_kernel<<<BA*ND/256, 256>>>(out);
}

// round 15
// speedup vs baseline: 1.6284x; 1.0400x over previous
#include <cuda_runtime.h>
#include <cuda_bf16.h>
#include <math.h>
#include <stdint.h>

#define NB 8
#define NA 512
#define NN 64
#define ND 128
#define NF 128
#define NG 25
#define NL 3
#define NGA 512
#define BA (NB*NA)          // 4096
#define CUTOFF 5.0f
#define RSTART 1.2f
#define LN2F 0.6931471805599453f

// -------- device scratch --------
__device__ float d_x[BA*ND];
__device__ float d_y[BA*NF];
__device__ float d_agg[BA*NF];
__device__ float d_vang[NL*BA*ND];
__device__ float d_cm[BA*NN];
__device__ __nv_bfloat16 d_fhi[BA*NN*32];
__device__ __nv_bfloat16 d_flo[BA*NN*32];
__device__ __nv_bfloat16 d_w1hi[NL*NF*32];
__device__ __nv_bfloat16 d_w1lo[NL*NF*32];
__device__ __nv_bfloat16 d_w2hi[NL*NF*NF];
__device__ __nv_bfloat16 d_w2lo[NL*NF*NF];
__device__ __nv_bfloat16 d_i2fhi[NL*NF*ND];
__device__ __nv_bfloat16 d_i2flo[NL*NF*ND];
__device__ __nv_bfloat16 d_anghi[NL*ND*NGA];
__device__ __nv_bfloat16 d_anglo[NL*ND*NGA];
__device__ __nv_bfloat16 d_wchi[NL*ND*ND];
__device__ __nv_bfloat16 d_wclo[NL*ND*ND];
__device__ float d_bc[NL*ND];

__device__ __forceinline__ float ssp(float v) {
    return fmaxf(v, 0.f) + __logf(1.f + __expf(-fabsf(v))) - LN2F;
}

__device__ __forceinline__ uint32_t smem_u32(const void* p) {
    uint32_t a;
    asm("{ .reg .u64 t; cvta.to.shared.u64 t, %1; cvt.u32.u64 %0, t; }" : "=r"(a) : "l"(p));
    return a;
}

__device__ __forceinline__ void split2(float a, float b, uint32_t& hi, uint32_t& lo) {
    __nv_bfloat16 ah = __float2bfloat16(a), bh = __float2bfloat16(b);
    float ar = a - __bfloat162float(ah);
    float br = b - __bfloat162float(bh);
    __nv_bfloat162 hp; hp.x = ah; hp.y = bh;
    __nv_bfloat162 lp = __floats2bfloat162_rn(ar, br);
    hi = *(uint32_t*)&hp;
    lo = *(uint32_t*)&lp;
}

// -------- embedding gather --------
__global__ void embed_kernel(const int* __restrict__ z, const float* __restrict__ emb) {
    int i = blockIdx.x, t = threadIdx.x;
    d_x[i*ND + t] = emb[z[i]*ND + t];
}

// -------- distances + gaussian smearing (bf16-split) + cutoff*mask --------
__global__ void dist_kernel(const float* __restrict__ pos,
                            const int* __restrict__ nb,
                            const int* __restrict__ nmask) {
    int i = blockIdx.x;
    int n = threadIdx.x;
    int bofs = (i >> 9) << 9;
    float px = pos[i*3+0], py = pos[i*3+1], pz = pos[i*3+2];
    int j = nb[i*NN + n];
    int gj = bofs + j;
    float dx = pos[gj*3+0] - px;
    float dy = pos[gj*3+1] - py;
    float dz = pos[gj*3+2] - pz;
    float r = sqrtf(dx*dx + dy*dy + dz*dz + 1e-12f);
    float m = (float)nmask[i*NN + n];
    d_cm[i*NN + n] = (r <= CUTOFF) ? m : 0.f;
    const float width = (CUTOFF - RSTART) / (float)(NG - 1);
    const float coeff = -0.5f / (width * width);
    __nv_bfloat16* oh = d_fhi + (size_t)(i*NN + n) * 32;
    __nv_bfloat16* ol = d_flo + (size_t)(i*NN + n) * 32;
    #pragma unroll
    for (int g = 0; g < 32; g++) {
        float v = 0.f;
        if (g < NG) {
            float d = r - (RSTART + width * (float)g);
            v = __expf(coeff * d * d);
        }
        __nv_bfloat16 hi = __float2bfloat16(v);
        oh[g] = hi;
        ol[g] = __float2bfloat16(v - __bfloat162float(hi));
    }
}

// -------- prestage: all weight transpose+splits in ONE launch --------
__global__ void allsplit_kernel(const float* __restrict__ w1,
                                const float* __restrict__ w2,
                                const float* __restrict__ i2f,
                                const float* __restrict__ ang) {
    int idx = blockIdx.x * 256 + threadIdx.x;
    float v;
    __nv_bfloat16 *ph, *pl;
    int o;
    if (idx < 12288) {
        int l = idx >> 12, r = idx & 4095;
        int f = r >> 5, k = r & 31;
        v = (k < NG) ? w1[l*3200 + k*128 + f] : 0.f;
        ph = d_w1hi; pl = d_w1lo; o = idx;
    } else if (idx < 61440) {
        int u = idx - 12288;
        int l = u >> 14, r = u & 16383;
        int k = r >> 7, f = r & 127;
        v = w2[u];
        ph = d_w2hi; pl = d_w2lo; o = l*16384 + f*128 + k;
    } else if (idx < 110592) {
        int u = idx - 61440;
        int l = u >> 14, r = u & 16383;
        int k = r >> 7, f = r & 127;
        v = i2f[u];
        ph = d_i2fhi; pl = d_i2flo; o = l*16384 + f*128 + k;
    } else {
        int u = idx - 110592;
        int l = u >> 16, r = u & 65535;
        int k = r >> 7, f = r & 127;
        v = ang[u];
        ph = d_anghi; pl = d_anglo; o = l*65536 + f*512 + k;
    }
    __nv_bfloat16 hi = __float2bfloat16(v);
    ph[o] = hi;
    pl[o] = __float2bfloat16(v - __bfloat162float(hi));
}

// -------- prestage: Wc = f2w@dense, fused transpose + bf16 split --------
// grid (32, NL), 128 threads; block = 4 rows of Wc.
__global__ __launch_bounds__(128)
void wcsplit_kernel(const float* __restrict__ f2w, const float* __restrict__ dwm) {
    __shared__ float Ash[4][128];
    int l = blockIdx.y;
    int row0 = blockIdx.x * 4;
    int t = threadIdx.x;
    #pragma unroll
    for (int p = 0; p < 4; p++) {
        int idx = t + 128*p;
        Ash[idx >> 7][idx & 127] = f2w[(size_t)l*16384 + (row0 + (idx >> 7))*128 + (idx & 127)];
    }
    __syncthreads();
    const float* Bm = dwm + (size_t)l*16384;
    float acc[4] = {0.f, 0.f, 0.f, 0.f};
    #pragma unroll 4
    for (int k = 0; k < 128; k++) {
        float bv = Bm[k*128 + t];
        #pragma unroll
        for (int r = 0; r < 4; r++) acc[r] += Ash[r][k] * bv;
    }
    #pragma unroll
    for (int r = 0; r < 4; r++) {
        float v = acc[r];
        __nv_bfloat16 hi = __float2bfloat16(v);
        int o = l*16384 + t*128 + row0 + r;   // transposed [f=t][k=row]
        d_wchi[o] = hi;
        d_wclo[o] = __float2bfloat16(v - __bfloat162float(hi));
    }
}

__global__ void bc_kernel(const float* __restrict__ f2b, const float* __restrict__ dwm,
                          const float* __restrict__ db) {
    int l = blockIdx.x, t = threadIdx.x;
    float acc = db[l*128 + t];
    #pragma unroll 4
    for (int k = 0; k < 128; k++)
        acc += f2b[l*128 + k] * dwm[(size_t)l*16384 + k*128 + t];
    d_bc[l*128 + t] = acc;
}

// -------- tensor GEMM: C[M,128] = A[M,K] @ B[K,128], bf16 hi/lo split --------
// M-tile 32 (grid M/32), 256 threads: warp = (w>>2) 16-row block x (w&3) f-quarter.
// cmode 0: C=d_y   1: C=d_vang[blockIdx.y]
// cmode 3: x += ssp(acc+bc+vang)   4: same but result -> outp (final layer)
#define TG_AHI 0
#define TG_ALO 4608
#define TG_BHI 9216
#define TG_BLO 27648
#define TG_SMEM 46080
#define TG_STRIDE 144

__global__ __launch_bounds__(256, 2)
void tgemm_kernel(const float* __restrict__ Aext,
                  const __nv_bfloat16* __restrict__ BtHi,
                  const __nv_bfloat16* __restrict__ BtLo,
                  int K, int amode, int cmode, int layer, float* __restrict__ outp) {
    extern __shared__ char smc[];
    uint32_t sb = smem_u32(smc);
    int t = threadIdx.x;
    int lane = t & 31;
    int w = t >> 5;
    int l = blockIdx.y;
    int M0 = blockIdx.x * 32;
    const float* Ap = (amode == 1) ? d_x : ((amode == 2) ? d_agg : Aext);
    const __nv_bfloat16* bhiL = BtHi + (size_t)l*128*K;
    const __nv_bfloat16* bloL = BtLo + (size_t)l*128*K;

    int R0 = (w >> 2) * 16;
    int jbase = (w & 3) * 4;

    float acc[4][4];
    #pragma unroll
    for (int j = 0; j < 4; j++)
        #pragma unroll
        for (int q = 0; q < 4; q++) acc[j][q] = 0.f;

    uint32_t aAddr = sb + TG_AHI + (uint32_t)(R0 + (lane & 15))*TG_STRIDE + (uint32_t)(lane & 16);
    uint32_t bAddr = sb + TG_BHI + (uint32_t)(lane & 7)*TG_STRIDE + (uint32_t)((lane & 8) << 1);

    for (int kc = 0; kc < K; kc += 64) {
        // A chunk [32][64] fp32 -> split
        #pragma unroll
        for (int p = 0; p < 4; p++) {
            int u = t + 256*p;               // 1024 float2 slots
            int r = u >> 5, kp = u & 31;
            float2 v = *(const float2*)&Ap[(size_t)(M0 + r)*K + kc + kp*2];
            uint32_t hi, lo;
            split2(v.x, v.y, hi, lo);
            *(uint32_t*)(smc + TG_AHI + r*TG_STRIDE + kp*4) = hi;
            *(uint32_t*)(smc + TG_ALO + r*TG_STRIDE + kp*4) = lo;
        }
        // B chunk [128][64]
        #pragma unroll
        for (int p = 0; p < 4; p++) {
            int u = t + 256*p;               // 1024 uint4 slots
            int f = u >> 3, c = u & 7;
            *(uint4*)(smc + TG_BHI + f*TG_STRIDE + c*16) =
                ((const uint4*)(bhiL + f*K + kc))[c];
            *(uint4*)(smc + TG_BLO + f*TG_STRIDE + c*16) =
                ((const uint4*)(bloL + f*K + kc))[c];
        }
        __syncthreads();

        #pragma unroll
        for (int s = 0; s < 4; s++) {
            uint32_t ah[4], al[4];
            asm volatile("ldmatrix.sync.aligned.m8n8.x4.shared.b16 {%0,%1,%2,%3}, [%4];"
                         : "=r"(ah[0]),"=r"(ah[1]),"=r"(ah[2]),"=r"(ah[3])
                         : "r"(aAddr + s*32));
            asm volatile("ldmatrix.sync.aligned.m8n8.x4.shared.b16 {%0,%1,%2,%3}, [%4];"
                         : "=r"(al[0]),"=r"(al[1]),"=r"(al[2]),"=r"(al[3])
                         : "r"(aAddr + (TG_ALO - TG_AHI) + s*32));
            #pragma unroll
            for (int j = 0; j < 4; j++) {
                uint32_t ba = bAddr + (uint32_t)((jbase + j)*(8*TG_STRIDE) + s*32);
                uint32_t bh0, bh1, bl0, bl1;
                asm volatile("ldmatrix.sync.aligned.m8n8.x2.shared.b16 {%0,%1}, [%2];"
                             : "=r"(bh0), "=r"(bh1) : "r"(ba));
                asm volatile("ldmatrix.sync.aligned.m8n8.x2.shared.b16 {%0,%1}, [%2];"
                             : "=r"(bl0), "=r"(bl1) : "r"(ba + (TG_BLO - TG_BHI)));
                asm volatile("mma.sync.aligned.m16n8k16.row.col.f32.bf16.bf16.f32 "
                             "{%0,%1,%2,%3}, {%4,%5,%6,%7}, {%8,%9}, {%0,%1,%2,%3};"
                             : "+f"(acc[j][0]),"+f"(acc[j][1]),"+f"(acc[j][2]),"+f"(acc[j][3])
                             : "r"(ah[0]),"r"(ah[1]),"r"(ah[2]),"r"(ah[3]),"r"(bh0),"r"(bh1));
                asm volatile("mma.sync.aligned.m16n8k16.row.col.f32.bf16.bf16.f32 "
                             "{%0,%1,%2,%3}, {%4,%5,%6,%7}, {%8,%9}, {%0,%1,%2,%3};"
                             : "+f"(acc[j][0]),"+f"(acc[j][1]),"+f"(acc[j][2]),"+f"(acc[j][3])
                             : "r"(ah[0]),"r"(ah[1]),"r"(ah[2]),"r"(ah[3]),"r"(bl0),"r"(bl1));
                asm volatile("mma.sync.aligned.m16n8k16.row.col.f32.bf16.bf16.f32 "
                             "{%0,%1,%2,%3}, {%4,%5,%6,%7}, {%8,%9}, {%0,%1,%2,%3};"
                             : "+f"(acc[j][0]),"+f"(acc[j][1]),"+f"(acc[j][2]),"+f"(acc[j][3])
                             : "r"(al[0]),"r"(al[1]),"r"(al[2]),"r"(al[3]),"r"(bh0),"r"(bh1));
            }
        }
        __syncthreads();
    }

    {
        int g = lane >> 2, tt = lane & 3;
        int r0 = M0 + R0 + g;
        if (cmode >= 3) {
            const float* bcL = d_bc + layer*128;
            const float* vaL = d_vang + (size_t)layer*BA*ND;
            #pragma unroll
            for (int j = 0; j < 4; j++) {
                int fa = (jbase + j)*8 + 2*tt;
                float2 bcv = *(const float2*)&bcL[fa];
                float2 va0 = *(const float2*)&vaL[(size_t)r0*128 + fa];
                float2 va1 = *(const float2*)&vaL[(size_t)(r0+8)*128 + fa];
                float2 x0 = *(float2*)&d_x[(size_t)r0*128 + fa];
                float2 x1 = *(float2*)&d_x[(size_t)(r0+8)*128 + fa];
                x0.x += ssp(acc[j][0] + bcv.x + va0.x);
                x0.y += ssp(acc[j][1] + bcv.y + va0.y);
                x1.x += ssp(acc[j][2] + bcv.x + va1.x);
                x1.y += ssp(acc[j][3] + bcv.y + va1.y);
                if (cmode == 4) {
                    *(float2*)&outp[(size_t)r0*128 + fa]     = x0;
                    *(float2*)&outp[(size_t)(r0+8)*128 + fa] = x1;
                } else {
                    *(float2*)&d_x[(size_t)r0*128 + fa]     = x0;
                    *(float2*)&d_x[(size_t)(r0+8)*128 + fa] = x1;
                }
            }
        } else {
            float* Cp = (cmode == 1) ? (d_vang + (size_t)l*BA*ND) : d_y;
            #pragma unroll
            for (int j = 0; j < 4; j++) {
                int fa = (jbase + j)*8 + 2*tt;
                *(float2*)&Cp[(size_t)r0*128 + fa]     = make_float2(acc[j][0], acc[j][1]);
                *(float2*)&Cp[(size_t)(r0+8)*128 + fa] = make_float2(acc[j][2], acc[j][3]);
            }
        }
    }
}

// -------- filter-network + aggregation, tensorized (v6, unchanged) --------
#define OFF_BHI 0
#define OFF_BLO 32768
#define OFF_FHI 65536
#define OFF_FLO 75776
#define OFF_W1HI 86016
#define OFF_W1LO 96256
#define OFF_B1  106496
#define OFF_B2  107008
#define OFF_CM  107520
#define OFF_NB  108032
#define OFF_RED OFF_FHI
#define FA_SMEM 108544

__global__ __launch_bounds__(256, 2)
void filter_agg_kernel(const float* __restrict__ b1g,
                       const float* __restrict__ b2g,
                       const int* __restrict__ nbg, int l)
{
    extern __shared__ char smc[];
    uint32_t sb = smem_u32(smc);
    float* b1s = (float*)(smc + OFF_B1);
    float* b2s = (float*)(smc + OFF_B2);
    float* cms = (float*)(smc + OFF_CM);
    int*   nbs = (int*)(smc + OFF_NB);
    float* red = (float*)(smc + OFF_RED);

    int t = threadIdx.x;
    int lane = t & 31;
    int w = t >> 5;
    int g = lane >> 2;
    int tt = lane & 3;
    int r7 = lane & 7;
    int hb = (lane >> 3) & 1;
    int jbit = (lane >> 4) & 1;
    int atom = w >> 2;
    int i0 = blockIdx.x * 2;
    int bofs = (i0 >> 9) << 9;

    {
        const uint4* hsrc = (const uint4*)(d_w2hi + (size_t)l * 16384);
        const uint4* lsrc = (const uint4*)(d_w2lo + (size_t)l * 16384);
        #pragma unroll
        for (int p = 0; p < 8; p++) {
            int u = t + 256*p;
            int f = u >> 4, c = u & 15;
            int cs = c ^ (f & 7);
            *(uint4*)(smc + OFF_BHI + f*256 + cs*16) = hsrc[u];
            *(uint4*)(smc + OFF_BLO + f*256 + cs*16) = lsrc[u];
        }
        const uint4* fh = (const uint4*)(d_fhi + (size_t)i0 * 64 * 32);
        const uint4* fl = (const uint4*)(d_flo + (size_t)i0 * 64 * 32);
        #pragma unroll
        for (int p = 0; p < 2; p++) {
            int u = t + 256*p;
            int r = u >> 2, c = u & 3;
            *(uint4*)(smc + OFF_FHI + r*80 + c*16) = fh[u];
            *(uint4*)(smc + OFF_FLO + r*80 + c*16) = fl[u];
        }
        const uint4* wh = (const uint4*)(d_w1hi + (size_t)l * 128 * 32);
        const uint4* wl = (const uint4*)(d_w1lo + (size_t)l * 128 * 32);
        #pragma unroll
        for (int p = 0; p < 2; p++) {
            int u = t + 256*p;
            int r = u >> 2, c = u & 3;
            *(uint4*)(smc + OFF_W1HI + r*80 + c*16) = wh[u];
            *(uint4*)(smc + OFF_W1LO + r*80 + c*16) = wl[u];
        }
        if (t < 128) {
            b1s[t] = b1g[l*128 + t];
            b2s[t] = b2g[l*128 + t];
            cms[t] = d_cm[i0*64 + t];
            nbs[t] = nbg[i0*64 + t];
        }
    }
    __syncthreads();

    int row0p = atom*64 + (w & 3)*16 + g;
    int row1p = row0p + 8;

    uint32_t ahi[32], alo[32];
    {
        int R0 = atom*64 + (w & 3)*16;
        uint32_t aAddr = sb + OFF_FHI + (uint32_t)(R0 + (lane & 15))*80 + (uint32_t)(lane & 16);
        uint32_t fh[2][4], fl[2][4];
        #pragma unroll
        for (int s2 = 0; s2 < 2; s2++) {
            asm volatile("ldmatrix.sync.aligned.m8n8.x4.shared.b16 {%0,%1,%2,%3}, [%4];"
                         : "=r"(fh[s2][0]),"=r"(fh[s2][1]),"=r"(fh[s2][2]),"=r"(fh[s2][3])
                         : "r"(aAddr + s2*32));
            asm volatile("ldmatrix.sync.aligned.m8n8.x4.shared.b16 {%0,%1,%2,%3}, [%4];"
                         : "=r"(fl[s2][0]),"=r"(fl[s2][1]),"=r"(fl[s2][2]),"=r"(fl[s2][3])
                         : "r"(aAddr + (OFF_FLO - OFF_FHI) + s2*32));
        }
        #pragma unroll
        for (int s = 0; s < 8; s++) {
            float aP[2][4];
            #pragma unroll
            for (int h = 0; h < 2; h++)
                #pragma unroll
                for (int q = 0; q < 4; q++) aP[h][q] = 0.f;
            uint32_t wAddr = sb + OFF_W1HI
                           + (uint32_t)(((2*s + jbit)*8 + r7)*80) + (uint32_t)(hb << 4);
            #pragma unroll
            for (int s2 = 0; s2 < 2; s2++) {
                uint32_t wh[4], wl[4];
                asm volatile("ldmatrix.sync.aligned.m8n8.x4.shared.b16 {%0,%1,%2,%3}, [%4];"
                             : "=r"(wh[0]),"=r"(wh[1]),"=r"(wh[2]),"=r"(wh[3])
                             : "r"(wAddr + s2*32));
                asm volatile("ldmatrix.sync.aligned.m8n8.x4.shared.b16 {%0,%1,%2,%3}, [%4];"
                             : "=r"(wl[0]),"=r"(wl[1]),"=r"(wl[2]),"=r"(wl[3])
                             : "r"(wAddr + (OFF_W1LO - OFF_W1HI) + s2*32));
                asm volatile("mma.sync.aligned.m16n8k16.row.col.f32.bf16.bf16.f32 "
                             "{%0,%1,%2,%3}, {%4,%5,%6,%7}, {%8,%9}, {%0,%1,%2,%3};"
                             : "+f"(aP[0][0]),"+f"(aP[0][1]),"+f"(aP[0][2]),"+f"(aP[0][3])
                             : "r"(fh[s2][0]),"r"(fh[s2][1]),"r"(fh[s2][2]),"r"(fh[s2][3]),
                               "r"(wh[0]),"r"(wh[1]));
                asm volatile("mma.sync.aligned.m16n8k16.row.col.f32.bf16.bf16.f32 "
                             "{%0,%1,%2,%3}, {%4,%5,%6,%7}, {%8,%9}, {%0,%1,%2,%3};"
                             : "+f"(aP[0][0]),"+f"(aP[0][1]),"+f"(aP[0][2]),"+f"(aP[0][3])
                             : "r"(fh[s2][0]),"r"(fh[s2][1]),"r"(fh[s2][2]),"r"(fh[s2][3]),
                               "r"(wl[0]),"r"(wl[1]));
                asm volatile("mma.sync.aligned.m16n8k16.row.col.f32.bf16.bf16.f32 "
                             "{%0,%1,%2,%3}, {%4,%5,%6,%7}, {%8,%9}, {%0,%1,%2,%3};"
                             : "+f"(aP[0][0]),"+f"(aP[0][1]),"+f"(aP[0][2]),"+f"(aP[0][3])
                             : "r"(fl[s2][0]),"r"(fl[s2][1]),"r"(fl[s2][2]),"r"(fl[s2][3]),
                               "r"(wh[0]),"r"(wh[1]));
                asm volatile("mma.sync.aligned.m16n8k16.row.col.f32.bf16.bf16.f32 "
                             "{%0,%1,%2,%3}, {%4,%5,%6,%7}, {%8,%9}, {%0,%1,%2,%3};"
                             : "+f"(aP[1][0]),"+f"(aP[1][1]),"+f"(aP[1][2]),"+f"(aP[1][3])
                             : "r"(fh[s2][0]),"r"(fh[s2][1]),"r"(fh[s2][2]),"r"(fh[s2][3]),
                               "r"(wh[2]),"r"(wh[3]));
                asm volatile("mma.sync.aligned.m16n8k16.row.col.f32.bf16.bf16.f32 "
                             "{%0,%1,%2,%3}, {%4,%5,%6,%7}, {%8,%9}, {%0,%1,%2,%3};"
                             : "+f"(aP[1][0]),"+f"(aP[1][1]),"+f"(aP[1][2]),"+f"(aP[1][3])
                             : "r"(fh[s2][0]),"r"(fh[s2][1]),"r"(fh[s2][2]),"r"(fh[s2][3]),
                               "r"(wl[2]),"r"(wl[3]));
                asm volatile("mma.sync.aligned.m16n8k16.row.col.f32.bf16.bf16.f32 "
                             "{%0,%1,%2,%3}, {%4,%5,%6,%7}, {%8,%9}, {%0,%1,%2,%3};"
                             : "+f"(aP[1][0]),"+f"(aP[1][1]),"+f"(aP[1][2]),"+f"(aP[1][3])
                             : "r"(fl[s2][0]),"r"(fl[s2][1]),"r"(fl[s2][2]),"r"(fl[s2][3]),
                               "r"(wh[2]),"r"(wh[3]));
            }
            int klo = 16*s + 2*tt;
            float2 blo = *(const float2*)&b1s[klo];
            float2 bhi = *(const float2*)&b1s[klo + 8];
            split2(ssp(aP[0][0] + blo.x), ssp(aP[0][1] + blo.y), ahi[s*4+0], alo[s*4+0]);
            split2(ssp(aP[0][2] + blo.x), ssp(aP[0][3] + blo.y), ahi[s*4+1], alo[s*4+1]);
            split2(ssp(aP[1][0] + bhi.x), ssp(aP[1][1] + bhi.y), ahi[s*4+2], alo[s*4+2]);
            split2(ssp(aP[1][2] + bhi.x), ssp(aP[1][3] + bhi.y), ahi[s*4+3], alo[s*4+3]);
        }
    }
    __syncthreads();

    float cm0 = cms[row0p], cm1 = cms[row1p];
    const float* yp0 = d_y + (size_t)(bofs + nbs[row0p]) * 128;
    const float* yp1 = d_y + (size_t)(bofs + nbs[row1p]) * 128;

    #pragma unroll
    for (int jq = 0; jq < 8; jq++) {
        float c0[4], c1[4];
        #pragma unroll
        for (int q = 0; q < 4; q++) { c0[q] = 0.f; c1[q] = 0.f; }
        uint32_t baseAddr = sb + OFF_BHI + (uint32_t)(((jq*2 + jbit)*8 + r7) * 256);
        #pragma unroll
        for (int s = 0; s < 8; s++) {
            uint32_t ba = baseAddr + (uint32_t)((((2*s + hb) ^ r7)) * 16);
            uint32_t bh[4], bl[4];
            asm volatile("ldmatrix.sync.aligned.m8n8.x4.shared.b16 {%0,%1,%2,%3}, [%4];"
                         : "=r"(bh[0]),"=r"(bh[1]),"=r"(bh[2]),"=r"(bh[3]) : "r"(ba));
            asm volatile("ldmatrix.sync.aligned.m8n8.x4.shared.b16 {%0,%1,%2,%3}, [%4];"
                         : "=r"(bl[0]),"=r"(bl[1]),"=r"(bl[2]),"=r"(bl[3])
                         : "r"(ba + (OFF_BLO - OFF_BHI)));
            asm volatile("mma.sync.aligned.m16n8k16.row.col.f32.bf16.bf16.f32 "
                         "{%0,%1,%2,%3}, {%4,%5,%6,%7}, {%8,%9}, {%0,%1,%2,%3};"
                         : "+f"(c0[0]),"+f"(c0[1]),"+f"(c0[2]),"+f"(c0[3])
                         : "r"(ahi[s*4+0]),"r"(ahi[s*4+1]),"r"(ahi[s*4+2]),"r"(ahi[s*4+3]),
                           "r"(bh[0]),"r"(bh[1]));
            asm volatile("mma.sync.aligned.m16n8k16.row.col.f32.bf16.bf16.f32 "
                         "{%0,%1,%2,%3}, {%4,%5,%6,%7}, {%8,%9}, {%0,%1,%2,%3};"
                         : "+f"(c0[0]),"+f"(c0[1]),"+f"(c0[2]),"+f"(c0[3])
                         : "r"(ahi[s*4+0]),"r"(ahi[s*4+1]),"r"(ahi[s*4+2]),"r"(ahi[s*4+3]),
                           "r"(bl[0]),"r"(bl[1]));
            asm volatile("mma.sync.aligned.m16n8k16.row.col.f32.bf16.bf16.f32 "
                         "{%0,%1,%2,%3}, {%4,%5,%6,%7}, {%8,%9}, {%0,%1,%2,%3};"
                         : "+f"(c0[0]),"+f"(c0[1]),"+f"(c0[2]),"+f"(c0[3])
                         : "r"(alo[s*4+0]),"r"(alo[s*4+1]),"r"(alo[s*4+2]),"r"(alo[s*4+3]),
                           "r"(bh[0]),"r"(bh[1]));
            asm volatile("mma.sync.aligned.m16n8k16.row.col.f32.bf16.bf16.f32 "
                         "{%0,%1,%2,%3}, {%4,%5,%6,%7}, {%8,%9}, {%0,%1,%2,%3};"
                         : "+f"(c1[0]),"+f"(c1[1]),"+f"(c1[2]),"+f"(c1[3])
                         : "r"(ahi[s*4+0]),"r"(ahi[s*4+1]),"r"(ahi[s*4+2]),"r"(ahi[s*4+3]),
                           "r"(bh[2]),"r"(bh[3]));
            asm volatile("mma.sync.aligned.m16n8k16.row.col.f32.bf16.bf16.f32 "
                         "{%0,%1,%2,%3}, {%4,%5,%6,%7}, {%8,%9}, {%0,%1,%2,%3};"
                         : "+f"(c1[0]),"+f"(c1[1]),"+f"(c1[2]),"+f"(c1[3])
                         : "r"(ahi[s*4+0]),"r"(ahi[s*4+1]),"r"(ahi[s*4+2]),"r"(ahi[s*4+3]),
                           "r"(bl[2]),"r"(bl[3]));
            asm volatile("mma.sync.aligned.m16n8k16.row.col.f32.bf16.bf16.f32 "
                         "{%0,%1,%2,%3}, {%4,%5,%6,%7}, {%8,%9}, {%0,%1,%2,%3};"
                         : "+f"(c1[0]),"+f"(c1[1]),"+f"(c1[2]),"+f"(c1[3])
                         : "r"(alo[s*4+0]),"r"(alo[s*4+1]),"r"(alo[s*4+2]),"r"(alo[s*4+3]),
                           "r"(bh[2]),"r"(bh[3]));
        }
        #pragma unroll
        for (int h = 0; h < 2; h++) {
            int j = 2*jq + h;
            float q0 = h ? c1[0] : c0[0], q1 = h ? c1[1] : c0[1];
            float q2 = h ? c1[2] : c0[2], q3 = h ? c1[3] : c0[3];
            int fa = 8*j + 2*tt;
            float2 b2v = *(const float2*)&b2s[fa];
            float2 ya  = *(const float2*)(yp0 + fa);
            float2 yb  = *(const float2*)(yp1 + fa);
            float p0 = cm0*ya.x*(q0 + b2v.x) + cm1*yb.x*(q2 + b2v.x);
            float p1 = cm0*ya.y*(q1 + b2v.y) + cm1*yb.y*(q3 + b2v.y);
            p0 += __shfl_xor_sync(0xffffffffu, p0, 4);
            p0 += __shfl_xor_sync(0xffffffffu, p0, 8);
            p0 += __shfl_xor_sync(0xffffffffu, p0, 16);
            p1 += __shfl_xor_sync(0xffffffffu, p1, 4);
            p1 += __shfl_xor_sync(0xffffffffu, p1, 8);
            p1 += __shfl_xor_sync(0xffffffffu, p1, 16);
            if (lane < 4)
                *(float2*)&red[w*128 + fa] = make_float2(p0, p1);
        }
    }

    __syncthreads();
    {
        int a = t >> 7, f = t & 127;
        const float* rb = red + (a*4)*128 + f;
        d_agg[(size_t)(i0 + a)*128 + f] = rb[0] + rb[128] + rb[256] + rb[384];
    }
}

extern "C" void kernel_launch(void* const* d_in, const int* in_sizes, int n_in,
                              void* d_out, int out_size) {
    const int*   z      = (const int*)  d_in[0];
    const float* pos    = (const float*)d_in[1];
    const int*   nb     = (const int*)  d_in[2];
    const int*   nmask  = (const int*)  d_in[3];
    const float* Gi     = (const float*)d_in[4];
    const float* emb    = (const float*)d_in[5];
    const float* fw1    = (const float*)d_in[6];
    const float* fb1    = (const float*)d_in[7];
    const float* fw2    = (const float*)d_in[8];
    const float* fb2    = (const float*)d_in[9];
    const float* in2f   = (const float*)d_in[10];
    const float* f2o    = (const float*)d_in[11];
    const float* f2ob   = (const float*)d_in[12];
    const float* dw     = (const float*)d_in[13];
    const float* db     = (const float*)d_in[14];
    const float* angw   = (const float*)d_in[15];
    float* out = (float*)d_out;

    static __nv_bfloat16 *p_i2fhi, *p_i2flo, *p_anghi, *p_anglo, *p_wchi, *p_wclo;
    cudaGetSymbolAddress((void**)&p_i2fhi, d_i2fhi);
    cudaGetSymbolAddress((void**)&p_i2flo, d_i2flo);
    cudaGetSymbolAddress((void**)&p_anghi, d_anghi);
    cudaGetSymbolAddress((void**)&p_anglo, d_anglo);
    cudaGetSymbolAddress((void**)&p_wchi, d_wchi);
    cudaGetSymbolAddress((void**)&p_wclo, d_wclo);

    cudaFuncSetAttribute(filter_agg_kernel,
                         cudaFuncAttributeMaxDynamicSharedMemorySize, FA_SMEM);
    cudaFuncSetAttribute(tgemm_kernel,
                         cudaFuncAttributeMaxDynamicSharedMemorySize, TG_SMEM);

    // prep (layer-invariant)
    embed_kernel<<<BA, 128>>>(z, emb);
    dist_kernel<<<BA, NN>>>(pos, nb, nmask);
    allsplit_kernel<<<1200, 256>>>(fw1, fw2, in2f, angw);
    wcsplit_kernel<<<dim3(32, NL), 128>>>(f2o, dw);
    bc_kernel<<<NL, 128>>>(f2ob, dw, db);

    // angular projections (all layers)
    tgemm_kernel<<<dim3(BA/32, NL), 256, TG_SMEM>>>(Gi, p_anghi, p_anglo, NGA, 0, 1, 0, out);

    for (int l = 0; l < NL; l++) {
        tgemm_kernel<<<dim3(BA/32, 1), 256, TG_SMEM>>>(nullptr,
            p_i2fhi + (size_t)l*NF*ND, p_i2flo + (size_t)l*NF*ND, ND, 1, 0, l, out);
        filter_agg_kernel<<<BA/2, 256, FA_SMEM>>>(fb1, fb2, nb, l);
        tgemm_kernel<<<dim3(BA/32, 1), 256, TG_SMEM>>>(nullptr,
            p_wchi + (size_t)l*ND*ND, p_wclo + (size_t)l*ND*ND, ND, 2,
            (l == NL-1) ? 4 : 3, l, out);
    }
}

// round 16
// speedup vs baseline: 1.6315x; 1.0019x over previous
#include <cuda_runtime.h>
#include <cuda_bf16.h>
#include <math.h>
#include <stdint.h>

#define NB 8
#define NA 512
#define NN 64
#define ND 128
#define NF 128
#define NG 25
#define NL 3
#define NGA 512
#define BA (NB*NA)          // 4096
#define CUTOFF 5.0f
#define RSTART 1.2f
#define LN2F 0.6931471805599453f

// -------- device scratch --------
__device__ float d_x[BA*ND];
__device__ float d_y[BA*NF];
__device__ float d_agg[BA*NF];
__device__ float d_vang[NL*BA*ND];
__device__ float d_cm[BA*NN];
__device__ __nv_bfloat16 d_fhi[BA*NN*32];
__device__ __nv_bfloat16 d_flo[BA*NN*32];
__device__ __nv_bfloat16 d_w1hi[NL*NF*32];
__device__ __nv_bfloat16 d_w1lo[NL*NF*32];
__device__ __nv_bfloat16 d_w2hi[NL*NF*NF];
__device__ __nv_bfloat16 d_w2lo[NL*NF*NF];
__device__ __nv_bfloat16 d_i2fhi[NL*NF*ND];
__device__ __nv_bfloat16 d_i2flo[NL*NF*ND];
__device__ __nv_bfloat16 d_anghi[NL*ND*NGA];
__device__ __nv_bfloat16 d_anglo[NL*ND*NGA];
__device__ __nv_bfloat16 d_wchi[NL*ND*ND];
__device__ __nv_bfloat16 d_wclo[NL*ND*ND];
__device__ float d_bc[NL*ND];

__device__ __forceinline__ float ssp(float v) {
    return fmaxf(v, 0.f) + __logf(1.f + __expf(-fabsf(v))) - LN2F;
}

__device__ __forceinline__ uint32_t smem_u32(const void* p) {
    uint32_t a;
    asm("{ .reg .u64 t; cvta.to.shared.u64 t, %1; cvt.u32.u64 %0, t; }" : "=r"(a) : "l"(p));
    return a;
}

__device__ __forceinline__ void split2(float a, float b, uint32_t& hi, uint32_t& lo) {
    __nv_bfloat16 ah = __float2bfloat16(a), bh = __float2bfloat16(b);
    float ar = a - __bfloat162float(ah);
    float br = b - __bfloat162float(bh);
    __nv_bfloat162 hp; hp.x = ah; hp.y = bh;
    __nv_bfloat162 lp = __floats2bfloat162_rn(ar, br);
    hi = *(uint32_t*)&hp;
    lo = *(uint32_t*)&lp;
}

// -------- embedding gather --------
__global__ void embed_kernel(const int* __restrict__ z, const float* __restrict__ emb) {
    int i = blockIdx.x, t = threadIdx.x;
    d_x[i*ND + t] = emb[z[i]*ND + t];
}

// -------- distances + gaussian smearing (bf16-split) + cutoff*mask --------
__global__ void dist_kernel(const float* __restrict__ pos,
                            const int* __restrict__ nb,
                            const int* __restrict__ nmask) {
    int i = blockIdx.x;
    int n = threadIdx.x;
    int bofs = (i >> 9) << 9;
    float px = pos[i*3+0], py = pos[i*3+1], pz = pos[i*3+2];
    int j = nb[i*NN + n];
    int gj = bofs + j;
    float dx = pos[gj*3+0] - px;
    float dy = pos[gj*3+1] - py;
    float dz = pos[gj*3+2] - pz;
    float r = sqrtf(dx*dx + dy*dy + dz*dz + 1e-12f);
    float m = (float)nmask[i*NN + n];
    d_cm[i*NN + n] = (r <= CUTOFF) ? m : 0.f;
    const float width = (CUTOFF - RSTART) / (float)(NG - 1);
    const float coeff = -0.5f / (width * width);
    __nv_bfloat16* oh = d_fhi + (size_t)(i*NN + n) * 32;
    __nv_bfloat16* ol = d_flo + (size_t)(i*NN + n) * 32;
    #pragma unroll
    for (int g = 0; g < 32; g++) {
        float v = 0.f;
        if (g < NG) {
            float d = r - (RSTART + width * (float)g);
            v = __expf(coeff * d * d);
        }
        __nv_bfloat16 hi = __float2bfloat16(v);
        oh[g] = hi;
        ol[g] = __float2bfloat16(v - __bfloat162float(hi));
    }
}

// -------- prestage: all weight transpose+splits in ONE launch --------
__global__ void allsplit_kernel(const float* __restrict__ w1,
                                const float* __restrict__ w2,
                                const float* __restrict__ i2f,
                                const float* __restrict__ ang) {
    int idx = blockIdx.x * 256 + threadIdx.x;
    float v;
    __nv_bfloat16 *ph, *pl;
    int o;
    if (idx < 12288) {
        int l = idx >> 12, r = idx & 4095;
        int f = r >> 5, k = r & 31;
        v = (k < NG) ? w1[l*3200 + k*128 + f] : 0.f;
        ph = d_w1hi; pl = d_w1lo; o = idx;
    } else if (idx < 61440) {
        int u = idx - 12288;
        int l = u >> 14, r = u & 16383;
        int k = r >> 7, f = r & 127;
        v = w2[u];
        ph = d_w2hi; pl = d_w2lo; o = l*16384 + f*128 + k;
    } else if (idx < 110592) {
        int u = idx - 61440;
        int l = u >> 14, r = u & 16383;
        int k = r >> 7, f = r & 127;
        v = i2f[u];
        ph = d_i2fhi; pl = d_i2flo; o = l*16384 + f*128 + k;
    } else {
        int u = idx - 110592;
        int l = u >> 16, r = u & 65535;
        int k = r >> 7, f = r & 127;
        v = ang[u];
        ph = d_anghi; pl = d_anglo; o = l*65536 + f*512 + k;
    }
    __nv_bfloat16 hi = __float2bfloat16(v);
    ph[o] = hi;
    pl[o] = __float2bfloat16(v - __bfloat162float(hi));
}

// -------- prestage: Wc = f2w@dense, fused transpose + bf16 split (high ILP) --------
__global__ __launch_bounds__(128)
void wcsplit_kernel(const float* __restrict__ f2w, const float* __restrict__ dwm) {
    __shared__ float Ash[4][128];
    int l = blockIdx.y;
    int row0 = blockIdx.x * 4;
    int t = threadIdx.x;
    #pragma unroll
    for (int p = 0; p < 4; p++) {
        int idx = t + 128*p;
        Ash[idx >> 7][idx & 127] = f2w[(size_t)l*16384 + (row0 + (idx >> 7))*128 + (idx & 127)];
    }
    __syncthreads();
    const float* Bm = dwm + (size_t)l*16384;
    float acc[4] = {0.f, 0.f, 0.f, 0.f};
    #pragma unroll
    for (int kt = 0; kt < 128; kt += 16) {
        float bv[16];
        #pragma unroll
        for (int u = 0; u < 16; u++) bv[u] = Bm[(kt + u)*128 + t];   // 16 loads in flight
        #pragma unroll
        for (int u = 0; u < 16; u++) {
            #pragma unroll
            for (int r = 0; r < 4; r++) acc[r] += Ash[r][kt + u] * bv[u];
        }
    }
    #pragma unroll
    for (int r = 0; r < 4; r++) {
        float v = acc[r];
        __nv_bfloat16 hi = __float2bfloat16(v);
        int o = l*16384 + t*128 + row0 + r;   // transposed [f=t][k=row]
        d_wchi[o] = hi;
        d_wclo[o] = __float2bfloat16(v - __bfloat162float(hi));
    }
}

__global__ void bc_kernel(const float* __restrict__ f2b, const float* __restrict__ dwm,
                          const float* __restrict__ db) {
    int l = blockIdx.x, t = threadIdx.x;
    const float* Bm = dwm + (size_t)l*16384;
    float acc = db[l*128 + t];
    #pragma unroll
    for (int kt = 0; kt < 128; kt += 16) {
        float bv[16];
        #pragma unroll
        for (int u = 0; u < 16; u++) bv[u] = Bm[(kt + u)*128 + t];
        #pragma unroll
        for (int u = 0; u < 16; u++) acc += f2b[l*128 + kt + u] * bv[u];
    }
    d_bc[l*128 + t] = acc;
}

// -------- tensor GEMM: C[M,128] = A[M,K] @ B[K,128], bf16 hi/lo split --------
// M-tile 32 (grid M/32), 256 threads: warp = (w>>2) 16-row block x (w&3) f-quarter.
// cmode 0: C=d_y   1: C=d_vang[blockIdx.y]
// cmode 3: x += ssp(acc+bc+vang)   4: same but result -> outp (final layer)
#define TG_AHI 0
#define TG_ALO 4608
#define TG_BHI 9216
#define TG_BLO 27648
#define TG_SMEM 46080
#define TG_STRIDE 144

__global__ __launch_bounds__(256, 2)
void tgemm_kernel(const float* __restrict__ Aext,
                  const __nv_bfloat16* __restrict__ BtHi,
                  const __nv_bfloat16* __restrict__ BtLo,
                  int K, int amode, int cmode, int layer, float* __restrict__ outp) {
    extern __shared__ char smc[];
    uint32_t sb = smem_u32(smc);
    int t = threadIdx.x;
    int lane = t & 31;
    int w = t >> 5;
    int l = blockIdx.y;
    int M0 = blockIdx.x * 32;
    const float* Ap = (amode == 1) ? d_x : ((amode == 2) ? d_agg : Aext);
    const __nv_bfloat16* bhiL = BtHi + (size_t)l*128*K;
    const __nv_bfloat16* bloL = BtLo + (size_t)l*128*K;

    int R0 = (w >> 2) * 16;
    int jbase = (w & 3) * 4;

    float acc[4][4];
    #pragma unroll
    for (int j = 0; j < 4; j++)
        #pragma unroll
        for (int q = 0; q < 4; q++) acc[j][q] = 0.f;

    uint32_t aAddr = sb + TG_AHI + (uint32_t)(R0 + (lane & 15))*TG_STRIDE + (uint32_t)(lane & 16);
    uint32_t bAddr = sb + TG_BHI + (uint32_t)(lane & 7)*TG_STRIDE + (uint32_t)((lane & 8) << 1);

    for (int kc = 0; kc < K; kc += 64) {
        // A chunk [32][64] fp32 -> split
        #pragma unroll
        for (int p = 0; p < 4; p++) {
            int u = t + 256*p;               // 1024 float2 slots
            int r = u >> 5, kp = u & 31;
            float2 v = *(const float2*)&Ap[(size_t)(M0 + r)*K + kc + kp*2];
            uint32_t hi, lo;
            split2(v.x, v.y, hi, lo);
            *(uint32_t*)(smc + TG_AHI + r*TG_STRIDE + kp*4) = hi;
            *(uint32_t*)(smc + TG_ALO + r*TG_STRIDE + kp*4) = lo;
        }
        // B chunk [128][64]
        #pragma unroll
        for (int p = 0; p < 4; p++) {
            int u = t + 256*p;               // 1024 uint4 slots
            int f = u >> 3, c = u & 7;
            *(uint4*)(smc + TG_BHI + f*TG_STRIDE + c*16) =
                ((const uint4*)(bhiL + f*K + kc))[c];
            *(uint4*)(smc + TG_BLO + f*TG_STRIDE + c*16) =
                ((const uint4*)(bloL + f*K + kc))[c];
        }
        __syncthreads();

        #pragma unroll
        for (int s = 0; s < 4; s++) {
            uint32_t ah[4], al[4];
            asm volatile("ldmatrix.sync.aligned.m8n8.x4.shared.b16 {%0,%1,%2,%3}, [%4];"
                         : "=r"(ah[0]),"=r"(ah[1]),"=r"(ah[2]),"=r"(ah[3])
                         : "r"(aAddr + s*32));
            asm volatile("ldmatrix.sync.aligned.m8n8.x4.shared.b16 {%0,%1,%2,%3}, [%4];"
                         : "=r"(al[0]),"=r"(al[1]),"=r"(al[2]),"=r"(al[3])
                         : "r"(aAddr + (TG_ALO - TG_AHI) + s*32));
            #pragma unroll
            for (int j = 0; j < 4; j++) {
                uint32_t ba = bAddr + (uint32_t)((jbase + j)*(8*TG_STRIDE) + s*32);
                uint32_t bh0, bh1, bl0, bl1;
                asm volatile("ldmatrix.sync.aligned.m8n8.x2.shared.b16 {%0,%1}, [%2];"
                             : "=r"(bh0), "=r"(bh1) : "r"(ba));
                asm volatile("ldmatrix.sync.aligned.m8n8.x2.shared.b16 {%0,%1}, [%2];"
                             : "=r"(bl0), "=r"(bl1) : "r"(ba + (TG_BLO - TG_BHI)));
                asm volatile("mma.sync.aligned.m16n8k16.row.col.f32.bf16.bf16.f32 "
                             "{%0,%1,%2,%3}, {%4,%5,%6,%7}, {%8,%9}, {%0,%1,%2,%3};"
                             : "+f"(acc[j][0]),"+f"(acc[j][1]),"+f"(acc[j][2]),"+f"(acc[j][3])
                             : "r"(ah[0]),"r"(ah[1]),"r"(ah[2]),"r"(ah[3]),"r"(bh0),"r"(bh1));
                asm volatile("mma.sync.aligned.m16n8k16.row.col.f32.bf16.bf16.f32 "
                             "{%0,%1,%2,%3}, {%4,%5,%6,%7}, {%8,%9}, {%0,%1,%2,%3};"
                             : "+f"(acc[j][0]),"+f"(acc[j][1]),"+f"(acc[j][2]),"+f"(acc[j][3])
                             : "r"(ah[0]),"r"(ah[1]),"r"(ah[2]),"r"(ah[3]),"r"(bl0),"r"(bl1));
                asm volatile("mma.sync.aligned.m16n8k16.row.col.f32.bf16.bf16.f32 "
                             "{%0,%1,%2,%3}, {%4,%5,%6,%7}, {%8,%9}, {%0,%1,%2,%3};"
                             : "+f"(acc[j][0]),"+f"(acc[j][1]),"+f"(acc[j][2]),"+f"(acc[j][3])
                             : "r"(al[0]),"r"(al[1]),"r"(al[2]),"r"(al[3]),"r"(bh0),"r"(bh1));
            }
        }
        __syncthreads();
    }

    {
        int g = lane >> 2, tt = lane & 3;
        int r0 = M0 + R0 + g;
        if (cmode >= 3) {
            const float* bcL = d_bc + layer*128;
            const float* vaL = d_vang + (size_t)layer*BA*ND;
            #pragma unroll
            for (int j = 0; j < 4; j++) {
                int fa = (jbase + j)*8 + 2*tt;
                float2 bcv = *(const float2*)&bcL[fa];
                float2 va0 = *(const float2*)&vaL[(size_t)r0*128 + fa];
                float2 va1 = *(const float2*)&vaL[(size_t)(r0+8)*128 + fa];
                float2 x0 = *(float2*)&d_x[(size_t)r0*128 + fa];
                float2 x1 = *(float2*)&d_x[(size_t)(r0+8)*128 + fa];
                x0.x += ssp(acc[j][0] + bcv.x + va0.x);
                x0.y += ssp(acc[j][1] + bcv.y + va0.y);
                x1.x += ssp(acc[j][2] + bcv.x + va1.x);
                x1.y += ssp(acc[j][3] + bcv.y + va1.y);
                if (cmode == 4) {
                    *(float2*)&outp[(size_t)r0*128 + fa]     = x0;
                    *(float2*)&outp[(size_t)(r0+8)*128 + fa] = x1;
                } else {
                    *(float2*)&d_x[(size_t)r0*128 + fa]     = x0;
                    *(float2*)&d_x[(size_t)(r0+8)*128 + fa] = x1;
                }
            }
        } else {
            float* Cp = (cmode == 1) ? (d_vang + (size_t)l*BA*ND) : d_y;
            #pragma unroll
            for (int j = 0; j < 4; j++) {
                int fa = (jbase + j)*8 + 2*tt;
                *(float2*)&Cp[(size_t)r0*128 + fa]     = make_float2(acc[j][0], acc[j][1]);
                *(float2*)&Cp[(size_t)(r0+8)*128 + fa] = make_float2(acc[j][2], acc[j][3]);
            }
        }
    }
}

// -------- filter-network + aggregation, tensorized (v6, unchanged) --------
#define OFF_BHI 0
#define OFF_BLO 32768
#define OFF_FHI 65536
#define OFF_FLO 75776
#define OFF_W1HI 86016
#define OFF_W1LO 96256
#define OFF_B1  106496
#define OFF_B2  107008
#define OFF_CM  107520
#define OFF_NB  108032
#define OFF_RED OFF_FHI
#define FA_SMEM 108544

__global__ __launch_bounds__(256, 2)
void filter_agg_kernel(const float* __restrict__ b1g,
                       const float* __restrict__ b2g,
                       const int* __restrict__ nbg, int l)
{
    extern __shared__ char smc[];
    uint32_t sb = smem_u32(smc);
    float* b1s = (float*)(smc + OFF_B1);
    float* b2s = (float*)(smc + OFF_B2);
    float* cms = (float*)(smc + OFF_CM);
    int*   nbs = (int*)(smc + OFF_NB);
    float* red = (float*)(smc + OFF_RED);

    int t = threadIdx.x;
    int lane = t & 31;
    int w = t >> 5;
    int g = lane >> 2;
    int tt = lane & 3;
    int r7 = lane & 7;
    int hb = (lane >> 3) & 1;
    int jbit = (lane >> 4) & 1;
    int atom = w >> 2;
    int i0 = blockIdx.x * 2;
    int bofs = (i0 >> 9) << 9;

    {
        const uint4* hsrc = (const uint4*)(d_w2hi + (size_t)l * 16384);
        const uint4* lsrc = (const uint4*)(d_w2lo + (size_t)l * 16384);
        #pragma unroll
        for (int p = 0; p < 8; p++) {
            int u = t + 256*p;
            int f = u >> 4, c = u & 15;
            int cs = c ^ (f & 7);
            *(uint4*)(smc + OFF_BHI + f*256 + cs*16) = hsrc[u];
            *(uint4*)(smc + OFF_BLO + f*256 + cs*16) = lsrc[u];
        }
        const uint4* fh = (const uint4*)(d_fhi + (size_t)i0 * 64 * 32);
        const uint4* fl = (const uint4*)(d_flo + (size_t)i0 * 64 * 32);
        #pragma unroll
        for (int p = 0; p < 2; p++) {
            int u = t + 256*p;
            int r = u >> 2, c = u & 3;
            *(uint4*)(smc + OFF_FHI + r*80 + c*16) = fh[u];
            *(uint4*)(smc + OFF_FLO + r*80 + c*16) = fl[u];
        }
        const uint4* wh = (const uint4*)(d_w1hi + (size_t)l * 128 * 32);
        const uint4* wl = (const uint4*)(d_w1lo + (size_t)l * 128 * 32);
        #pragma unroll
        for (int p = 0; p < 2; p++) {
            int u = t + 256*p;
            int r = u >> 2, c = u & 3;
            *(uint4*)(smc + OFF_W1HI + r*80 + c*16) = wh[u];
            *(uint4*)(smc + OFF_W1LO + r*80 + c*16) = wl[u];
        }
        if (t < 128) {
            b1s[t] = b1g[l*128 + t];
            b2s[t] = b2g[l*128 + t];
            cms[t] = d_cm[i0*64 + t];
            nbs[t] = nbg[i0*64 + t];
        }
    }
    __syncthreads();

    int row0p = atom*64 + (w & 3)*16 + g;
    int row1p = row0p + 8;

    uint32_t ahi[32], alo[32];
    {
        int R0 = atom*64 + (w & 3)*16;
        uint32_t aAddr = sb + OFF_FHI + (uint32_t)(R0 + (lane & 15))*80 + (uint32_t)(lane & 16);
        uint32_t fh[2][4], fl[2][4];
        #pragma unroll
        for (int s2 = 0; s2 < 2; s2++) {
            asm volatile("ldmatrix.sync.aligned.m8n8.x4.shared.b16 {%0,%1,%2,%3}, [%4];"
                         : "=r"(fh[s2][0]),"=r"(fh[s2][1]),"=r"(fh[s2][2]),"=r"(fh[s2][3])
                         : "r"(aAddr + s2*32));
            asm volatile("ldmatrix.sync.aligned.m8n8.x4.shared.b16 {%0,%1,%2,%3}, [%4];"
                         : "=r"(fl[s2][0]),"=r"(fl[s2][1]),"=r"(fl[s2][2]),"=r"(fl[s2][3])
                         : "r"(aAddr + (OFF_FLO - OFF_FHI) + s2*32));
        }
        #pragma unroll
        for (int s = 0; s < 8; s++) {
            float aP[2][4];
            #pragma unroll
            for (int h = 0; h < 2; h++)
                #pragma unroll
                for (int q = 0; q < 4; q++) aP[h][q] = 0.f;
            uint32_t wAddr = sb + OFF_W1HI
                           + (uint32_t)(((2*s + jbit)*8 + r7)*80) + (uint32_t)(hb << 4);
            #pragma unroll
            for (int s2 = 0; s2 < 2; s2++) {
                uint32_t wh[4], wl[4];
                asm volatile("ldmatrix.sync.aligned.m8n8.x4.shared.b16 {%0,%1,%2,%3}, [%4];"
                             : "=r"(wh[0]),"=r"(wh[1]),"=r"(wh[2]),"=r"(wh[3])
                             : "r"(wAddr + s2*32));
                asm volatile("ldmatrix.sync.aligned.m8n8.x4.shared.b16 {%0,%1,%2,%3}, [%4];"
                             : "=r"(wl[0]),"=r"(wl[1]),"=r"(wl[2]),"=r"(wl[3])
                             : "r"(wAddr + (OFF_W1LO - OFF_W1HI) + s2*32));
                asm volatile("mma.sync.aligned.m16n8k16.row.col.f32.bf16.bf16.f32 "
                             "{%0,%1,%2,%3}, {%4,%5,%6,%7}, {%8,%9}, {%0,%1,%2,%3};"
                             : "+f"(aP[0][0]),"+f"(aP[0][1]),"+f"(aP[0][2]),"+f"(aP[0][3])
                             : "r"(fh[s2][0]),"r"(fh[s2][1]),"r"(fh[s2][2]),"r"(fh[s2][3]),
                               "r"(wh[0]),"r"(wh[1]));
                asm volatile("mma.sync.aligned.m16n8k16.row.col.f32.bf16.bf16.f32 "
                             "{%0,%1,%2,%3}, {%4,%5,%6,%7}, {%8,%9}, {%0,%1,%2,%3};"
                             : "+f"(aP[0][0]),"+f"(aP[0][1]),"+f"(aP[0][2]),"+f"(aP[0][3])
                             : "r"(fh[s2][0]),"r"(fh[s2][1]),"r"(fh[s2][2]),"r"(fh[s2][3]),
                               "r"(wl[0]),"r"(wl[1]));
                asm volatile("mma.sync.aligned.m16n8k16.row.col.f32.bf16.bf16.f32 "
                             "{%0,%1,%2,%3}, {%4,%5,%6,%7}, {%8,%9}, {%0,%1,%2,%3};"
                             : "+f"(aP[0][0]),"+f"(aP[0][1]),"+f"(aP[0][2]),"+f"(aP[0][3])
                             : "r"(fl[s2][0]),"r"(fl[s2][1]),"r"(fl[s2][2]),"r"(fl[s2][3]),
                               "r"(wh[0]),"r"(wh[1]));
                asm volatile("mma.sync.aligned.m16n8k16.row.col.f32.bf16.bf16.f32 "
                             "{%0,%1,%2,%3}, {%4,%5,%6,%7}, {%8,%9}, {%0,%1,%2,%3};"
                             : "+f"(aP[1][0]),"+f"(aP[1][1]),"+f"(aP[1][2]),"+f"(aP[1][3])
                             : "r"(fh[s2][0]),"r"(fh[s2][1]),"r"(fh[s2][2]),"r"(fh[s2][3]),
                               "r"(wh[2]),"r"(wh[3]));
                asm volatile("mma.sync.aligned.m16n8k16.row.col.f32.bf16.bf16.f32 "
                             "{%0,%1,%2,%3}, {%4,%5,%6,%7}, {%8,%9}, {%0,%1,%2,%3};"
                             : "+f"(aP[1][0]),"+f"(aP[1][1]),"+f"(aP[1][2]),"+f"(aP[1][3])
                             : "r"(fh[s2][0]),"r"(fh[s2][1]),"r"(fh[s2][2]),"r"(fh[s2][3]),
                               "r"(wl[2]),"r"(wl[3]));
                asm volatile("mma.sync.aligned.m16n8k16.row.col.f32.bf16.bf16.f32 "
                             "{%0,%1,%2,%3}, {%4,%5,%6,%7}, {%8,%9}, {%0,%1,%2,%3};"
                             : "+f"(aP[1][0]),"+f"(aP[1][1]),"+f"(aP[1][2]),"+f"(aP[1][3])
                             : "r"(fl[s2][0]),"r"(fl[s2][1]),"r"(fl[s2][2]),"r"(fl[s2][3]),
                               "r"(wh[2]),"r"(wh[3]));
            }
            int klo = 16*s + 2*tt;
            float2 blo = *(const float2*)&b1s[klo];
            float2 bhi = *(const float2*)&b1s[klo + 8];
            split2(ssp(aP[0][0] + blo.x), ssp(aP[0][1] + blo.y), ahi[s*4+0], alo[s*4+0]);
            split2(ssp(aP[0][2] + blo.x), ssp(aP[0][3] + blo.y), ahi[s*4+1], alo[s*4+1]);
            split2(ssp(aP[1][0] + bhi.x), ssp(aP[1][1] + bhi.y), ahi[s*4+2], alo[s*4+2]);
            split2(ssp(aP[1][2] + bhi.x), ssp(aP[1][3] + bhi.y), ahi[s*4+3], alo[s*4+3]);
        }
    }
    __syncthreads();

    float cm0 = cms[row0p], cm1 = cms[row1p];
    const float* yp0 = d_y + (size_t)(bofs + nbs[row0p]) * 128;
    const float* yp1 = d_y + (size_t)(bofs + nbs[row1p]) * 128;

    #pragma unroll
    for (int jq = 0; jq < 8; jq++) {
        float c0[4], c1[4];
        #pragma unroll
        for (int q = 0; q < 4; q++) { c0[q] = 0.f; c1[q] = 0.f; }
        uint32_t baseAddr = sb + OFF_BHI + (uint32_t)(((jq*2 + jbit)*8 + r7) * 256);
        #pragma unroll
        for (int s = 0; s < 8; s++) {
            uint32_t ba = baseAddr + (uint32_t)((((2*s + hb) ^ r7)) * 16);
            uint32_t bh[4], bl[4];
            asm volatile("ldmatrix.sync.aligned.m8n8.x4.shared.b16 {%0,%1,%2,%3}, [%4];"
                         : "=r"(bh[0]),"=r"(bh[1]),"=r"(bh[2]),"=r"(bh[3]) : "r"(ba));
            asm volatile("ldmatrix.sync.aligned.m8n8.x4.shared.b16 {%0,%1,%2,%3}, [%4];"
                         : "=r"(bl[0]),"=r"(bl[1]),"=r"(bl[2]),"=r"(bl[3])
                         : "r"(ba + (OFF_BLO - OFF_BHI)));
            asm volatile("mma.sync.aligned.m16n8k16.row.col.f32.bf16.bf16.f32 "
                         "{%0,%1,%2,%3}, {%4,%5,%6,%7}, {%8,%9}, {%0,%1,%2,%3};"
                         : "+f"(c0[0]),"+f"(c0[1]),"+f"(c0[2]),"+f"(c0[3])
                         : "r"(ahi[s*4+0]),"r"(ahi[s*4+1]),"r"(ahi[s*4+2]),"r"(ahi[s*4+3]),
                           "r"(bh[0]),"r"(bh[1]));
            asm volatile("mma.sync.aligned.m16n8k16.row.col.f32.bf16.bf16.f32 "
                         "{%0,%1,%2,%3}, {%4,%5,%6,%7}, {%8,%9}, {%0,%1,%2,%3};"
                         : "+f"(c0[0]),"+f"(c0[1]),"+f"(c0[2]),"+f"(c0[3])
                         : "r"(ahi[s*4+0]),"r"(ahi[s*4+1]),"r"(ahi[s*4+2]),"r"(ahi[s*4+3]),
                           "r"(bl[0]),"r"(bl[1]));
            asm volatile("mma.sync.aligned.m16n8k16.row.col.f32.bf16.bf16.f32 "
                         "{%0,%1,%2,%3}, {%4,%5,%6,%7}, {%8,%9}, {%0,%1,%2,%3};"
                         : "+f"(c0[0]),"+f"(c0[1]),"+f"(c0[2]),"+f"(c0[3])
                         : "r"(alo[s*4+0]),"r"(alo[s*4+1]),"r"(alo[s*4+2]),"r"(alo[s*4+3]),
                           "r"(bh[0]),"r"(bh[1]));
            asm volatile("mma.sync.aligned.m16n8k16.row.col.f32.bf16.bf16.f32 "
                         "{%0,%1,%2,%3}, {%4,%5,%6,%7}, {%8,%9}, {%0,%1,%2,%3};"
                         : "+f"(c1[0]),"+f"(c1[1]),"+f"(c1[2]),"+f"(c1[3])
                         : "r"(ahi[s*4+0]),"r"(ahi[s*4+1]),"r"(ahi[s*4+2]),"r"(ahi[s*4+3]),
                           "r"(bh[2]),"r"(bh[3]));
            asm volatile("mma.sync.aligned.m16n8k16.row.col.f32.bf16.bf16.f32 "
                         "{%0,%1,%2,%3}, {%4,%5,%6,%7}, {%8,%9}, {%0,%1,%2,%3};"
                         : "+f"(c1[0]),"+f"(c1[1]),"+f"(c1[2]),"+f"(c1[3])
                         : "r"(ahi[s*4+0]),"r"(ahi[s*4+1]),"r"(ahi[s*4+2]),"r"(ahi[s*4+3]),
                           "r"(bl[2]),"r"(bl[3]));
            asm volatile("mma.sync.aligned.m16n8k16.row.col.f32.bf16.bf16.f32 "
                         "{%0,%1,%2,%3}, {%4,%5,%6,%7}, {%8,%9}, {%0,%1,%2,%3};"
                         : "+f"(c1[0]),"+f"(c1[1]),"+f"(c1[2]),"+f"(c1[3])
                         : "r"(alo[s*4+0]),"r"(alo[s*4+1]),"r"(alo[s*4+2]),"r"(alo[s*4+3]),
                           "r"(bh[2]),"r"(bh[3]));
        }
        #pragma unroll
        for (int h = 0; h < 2; h++) {
            int j = 2*jq + h;
            float q0 = h ? c1[0] : c0[0], q1 = h ? c1[1] : c0[1];
            float q2 = h ? c1[2] : c0[2], q3 = h ? c1[3] : c0[3];
            int fa = 8*j + 2*tt;
            float2 b2v = *(const float2*)&b2s[fa];
            float2 ya  = *(const float2*)(yp0 + fa);
            float2 yb  = *(const float2*)(yp1 + fa);
            float p0 = cm0*ya.x*(q0 + b2v.x) + cm1*yb.x*(q2 + b2v.x);
            float p1 = cm0*ya.y*(q1 + b2v.y) + cm1*yb.y*(q3 + b2v.y);
            p0 += __shfl_xor_sync(0xffffffffu, p0, 4);
            p0 += __shfl_xor_sync(0xffffffffu, p0, 8);
            p0 += __shfl_xor_sync(0xffffffffu, p0, 16);
            p1 += __shfl_xor_sync(0xffffffffu, p1, 4);
            p1 += __shfl_xor_sync(0xffffffffu, p1, 8);
            p1 += __shfl_xor_sync(0xffffffffu, p1, 16);
            if (lane < 4)
                *(float2*)&red[w*128 + fa] = make_float2(p0, p1);
        }
    }

    __syncthreads();
    {
        int a = t >> 7, f = t & 127;
        const float* rb = red + (a*4)*128 + f;
        d_agg[(size_t)(i0 + a)*128 + f] = rb[0] + rb[128] + rb[256] + rb[384];
    }
}

extern "C" void kernel_launch(void* const* d_in, const int* in_sizes, int n_in,
                              void* d_out, int out_size) {
    const int*   z      = (const int*)  d_in[0];
    const float* pos    = (const float*)d_in[1];
    const int*   nb     = (const int*)  d_in[2];
    const int*   nmask  = (const int*)  d_in[3];
    const float* Gi     = (const float*)d_in[4];
    const float* emb    = (const float*)d_in[5];
    const float* fw1    = (const float*)d_in[6];
    const float* fb1    = (const float*)d_in[7];
    const float* fw2    = (const float*)d_in[8];
    const float* fb2    = (const float*)d_in[9];
    const float* in2f   = (const float*)d_in[10];
    const float* f2o    = (const float*)d_in[11];
    const float* f2ob   = (const float*)d_in[12];
    const float* dw     = (const float*)d_in[13];
    const float* db     = (const float*)d_in[14];
    const float* angw   = (const float*)d_in[15];
    float* out = (float*)d_out;

    static __nv_bfloat16 *p_i2fhi, *p_i2flo, *p_anghi, *p_anglo, *p_wchi, *p_wclo;
    cudaGetSymbolAddress((void**)&p_i2fhi, d_i2fhi);
    cudaGetSymbolAddress((void**)&p_i2flo, d_i2flo);
    cudaGetSymbolAddress((void**)&p_anghi, d_anghi);
    cudaGetSymbolAddress((void**)&p_anglo, d_anglo);
    cudaGetSymbolAddress((void**)&p_wchi, d_wchi);
    cudaGetSymbolAddress((void**)&p_wclo, d_wclo);

    cudaFuncSetAttribute(filter_agg_kernel,
                         cudaFuncAttributeMaxDynamicSharedMemorySize, FA_SMEM);
    cudaFuncSetAttribute(tgemm_kernel,
                         cudaFuncAttributeMaxDynamicSharedMemorySize, TG_SMEM);

    // prep (layer-invariant)
    embed_kernel<<<BA, 128>>>(z, emb);
    dist_kernel<<<BA, NN>>>(pos, nb, nmask);
    allsplit_kernel<<<1200, 256>>>(fw1, fw2, in2f, angw);
    wcsplit_kernel<<<dim3(32, NL), 128>>>(f2o, dw);
    bc_kernel<<<NL, 128>>>(f2ob, dw, db);

    // angular projections (all layers)
    tgemm_kernel<<<dim3(BA/32, NL), 256, TG_SMEM>>>(Gi, p_anghi, p_anglo, NGA, 0, 1, 0, out);

    for (int l = 0; l < NL; l++) {
        tgemm_kernel<<<dim3(BA/32, 1), 256, TG_SMEM>>>(nullptr,
            p_i2fhi + (size_t)l*NF*ND, p_i2flo + (size_t)l*NF*ND, ND, 1, 0, l, out);
        filter_agg_kernel<<<BA/2, 256, FA_SMEM>>>(fb1, fb2, nb, l);
        tgemm_kernel<<<dim3(BA/32, 1), 256, TG_SMEM>>>(nullptr,
            p_wchi + (size_t)l*ND*ND, p_wclo + (size_t)l*ND*ND, ND, 2,
            (l == NL-1) ? 4 : 3, l, out);
    }
}

// round 17
// speedup vs baseline: 1.6884x; 1.0348x over previous
#include <cuda_runtime.h>
#include <cuda_bf16.h>
#include <math.h>
#include <stdint.h>

#define NB 8
#define NA 512
#define NN 64
#define ND 128
#define NF 128
#define NG 25
#define NL 3
#define NGA 512
#define BA (NB*NA)          // 4096
#define CUTOFF 5.0f
#define RSTART 1.2f
#define LN2F 0.6931471805599453f

// -------- device scratch --------
__device__ float d_x[BA*ND];
__device__ float d_y[BA*NF];
__device__ float d_agg[BA*NF];
__device__ float d_vang[NL*BA*ND];
__device__ float d_cm[BA*NN];
__device__ __nv_bfloat16 d_fhi[BA*NN*32];
__device__ __nv_bfloat16 d_flo[BA*NN*32];
__device__ __nv_bfloat16 d_w1hi[NL*NF*32];
__device__ __nv_bfloat16 d_w1lo[NL*NF*32];
__device__ __nv_bfloat16 d_w2hi[NL*NF*NF];
__device__ __nv_bfloat16 d_w2lo[NL*NF*NF];
__device__ __nv_bfloat16 d_i2fhi[NL*NF*ND];
__device__ __nv_bfloat16 d_i2flo[NL*NF*ND];
__device__ __nv_bfloat16 d_anghi[NL*ND*NGA];
__device__ __nv_bfloat16 d_anglo[NL*ND*NGA];
__device__ __nv_bfloat16 d_wchi[NL*ND*ND];
__device__ __nv_bfloat16 d_wclo[NL*ND*ND];
__device__ float d_bc[NL*ND];

__device__ __forceinline__ float ssp(float v) {
    return fmaxf(v, 0.f) + __logf(1.f + __expf(-fabsf(v))) - LN2F;
}

__device__ __forceinline__ uint32_t smem_u32(const void* p) {
    uint32_t a;
    asm("{ .reg .u64 t; cvta.to.shared.u64 t, %1; cvt.u32.u64 %0, t; }" : "=r"(a) : "l"(p));
    return a;
}

__device__ __forceinline__ void split2(float a, float b, uint32_t& hi, uint32_t& lo) {
    __nv_bfloat16 ah = __float2bfloat16(a), bh = __float2bfloat16(b);
    float ar = a - __bfloat162float(ah);
    float br = b - __bfloat162float(bh);
    __nv_bfloat162 hp; hp.x = ah; hp.y = bh;
    __nv_bfloat162 lp = __floats2bfloat162_rn(ar, br);
    hi = *(uint32_t*)&hp;
    lo = *(uint32_t*)&lp;
}

// -------- embedding gather --------
__global__ void embed_kernel(const int* __restrict__ z, const float* __restrict__ emb) {
    int i = blockIdx.x, t = threadIdx.x;
    d_x[i*ND + t] = emb[z[i]*ND + t];
}

// -------- distances + gaussian smearing (bf16-split) + cutoff*mask --------
__global__ void dist_kernel(const float* __restrict__ pos,
                            const int* __restrict__ nb,
                            const int* __restrict__ nmask) {
    int i = blockIdx.x;
    int n = threadIdx.x;
    int bofs = (i >> 9) << 9;
    float px = pos[i*3+0], py = pos[i*3+1], pz = pos[i*3+2];
    int j = nb[i*NN + n];
    int gj = bofs + j;
    float dx = pos[gj*3+0] - px;
    float dy = pos[gj*3+1] - py;
    float dz = pos[gj*3+2] - pz;
    float r = sqrtf(dx*dx + dy*dy + dz*dz + 1e-12f);
    float m = (float)nmask[i*NN + n];
    d_cm[i*NN + n] = (r <= CUTOFF) ? m : 0.f;
    const float width = (CUTOFF - RSTART) / (float)(NG - 1);
    const float coeff = -0.5f / (width * width);
    __nv_bfloat16* oh = d_fhi + (size_t)(i*NN + n) * 32;
    __nv_bfloat16* ol = d_flo + (size_t)(i*NN + n) * 32;
    #pragma unroll
    for (int g = 0; g < 32; g++) {
        float v = 0.f;
        if (g < NG) {
            float d = r - (RSTART + width * (float)g);
            v = __expf(coeff * d * d);
        }
        __nv_bfloat16 hi = __float2bfloat16(v);
        oh[g] = hi;
        ol[g] = __float2bfloat16(v - __bfloat162float(hi));
    }
}

// -------- prestage: all weight transpose+splits in ONE launch --------
__global__ void allsplit_kernel(const float* __restrict__ w1,
                                const float* __restrict__ w2,
                                const float* __restrict__ i2f,
                                const float* __restrict__ ang) {
    int idx = blockIdx.x * 256 + threadIdx.x;
    float v;
    __nv_bfloat16 *ph, *pl;
    int o;
    if (idx < 12288) {
        int l = idx >> 12, r = idx & 4095;
        int f = r >> 5, k = r & 31;
        v = (k < NG) ? w1[l*3200 + k*128 + f] : 0.f;
        ph = d_w1hi; pl = d_w1lo; o = idx;
    } else if (idx < 61440) {
        int u = idx - 12288;
        int l = u >> 14, r = u & 16383;
        int k = r >> 7, f = r & 127;
        v = w2[u];
        ph = d_w2hi; pl = d_w2lo; o = l*16384 + f*128 + k;
    } else if (idx < 110592) {
        int u = idx - 61440;
        int l = u >> 14, r = u & 16383;
        int k = r >> 7, f = r & 127;
        v = i2f[u];
        ph = d_i2fhi; pl = d_i2flo; o = l*16384 + f*128 + k;
    } else {
        int u = idx - 110592;
        int l = u >> 16, r = u & 65535;
        int k = r >> 7, f = r & 127;
        v = ang[u];
        ph = d_anghi; pl = d_anglo; o = l*65536 + f*512 + k;
    }
    __nv_bfloat16 hi = __float2bfloat16(v);
    ph[o] = hi;
    pl[o] = __float2bfloat16(v - __bfloat162float(hi));
}

// -------- prestage: Wc = f2w@dense, one row per block (high parallelism) --------
__global__ __launch_bounds__(128)
void wcsplit_kernel(const float* __restrict__ f2w, const float* __restrict__ dwm) {
    __shared__ float Ash[128];
    int l = blockIdx.y;
    int r = blockIdx.x;            // Wc row
    int t = threadIdx.x;
    Ash[t] = f2w[(size_t)l*16384 + r*128 + t];
    __syncthreads();
    const float* Bm = dwm + (size_t)l*16384;
    float acc = 0.f;
    #pragma unroll
    for (int kt = 0; kt < 128; kt += 16) {
        float bv[16];
        #pragma unroll
        for (int u = 0; u < 16; u++) bv[u] = Bm[(kt + u)*128 + t];
        #pragma unroll
        for (int u = 0; u < 16; u++) acc += Ash[kt + u] * bv[u];
    }
    __nv_bfloat16 hi = __float2bfloat16(acc);
    int o = l*16384 + t*128 + r;   // transposed [f=t][k=r]
    d_wchi[o] = hi;
    d_wclo[o] = __float2bfloat16(acc - __bfloat162float(hi));
}

__global__ void bc_kernel(const float* __restrict__ f2b, const float* __restrict__ dwm,
                          const float* __restrict__ db) {
    int l = blockIdx.x, t = threadIdx.x;
    const float* Bm = dwm + (size_t)l*16384;
    float acc = db[l*128 + t];
    #pragma unroll
    for (int kt = 0; kt < 128; kt += 16) {
        float bv[16];
        #pragma unroll
        for (int u = 0; u < 16; u++) bv[u] = Bm[(kt + u)*128 + t];
        #pragma unroll
        for (int u = 0; u < 16; u++) acc += f2b[l*128 + kt + u] * bv[u];
    }
    d_bc[l*128 + t] = acc;
}

// -------- tensor GEMM: C[M,128] = A[M,K] @ B[K,128], bf16 hi/lo split --------
// M-tile 32 (grid M/32), 256 threads: warp = (w>>2) 16-row block x (w&3) f-quarter.
// cmode 0: C=d_y   1: C=d_vang[blockIdx.y]
// cmode 3: x += ssp(acc+bc+vang)   4: same but result -> outp (final layer)
#define TG_AHI 0
#define TG_ALO 4608
#define TG_BHI 9216
#define TG_BLO 27648
#define TG_SMEM 46080
#define TG_STRIDE 144

__global__ __launch_bounds__(256, 2)
void tgemm_kernel(const float* __restrict__ Aext,
                  const __nv_bfloat16* __restrict__ BtHi,
                  const __nv_bfloat16* __restrict__ BtLo,
                  int K, int amode, int cmode, int layer, float* __restrict__ outp) {
    extern __shared__ char smc[];
    uint32_t sb = smem_u32(smc);
    int t = threadIdx.x;
    int lane = t & 31;
    int w = t >> 5;
    int l = blockIdx.y;
    int M0 = blockIdx.x * 32;
    const float* Ap = (amode == 1) ? d_x : ((amode == 2) ? d_agg : Aext);
    const __nv_bfloat16* bhiL = BtHi + (size_t)l*128*K;
    const __nv_bfloat16* bloL = BtLo + (size_t)l*128*K;

    int R0 = (w >> 2) * 16;
    int jbase = (w & 3) * 4;

    float acc[4][4];
    #pragma unroll
    for (int j = 0; j < 4; j++)
        #pragma unroll
        for (int q = 0; q < 4; q++) acc[j][q] = 0.f;

    uint32_t aAddr = sb + TG_AHI + (uint32_t)(R0 + (lane & 15))*TG_STRIDE + (uint32_t)(lane & 16);
    uint32_t bAddr = sb + TG_BHI + (uint32_t)(lane & 7)*TG_STRIDE + (uint32_t)((lane & 8) << 1);

    for (int kc = 0; kc < K; kc += 64) {
        #pragma unroll
        for (int p = 0; p < 4; p++) {
            int u = t + 256*p;
            int r = u >> 5, kp = u & 31;
            float2 v = *(const float2*)&Ap[(size_t)(M0 + r)*K + kc + kp*2];
            uint32_t hi, lo;
            split2(v.x, v.y, hi, lo);
            *(uint32_t*)(smc + TG_AHI + r*TG_STRIDE + kp*4) = hi;
            *(uint32_t*)(smc + TG_ALO + r*TG_STRIDE + kp*4) = lo;
        }
        #pragma unroll
        for (int p = 0; p < 4; p++) {
            int u = t + 256*p;
            int f = u >> 3, c = u & 7;
            *(uint4*)(smc + TG_BHI + f*TG_STRIDE + c*16) =
                ((const uint4*)(bhiL + f*K + kc))[c];
            *(uint4*)(smc + TG_BLO + f*TG_STRIDE + c*16) =
                ((const uint4*)(bloL + f*K + kc))[c];
        }
        __syncthreads();

        #pragma unroll
        for (int s = 0; s < 4; s++) {
            uint32_t ah[4], al[4];
            asm volatile("ldmatrix.sync.aligned.m8n8.x4.shared.b16 {%0,%1,%2,%3}, [%4];"
                         : "=r"(ah[0]),"=r"(ah[1]),"=r"(ah[2]),"=r"(ah[3])
                         : "r"(aAddr + s*32));
            asm volatile("ldmatrix.sync.aligned.m8n8.x4.shared.b16 {%0,%1,%2,%3}, [%4];"
                         : "=r"(al[0]),"=r"(al[1]),"=r"(al[2]),"=r"(al[3])
                         : "r"(aAddr + (TG_ALO - TG_AHI) + s*32));
            #pragma unroll
            for (int j = 0; j < 4; j++) {
                uint32_t ba = bAddr + (uint32_t)((jbase + j)*(8*TG_STRIDE) + s*32);
                uint32_t bh0, bh1, bl0, bl1;
                asm volatile("ldmatrix.sync.aligned.m8n8.x2.shared.b16 {%0,%1}, [%2];"
                             : "=r"(bh0), "=r"(bh1) : "r"(ba));
                asm volatile("ldmatrix.sync.aligned.m8n8.x2.shared.b16 {%0,%1}, [%2];"
                             : "=r"(bl0), "=r"(bl1) : "r"(ba + (TG_BLO - TG_BHI)));
                asm volatile("mma.sync.aligned.m16n8k16.row.col.f32.bf16.bf16.f32 "
                             "{%0,%1,%2,%3}, {%4,%5,%6,%7}, {%8,%9}, {%0,%1,%2,%3};"
                             : "+f"(acc[j][0]),"+f"(acc[j][1]),"+f"(acc[j][2]),"+f"(acc[j][3])
                             : "r"(ah[0]),"r"(ah[1]),"r"(ah[2]),"r"(ah[3]),"r"(bh0),"r"(bh1));
                asm volatile("mma.sync.aligned.m16n8k16.row.col.f32.bf16.bf16.f32 "
                             "{%0,%1,%2,%3}, {%4,%5,%6,%7}, {%8,%9}, {%0,%1,%2,%3};"
                             : "+f"(acc[j][0]),"+f"(acc[j][1]),"+f"(acc[j][2]),"+f"(acc[j][3])
                             : "r"(ah[0]),"r"(ah[1]),"r"(ah[2]),"r"(ah[3]),"r"(bl0),"r"(bl1));
                asm volatile("mma.sync.aligned.m16n8k16.row.col.f32.bf16.bf16.f32 "
                             "{%0,%1,%2,%3}, {%4,%5,%6,%7}, {%8,%9}, {%0,%1,%2,%3};"
                             : "+f"(acc[j][0]),"+f"(acc[j][1]),"+f"(acc[j][2]),"+f"(acc[j][3])
                             : "r"(al[0]),"r"(al[1]),"r"(al[2]),"r"(al[3]),"r"(bh0),"r"(bh1));
            }
        }
        __syncthreads();
    }

    {
        int g = lane >> 2, tt = lane & 3;
        int r0 = M0 + R0 + g;
        if (cmode >= 3) {
            const float* bcL = d_bc + layer*128;
            const float* vaL = d_vang + (size_t)layer*BA*ND;
            #pragma unroll
            for (int j = 0; j < 4; j++) {
                int fa = (jbase + j)*8 + 2*tt;
                float2 bcv = *(const float2*)&bcL[fa];
                float2 va0 = *(const float2*)&vaL[(size_t)r0*128 + fa];
                float2 va1 = *(const float2*)&vaL[(size_t)(r0+8)*128 + fa];
                float2 x0 = *(float2*)&d_x[(size_t)r0*128 + fa];
                float2 x1 = *(float2*)&d_x[(size_t)(r0+8)*128 + fa];
                x0.x += ssp(acc[j][0] + bcv.x + va0.x);
                x0.y += ssp(acc[j][1] + bcv.y + va0.y);
                x1.x += ssp(acc[j][2] + bcv.x + va1.x);
                x1.y += ssp(acc[j][3] + bcv.y + va1.y);
                if (cmode == 4) {
                    *(float2*)&outp[(size_t)r0*128 + fa]     = x0;
                    *(float2*)&outp[(size_t)(r0+8)*128 + fa] = x1;
                } else {
                    *(float2*)&d_x[(size_t)r0*128 + fa]     = x0;
                    *(float2*)&d_x[(size_t)(r0+8)*128 + fa] = x1;
                }
            }
        } else {
            float* Cp = (cmode == 1) ? (d_vang + (size_t)l*BA*ND) : d_y;
            #pragma unroll
            for (int j = 0; j < 4; j++) {
                int fa = (jbase + j)*8 + 2*tt;
                *(float2*)&Cp[(size_t)r0*128 + fa]     = make_float2(acc[j][0], acc[j][1]);
                *(float2*)&Cp[(size_t)(r0+8)*128 + fa] = make_float2(acc[j][2], acc[j][3]);
            }
        }
    }
}

// -------- filter-network + aggregation, tensorized (v7: 2 pairs per CTA) --------
// w2/w1/bias tiles loaded once; f/cm/nb reloaded per pair. red in own region.
#define OFF_BHI 0
#define OFF_BLO 32768
#define OFF_FHI 65536
#define OFF_FLO 75776
#define OFF_W1HI 86016
#define OFF_W1LO 96256
#define OFF_B1  106496
#define OFF_B2  107008
#define OFF_CM  107520
#define OFF_NB  108032
#define OFF_RED 108544
#define FA_SMEM 112640

__global__ __launch_bounds__(256, 2)
void filter_agg_kernel(const float* __restrict__ b1g,
                       const float* __restrict__ b2g,
                       const int* __restrict__ nbg, int l)
{
    extern __shared__ char smc[];
    uint32_t sb = smem_u32(smc);
    float* b1s = (float*)(smc + OFF_B1);
    float* b2s = (float*)(smc + OFF_B2);
    float* cms = (float*)(smc + OFF_CM);
    int*   nbs = (int*)(smc + OFF_NB);
    float* red = (float*)(smc + OFF_RED);

    int t = threadIdx.x;
    int lane = t & 31;
    int w = t >> 5;
    int g = lane >> 2;
    int tt = lane & 3;
    int r7 = lane & 7;
    int hb = (lane >> 3) & 1;
    int jbit = (lane >> 4) & 1;
    int atom = w >> 2;

    // ---- once: w2/w1/bias loads ----
    {
        const uint4* hsrc = (const uint4*)(d_w2hi + (size_t)l * 16384);
        const uint4* lsrc = (const uint4*)(d_w2lo + (size_t)l * 16384);
        #pragma unroll
        for (int p = 0; p < 8; p++) {
            int u = t + 256*p;
            int f = u >> 4, c = u & 15;
            int cs = c ^ (f & 7);
            *(uint4*)(smc + OFF_BHI + f*256 + cs*16) = hsrc[u];
            *(uint4*)(smc + OFF_BLO + f*256 + cs*16) = lsrc[u];
        }
        const uint4* wh = (const uint4*)(d_w1hi + (size_t)l * 128 * 32);
        const uint4* wl = (const uint4*)(d_w1lo + (size_t)l * 128 * 32);
        #pragma unroll
        for (int p = 0; p < 2; p++) {
            int u = t + 256*p;
            int r = u >> 2, c = u & 3;
            *(uint4*)(smc + OFF_W1HI + r*80 + c*16) = wh[u];
            *(uint4*)(smc + OFF_W1LO + r*80 + c*16) = wl[u];
        }
        if (t < 128) {
            b1s[t] = b1g[l*128 + t];
            b2s[t] = b2g[l*128 + t];
        }
    }

    for (int pp = 0; pp < 2; pp++) {
        int i0 = blockIdx.x * 4 + pp * 2;
        int bofs = (i0 >> 9) << 9;

        // ---- per-pair: f tiles + cm/nb ----
        {
            const uint4* fh = (const uint4*)(d_fhi + (size_t)i0 * 64 * 32);
            const uint4* fl = (const uint4*)(d_flo + (size_t)i0 * 64 * 32);
            #pragma unroll
            for (int p = 0; p < 2; p++) {
                int u = t + 256*p;
                int r = u >> 2, c = u & 3;
                *(uint4*)(smc + OFF_FHI + r*80 + c*16) = fh[u];
                *(uint4*)(smc + OFF_FLO + r*80 + c*16) = fl[u];
            }
            if (t < 128) {
                cms[t] = d_cm[i0*64 + t];
                nbs[t] = nbg[i0*64 + t];
            }
        }
        __syncthreads();

        int row0p = atom*64 + (w & 3)*16 + g;
        int row1p = row0p + 8;

        // ---- stage A ----
        uint32_t ahi[32], alo[32];
        {
            int R0 = atom*64 + (w & 3)*16;
            uint32_t aAddr = sb + OFF_FHI + (uint32_t)(R0 + (lane & 15))*80 + (uint32_t)(lane & 16);
            uint32_t fh[2][4], fl[2][4];
            #pragma unroll
            for (int s2 = 0; s2 < 2; s2++) {
                asm volatile("ldmatrix.sync.aligned.m8n8.x4.shared.b16 {%0,%1,%2,%3}, [%4];"
                             : "=r"(fh[s2][0]),"=r"(fh[s2][1]),"=r"(fh[s2][2]),"=r"(fh[s2][3])
                             : "r"(aAddr + s2*32));
                asm volatile("ldmatrix.sync.aligned.m8n8.x4.shared.b16 {%0,%1,%2,%3}, [%4];"
                             : "=r"(fl[s2][0]),"=r"(fl[s2][1]),"=r"(fl[s2][2]),"=r"(fl[s2][3])
                             : "r"(aAddr + (OFF_FLO - OFF_FHI) + s2*32));
            }
            #pragma unroll
            for (int s = 0; s < 8; s++) {
                float aP[2][4];
                #pragma unroll
                for (int h = 0; h < 2; h++)
                    #pragma unroll
                    for (int q = 0; q < 4; q++) aP[h][q] = 0.f;
                uint32_t wAddr = sb + OFF_W1HI
                               + (uint32_t)(((2*s + jbit)*8 + r7)*80) + (uint32_t)(hb << 4);
                #pragma unroll
                for (int s2 = 0; s2 < 2; s2++) {
                    uint32_t wh[4], wl[4];
                    asm volatile("ldmatrix.sync.aligned.m8n8.x4.shared.b16 {%0,%1,%2,%3}, [%4];"
                                 : "=r"(wh[0]),"=r"(wh[1]),"=r"(wh[2]),"=r"(wh[3])
                                 : "r"(wAddr + s2*32));
                    asm volatile("ldmatrix.sync.aligned.m8n8.x4.shared.b16 {%0,%1,%2,%3}, [%4];"
                                 : "=r"(wl[0]),"=r"(wl[1]),"=r"(wl[2]),"=r"(wl[3])
                                 : "r"(wAddr + (OFF_W1LO - OFF_W1HI) + s2*32));
                    asm volatile("mma.sync.aligned.m16n8k16.row.col.f32.bf16.bf16.f32 "
                                 "{%0,%1,%2,%3}, {%4,%5,%6,%7}, {%8,%9}, {%0,%1,%2,%3};"
                                 : "+f"(aP[0][0]),"+f"(aP[0][1]),"+f"(aP[0][2]),"+f"(aP[0][3])
                                 : "r"(fh[s2][0]),"r"(fh[s2][1]),"r"(fh[s2][2]),"r"(fh[s2][3]),
                                   "r"(wh[0]),"r"(wh[1]));
                    asm volatile("mma.sync.aligned.m16n8k16.row.col.f32.bf16.bf16.f32 "
                                 "{%0,%1,%2,%3}, {%4,%5,%6,%7}, {%8,%9}, {%0,%1,%2,%3};"
                                 : "+f"(aP[0][0]),"+f"(aP[0][1]),"+f"(aP[0][2]),"+f"(aP[0][3])
                                 : "r"(fh[s2][0]),"r"(fh[s2][1]),"r"(fh[s2][2]),"r"(fh[s2][3]),
                                   "r"(wl[0]),"r"(wl[1]));
                    asm volatile("mma.sync.aligned.m16n8k16.row.col.f32.bf16.bf16.f32 "
                                 "{%0,%1,%2,%3}, {%4,%5,%6,%7}, {%8,%9}, {%0,%1,%2,%3};"
                                 : "+f"(aP[0][0]),"+f"(aP[0][1]),"+f"(aP[0][2]),"+f"(aP[0][3])
                                 : "r"(fl[s2][0]),"r"(fl[s2][1]),"r"(fl[s2][2]),"r"(fl[s2][3]),
                                   "r"(wh[0]),"r"(wh[1]));
                    asm volatile("mma.sync.aligned.m16n8k16.row.col.f32.bf16.bf16.f32 "
                                 "{%0,%1,%2,%3}, {%4,%5,%6,%7}, {%8,%9}, {%0,%1,%2,%3};"
                                 : "+f"(aP[1][0]),"+f"(aP[1][1]),"+f"(aP[1][2]),"+f"(aP[1][3])
                                 : "r"(fh[s2][0]),"r"(fh[s2][1]),"r"(fh[s2][2]),"r"(fh[s2][3]),
                                   "r"(wh[2]),"r"(wh[3]));
                    asm volatile("mma.sync.aligned.m16n8k16.row.col.f32.bf16.bf16.f32 "
                                 "{%0,%1,%2,%3}, {%4,%5,%6,%7}, {%8,%9}, {%0,%1,%2,%3};"
                                 : "+f"(aP[1][0]),"+f"(aP[1][1]),"+f"(aP[1][2]),"+f"(aP[1][3])
                                 : "r"(fh[s2][0]),"r"(fh[s2][1]),"r"(fh[s2][2]),"r"(fh[s2][3]),
                                   "r"(wl[2]),"r"(wl[3]));
                    asm volatile("mma.sync.aligned.m16n8k16.row.col.f32.bf16.bf16.f32 "
                                 "{%0,%1,%2,%3}, {%4,%5,%6,%7}, {%8,%9}, {%0,%1,%2,%3};"
                                 : "+f"(aP[1][0]),"+f"(aP[1][1]),"+f"(aP[1][2]),"+f"(aP[1][3])
                                 : "r"(fl[s2][0]),"r"(fl[s2][1]),"r"(fl[s2][2]),"r"(fl[s2][3]),
                                   "r"(wh[2]),"r"(wh[3]));
                }
                int klo = 16*s + 2*tt;
                float2 blo = *(const float2*)&b1s[klo];
                float2 bhi = *(const float2*)&b1s[klo + 8];
                split2(ssp(aP[0][0] + blo.x), ssp(aP[0][1] + blo.y), ahi[s*4+0], alo[s*4+0]);
                split2(ssp(aP[0][2] + blo.x), ssp(aP[0][3] + blo.y), ahi[s*4+1], alo[s*4+1]);
                split2(ssp(aP[1][0] + bhi.x), ssp(aP[1][1] + bhi.y), ahi[s*4+2], alo[s*4+2]);
                split2(ssp(aP[1][2] + bhi.x), ssp(aP[1][3] + bhi.y), ahi[s*4+3], alo[s*4+3]);
            }
        }

        // ---- stage B ----
        float cm0 = cms[row0p], cm1 = cms[row1p];
        const float* yp0 = d_y + (size_t)(bofs + nbs[row0p]) * 128;
        const float* yp1 = d_y + (size_t)(bofs + nbs[row1p]) * 128;

        #pragma unroll
        for (int jq = 0; jq < 8; jq++) {
            float c0[4], c1[4];
            #pragma unroll
            for (int q = 0; q < 4; q++) { c0[q] = 0.f; c1[q] = 0.f; }
            uint32_t baseAddr = sb + OFF_BHI + (uint32_t)(((jq*2 + jbit)*8 + r7) * 256);
            #pragma unroll
            for (int s = 0; s < 8; s++) {
                uint32_t ba = baseAddr + (uint32_t)((((2*s + hb) ^ r7)) * 16);
                uint32_t bh[4], bl[4];
                asm volatile("ldmatrix.sync.aligned.m8n8.x4.shared.b16 {%0,%1,%2,%3}, [%4];"
                             : "=r"(bh[0]),"=r"(bh[1]),"=r"(bh[2]),"=r"(bh[3]) : "r"(ba));
                asm volatile("ldmatrix.sync.aligned.m8n8.x4.shared.b16 {%0,%1,%2,%3}, [%4];"
                             : "=r"(bl[0]),"=r"(bl[1]),"=r"(bl[2]),"=r"(bl[3])
                             : "r"(ba + (OFF_BLO - OFF_BHI)));
                asm volatile("mma.sync.aligned.m16n8k16.row.col.f32.bf16.bf16.f32 "
                             "{%0,%1,%2,%3}, {%4,%5,%6,%7}, {%8,%9}, {%0,%1,%2,%3};"
                             : "+f"(c0[0]),"+f"(c0[1]),"+f"(c0[2]),"+f"(c0[3])
                             : "r"(ahi[s*4+0]),"r"(ahi[s*4+1]),"r"(ahi[s*4+2]),"r"(ahi[s*4+3]),
                               "r"(bh[0]),"r"(bh[1]));
                asm volatile("mma.sync.aligned.m16n8k16.row.col.f32.bf16.bf16.f32 "
                             "{%0,%1,%2,%3}, {%4,%5,%6,%7}, {%8,%9}, {%0,%1,%2,%3};"
                             : "+f"(c0[0]),"+f"(c0[1]),"+f"(c0[2]),"+f"(c0[3])
                             : "r"(ahi[s*4+0]),"r"(ahi[s*4+1]),"r"(ahi[s*4+2]),"r"(ahi[s*4+3]),
                               "r"(bl[0]),"r"(bl[1]));
                asm volatile("mma.sync.aligned.m16n8k16.row.col.f32.bf16.bf16.f32 "
                             "{%0,%1,%2,%3}, {%4,%5,%6,%7}, {%8,%9}, {%0,%1,%2,%3};"
                             : "+f"(c0[0]),"+f"(c0[1]),"+f"(c0[2]),"+f"(c0[3])
                             : "r"(alo[s*4+0]),"r"(alo[s*4+1]),"r"(alo[s*4+2]),"r"(alo[s*4+3]),
                               "r"(bh[0]),"r"(bh[1]));
                asm volatile("mma.sync.aligned.m16n8k16.row.col.f32.bf16.bf16.f32 "
                             "{%0,%1,%2,%3}, {%4,%5,%6,%7}, {%8,%9}, {%0,%1,%2,%3};"
                             : "+f"(c1[0]),"+f"(c1[1]),"+f"(c1[2]),"+f"(c1[3])
                             : "r"(ahi[s*4+0]),"r"(ahi[s*4+1]),"r"(ahi[s*4+2]),"r"(ahi[s*4+3]),
                               "r"(bh[2]),"r"(bh[3]));
                asm volatile("mma.sync.aligned.m16n8k16.row.col.f32.bf16.bf16.f32 "
                             "{%0,%1,%2,%3}, {%4,%5,%6,%7}, {%8,%9}, {%0,%1,%2,%3};"
                             : "+f"(c1[0]),"+f"(c1[1]),"+f"(c1[2]),"+f"(c1[3])
                             : "r"(ahi[s*4+0]),"r"(ahi[s*4+1]),"r"(ahi[s*4+2]),"r"(ahi[s*4+3]),
                               "r"(bl[2]),"r"(bl[3]));
                asm volatile("mma.sync.aligned.m16n8k16.row.col.f32.bf16.bf16.f32 "
                             "{%0,%1,%2,%3}, {%4,%5,%6,%7}, {%8,%9}, {%0,%1,%2,%3};"
                             : "+f"(c1[0]),"+f"(c1[1]),"+f"(c1[2]),"+f"(c1[3])
                             : "r"(alo[s*4+0]),"r"(alo[s*4+1]),"r"(alo[s*4+2]),"r"(alo[s*4+3]),
                               "r"(bh[2]),"r"(bh[3]));
            }
            #pragma unroll
            for (int h = 0; h < 2; h++) {
                int j = 2*jq + h;
                float q0 = h ? c1[0] : c0[0], q1 = h ? c1[1] : c0[1];
                float q2 = h ? c1[2] : c0[2], q3 = h ? c1[3] : c0[3];
                int fa = 8*j + 2*tt;
                float2 b2v = *(const float2*)&b2s[fa];
                float2 ya  = *(const float2*)(yp0 + fa);
                float2 yb  = *(const float2*)(yp1 + fa);
                float p0 = cm0*ya.x*(q0 + b2v.x) + cm1*yb.x*(q2 + b2v.x);
                float p1 = cm0*ya.y*(q1 + b2v.y) + cm1*yb.y*(q3 + b2v.y);
                p0 += __shfl_xor_sync(0xffffffffu, p0, 4);
                p0 += __shfl_xor_sync(0xffffffffu, p0, 8);
                p0 += __shfl_xor_sync(0xffffffffu, p0, 16);
                p1 += __shfl_xor_sync(0xffffffffu, p1, 4);
                p1 += __shfl_xor_sync(0xffffffffu, p1, 8);
                p1 += __shfl_xor_sync(0xffffffffu, p1, 16);
                if (lane < 4)
                    *(float2*)&red[w*128 + fa] = make_float2(p0, p1);
            }
        }

        __syncthreads();
        {
            int a = t >> 7, f = t & 127;
            const float* rb = red + (a*4)*128 + f;
            d_agg[(size_t)(i0 + a)*128 + f] = rb[0] + rb[128] + rb[256] + rb[384];
        }
        __syncthreads();
    }
}

extern "C" void kernel_launch(void* const* d_in, const int* in_sizes, int n_in,
                              void* d_out, int out_size) {
    const int*   z      = (const int*)  d_in[0];
    const float* pos    = (const float*)d_in[1];
    const int*   nb     = (const int*)  d_in[2];
    const int*   nmask  = (const int*)  d_in[3];
    const float* Gi     = (const float*)d_in[4];
    const float* emb    = (const float*)d_in[5];
    const float* fw1    = (const float*)d_in[6];
    const float* fb1    = (const float*)d_in[7];
    const float* fw2    = (const float*)d_in[8];
    const float* fb2    = (const float*)d_in[9];
    const float* in2f   = (const float*)d_in[10];
    const float* f2o    = (const float*)d_in[11];
    const float* f2ob   = (const float*)d_in[12];
    const float* dw     = (const float*)d_in[13];
    const float* db     = (const float*)d_in[14];
    const float* angw   = (const float*)d_in[15];
    float* out = (float*)d_out;

    static __nv_bfloat16 *p_i2fhi, *p_i2flo, *p_anghi, *p_anglo, *p_wchi, *p_wclo;
    cudaGetSymbolAddress((void**)&p_i2fhi, d_i2fhi);
    cudaGetSymbolAddress((void**)&p_i2flo, d_i2flo);
    cudaGetSymbolAddress((void**)&p_anghi, d_anghi);
    cudaGetSymbolAddress((void**)&p_anglo, d_anglo);
    cudaGetSymbolAddress((void**)&p_wchi, d_wchi);
    cudaGetSymbolAddress((void**)&p_wclo, d_wclo);

    cudaFuncSetAttribute(filter_agg_kernel,
                         cudaFuncAttributeMaxDynamicSharedMemorySize, FA_SMEM);
    cudaFuncSetAttribute(tgemm_kernel,
                         cudaFuncAttributeMaxDynamicSharedMemorySize, TG_SMEM);

    // prep (layer-invariant)
    embed_kernel<<<BA, 128>>>(z, emb);
    dist_kernel<<<BA, NN>>>(pos, nb, nmask);
    allsplit_kernel<<<1200, 256>>>(fw1, fw2, in2f, angw);
    wcsplit_kernel<<<dim3(128, NL), 128>>>(f2o, dw);
    bc_kernel<<<NL, 128>>>(f2ob, dw, db);

    // angular projections (all layers)
    tgemm_kernel<<<dim3(BA/32, NL), 256, TG_SMEM>>>(Gi, p_anghi, p_anglo, NGA, 0, 1, 0, out);

    for (int l = 0; l < NL; l++) {
        tgemm_kernel<<<dim3(BA/32, 1), 256, TG_SMEM>>>(nullptr,
            p_i2fhi + (size_t)l*NF*ND, p_i2flo + (size_t)l*NF*ND, ND, 1, 0, l, out);
        filter_agg_kernel<<<BA/4, 256, FA_SMEM>>>(fb1, fb2, nb, l);
        tgemm_kernel<<<dim3(BA/32, 1), 256, TG_SMEM>>>(nullptr,
            p_wchi + (size_t)l*ND*ND, p_wclo + (size_t)l*ND*ND, ND, 2,
            (l == NL-1) ? 4 : 3, l, out);
    }
}